// round 1
// baseline (speedup 1.0000x reference)
#include <cuda_runtime.h>
#include <cstdint>

// ---------------- problem constants ----------------
#define BB 4
#define SS 1024
#define DD 1280
#define HH 20
#define DH 64
#define DF 5120
#define MM (BB*SS)          // 4096 rows

// ---------------- scratch (device globals; no cudaMalloc allowed) ----------------
__device__ float g_Q [MM*DD];
__device__ float g_K [MM*DD];
__device__ float g_V [MM*DD];
__device__ float g_x1[MM*DD];   // attention out + residual
__device__ float g_h0[MM*DD];   // layernorm output
__device__ float g_h1[(size_t)MM*DF]; // ffn hidden

// ============================================================================
// Generic 128x128x8 fp32 SGEMM, 256 threads, 8x8 microtile.
// MODE 0: C = alpha * (A@B)
// MODE 1: C = relu(A@B + bias)
// MODE 2: C = A@B + bias + resid
// Requires M%128==0, N%128==0, K%8==0 (true for all calls here).
// ============================================================================
template <int MODE>
__global__ __launch_bounds__(256, 2)
void sgemm_kernel(const float* __restrict__ A, const float* __restrict__ Bm,
                  float* __restrict__ C, int M, int N, int K,
                  const float* __restrict__ bias, const float* __restrict__ resid,
                  float alpha)
{
    __shared__ float As[8][132];   // transposed A tile, padded -> conflict-free
    __shared__ float Bs[8][128];

    const int tid = threadIdx.x;
    const int tx  = tid & 15;      // N direction
    const int ty  = tid >> 4;      // M direction
    const int mbase = blockIdx.y * 128;
    const int nbase = blockIdx.x * 128;

    // A tile loader: one float4 per thread, row = tid/2, kcol = (tid&1)*4
    const int arow = tid >> 1;
    const int acol = (tid & 1) * 4;
    // B tile loader: row = tid/32, col4 = (tid&31)*4
    const int brow = tid >> 5;
    const int bcol = (tid & 31) * 4;

    const float* Ap = A  + (size_t)(mbase + arow) * K + acol;
    const float* Bp = Bm + (size_t)brow * N + nbase + bcol;

    float acc[8][8];
#pragma unroll
    for (int i = 0; i < 8; i++)
#pragma unroll
        for (int j = 0; j < 8; j++) acc[i][j] = 0.f;

    for (int kb = 0; kb < K; kb += 8) {
        float4 av = *(const float4*)(Ap + kb);
        float4 bv = *(const float4*)(Bp + (size_t)kb * N);
        As[acol + 0][arow] = av.x;
        As[acol + 1][arow] = av.y;
        As[acol + 2][arow] = av.z;
        As[acol + 3][arow] = av.w;
        *(float4*)&Bs[brow][bcol] = bv;
        __syncthreads();

#pragma unroll
        for (int k = 0; k < 8; k++) {
            float a[8], b[8];
            *(float4*)&a[0] = *(const float4*)&As[k][ty * 8];
            *(float4*)&a[4] = *(const float4*)&As[k][ty * 8 + 4];
            *(float4*)&b[0] = *(const float4*)&Bs[k][tx * 8];
            *(float4*)&b[4] = *(const float4*)&Bs[k][tx * 8 + 4];
#pragma unroll
            for (int i = 0; i < 8; i++)
#pragma unroll
                for (int j = 0; j < 8; j++)
                    acc[i][j] += a[i] * b[j];
        }
        __syncthreads();
    }

    // ---------------- epilogue ----------------
    const int col = nbase + tx * 8;
    float bv0x=0,bv0y=0,bv0z=0,bv0w=0,bv1x=0,bv1y=0,bv1z=0,bv1w=0;
    if (MODE == 1 || MODE == 2) {
        float4 b0 = *(const float4*)(bias + col);
        float4 b1 = *(const float4*)(bias + col + 4);
        bv0x=b0.x; bv0y=b0.y; bv0z=b0.z; bv0w=b0.w;
        bv1x=b1.x; bv1y=b1.y; bv1z=b1.z; bv1w=b1.w;
    }
#pragma unroll
    for (int i = 0; i < 8; i++) {
        const int row = mbase + ty * 8 + i;
        float* cp = C + (size_t)row * N + col;
        float4 o0, o1;
        if (MODE == 0) {
            o0 = make_float4(acc[i][0]*alpha, acc[i][1]*alpha, acc[i][2]*alpha, acc[i][3]*alpha);
            o1 = make_float4(acc[i][4]*alpha, acc[i][5]*alpha, acc[i][6]*alpha, acc[i][7]*alpha);
        } else if (MODE == 1) {
            o0 = make_float4(fmaxf(acc[i][0]+bv0x,0.f), fmaxf(acc[i][1]+bv0y,0.f),
                             fmaxf(acc[i][2]+bv0z,0.f), fmaxf(acc[i][3]+bv0w,0.f));
            o1 = make_float4(fmaxf(acc[i][4]+bv1x,0.f), fmaxf(acc[i][5]+bv1y,0.f),
                             fmaxf(acc[i][6]+bv1z,0.f), fmaxf(acc[i][7]+bv1w,0.f));
        } else {
            const float* rp = resid + (size_t)row * N + col;
            float4 r0 = *(const float4*)rp;
            float4 r1 = *(const float4*)(rp + 4);
            o0 = make_float4(acc[i][0]+bv0x+r0.x, acc[i][1]+bv0y+r0.y,
                             acc[i][2]+bv0z+r0.z, acc[i][3]+bv0w+r0.w);
            o1 = make_float4(acc[i][4]+bv1x+r1.x, acc[i][5]+bv1y+r1.y,
                             acc[i][6]+bv1z+r1.z, acc[i][7]+bv1w+r1.w);
        }
        *(float4*)cp       = o0;
        *(float4*)(cp + 4) = o1;
    }
}

// ============================================================================
// Fused flash-style attention. One block = (b, h, 64-query tile). 256 threads.
// Q already carries the 1/sqrt(DH) scale. Writes x1 = attn_out + x.
// Dynamic smem layout (floats):
//   Qs[64][65], Ks[64][65], Vs[64][65], Ps[64][65] (Ps[k][q]), red[64][16],
//   m_s[64], l_s[64], al_s[64]
// ============================================================================
#define ATT_SMEM_FLOATS (4*64*65 + 64*16 + 3*64)
#define ATT_SMEM_BYTES  (ATT_SMEM_FLOATS * 4)

__global__ __launch_bounds__(256, 1)
void attention_kernel(const float* __restrict__ Q, const float* __restrict__ Kmat,
                      const float* __restrict__ V, const float* __restrict__ X,
                      float* __restrict__ X1)
{
    extern __shared__ float sm[];
    float* Qs  = sm;
    float* Ks  = Qs + 64*65;
    float* Vs  = Ks + 64*65;
    float* Ps  = Vs + 64*65;
    float* red = Ps + 64*65;
    float* m_s = red + 64*16;
    float* l_s = m_s + 64;
    float* al_s= l_s + 64;

    const int tid = threadIdx.x;
    const int tx  = tid & 15;     // key / dh direction (4 each)
    const int ty  = tid >> 4;     // query direction (4 each)
    const int b   = blockIdx.z;
    const int h   = blockIdx.y;
    const int qb  = blockIdx.x * 64;

    const size_t base = (size_t)b * SS * DD + (size_t)h * DH;

    // load Q tile (coalesced)
#pragma unroll
    for (int i = 0; i < 16; i++) {
        int e = i * 256 + tid;
        int q = e >> 6, d = e & 63;
        Qs[q * 65 + d] = Q[base + (size_t)(qb + q) * DD + d];
    }
    if (tid < 64) { m_s[tid] = -1e30f; l_s[tid] = 0.f; }
    float o[4][4];
#pragma unroll
    for (int i = 0; i < 4; i++)
#pragma unroll
        for (int j = 0; j < 4; j++) o[i][j] = 0.f;
    __syncthreads();

    for (int kt = 0; kt < SS; kt += 64) {
        // load K & V tiles (coalesced)
#pragma unroll
        for (int i = 0; i < 16; i++) {
            int e = i * 256 + tid;
            int r = e >> 6, d = e & 63;
            size_t ga = base + (size_t)(kt + r) * DD + d;
            Ks[r * 65 + d] = Kmat[ga];
            Vs[r * 65 + d] = V[ga];
        }
        __syncthreads();

        // ----- phase 1: S = Q K^T (4x4 per thread) -----
        float s[4][4];
#pragma unroll
        for (int i = 0; i < 4; i++)
#pragma unroll
            for (int j = 0; j < 4; j++) s[i][j] = 0.f;

#pragma unroll 4
        for (int d = 0; d < 64; d++) {
            float a[4], bb[4];
#pragma unroll
            for (int i = 0; i < 4; i++) a[i]  = Qs[(ty*4 + i) * 65 + d];
#pragma unroll
            for (int j = 0; j < 4; j++) bb[j] = Ks[(tx*4 + j) * 65 + d];
#pragma unroll
            for (int i = 0; i < 4; i++)
#pragma unroll
                for (int j = 0; j < 4; j++)
                    s[i][j] += a[i] * bb[j];
        }

        // ----- partial row max -----
#pragma unroll
        for (int i = 0; i < 4; i++) {
            float mx = fmaxf(fmaxf(s[i][0], s[i][1]), fmaxf(s[i][2], s[i][3]));
            red[(ty*4 + i) * 16 + tx] = mx;
        }
        __syncthreads();
        if (tid < 64) {
            float mx = red[tid * 16];
#pragma unroll
            for (int j = 1; j < 16; j++) mx = fmaxf(mx, red[tid * 16 + j]);
            float mold = m_s[tid];
            float mnew = fmaxf(mold, mx);
            m_s[tid]  = mnew;
            al_s[tid] = __expf(mold - mnew);
        }
        __syncthreads();

        // ----- exp, write P (transposed), partial sums, rescale O -----
#pragma unroll
        for (int i = 0; i < 4; i++) {
            int q = ty*4 + i;
            float mnew = m_s[q];
            float rs = 0.f;
#pragma unroll
            for (int j = 0; j < 4; j++) {
                float p = __expf(s[i][j] - mnew);
                Ps[(tx*4 + j) * 65 + q] = p;
                rs += p;
            }
            red[q * 16 + tx] = rs;
            float al = al_s[q];
#pragma unroll
            for (int j = 0; j < 4; j++) o[i][j] *= al;
        }
        __syncthreads();
        if (tid < 64) {
            float rs = 0.f;
#pragma unroll
            for (int j = 0; j < 16; j++) rs += red[tid * 16 + j];
            l_s[tid] = l_s[tid] * al_s[tid] + rs;
        }

        // ----- phase 2: O += P @ V -----
#pragma unroll 4
        for (int k = 0; k < 64; k++) {
            float p[4], v[4];
#pragma unroll
            for (int i = 0; i < 4; i++) p[i] = Ps[k * 65 + ty*4 + i];
#pragma unroll
            for (int j = 0; j < 4; j++) v[j] = Vs[k * 65 + tx*4 + j];
#pragma unroll
            for (int i = 0; i < 4; i++)
#pragma unroll
                for (int j = 0; j < 4; j++)
                    o[i][j] += p[i] * v[j];
        }
        __syncthreads();   // protect Ks/Vs/Ps/red before next tile
    }

    // ----- epilogue: x1 = O/l + x -----
#pragma unroll
    for (int i = 0; i < 4; i++) {
        int q = ty*4 + i;
        float inv = 1.f / l_s[q];
        size_t ga = base + (size_t)(qb + q) * DD + tx * 4;
        float4 xv = *(const float4*)(X + ga);
        float4 ov;
        ov.x = o[i][0]*inv + xv.x;
        ov.y = o[i][1]*inv + xv.y;
        ov.z = o[i][2]*inv + xv.z;
        ov.w = o[i][3]*inv + xv.w;
        *(float4*)(X1 + ga) = ov;
    }
}

// ============================================================================
// LayerNorm over D=1280. One block per row, 256 threads (5 elems each).
// ============================================================================
__global__ __launch_bounds__(256)
void ln_kernel(const float* __restrict__ X, const float* __restrict__ gam,
               const float* __restrict__ bet, float* __restrict__ Y)
{
    const int row = blockIdx.x;
    const float* xr = X + (size_t)row * DD;
    float v[5];
    float sum = 0.f, sq = 0.f;
#pragma unroll
    for (int i = 0; i < 5; i++) {
        v[i] = xr[threadIdx.x + i * 256];
        sum += v[i];
        sq  += v[i] * v[i];
    }
#pragma unroll
    for (int off = 16; off; off >>= 1) {
        sum += __shfl_xor_sync(0xffffffffu, sum, off);
        sq  += __shfl_xor_sync(0xffffffffu, sq , off);
    }
    __shared__ float sS[8], sQ[8];
    const int w = threadIdx.x >> 5, lane = threadIdx.x & 31;
    if (lane == 0) { sS[w] = sum; sQ[w] = sq; }
    __syncthreads();
    if (threadIdx.x == 0) {
        float a = 0.f, q = 0.f;
#pragma unroll
        for (int i = 0; i < 8; i++) { a += sS[i]; q += sQ[i]; }
        sS[0] = a; sQ[0] = q;
    }
    __syncthreads();
    const float mu   = sS[0] * (1.0f / DD);
    const float var  = sQ[0] * (1.0f / DD) - mu * mu;
    const float rstd = rsqrtf(var + 1e-5f);
    float* yr = Y + (size_t)row * DD;
#pragma unroll
    for (int i = 0; i < 5; i++) {
        int c = threadIdx.x + i * 256;
        yr[c] = (v[i] - mu) * rstd * gam[c] + bet[c];
    }
}

// ============================================================================
// launch
// ============================================================================
extern "C" void kernel_launch(void* const* d_in, const int* in_sizes, int n_in,
                              void* d_out, int out_size)
{
    const float* x   = (const float*)d_in[0];
    const float* Wq  = (const float*)d_in[1];
    const float* Wk  = (const float*)d_in[2];
    const float* Wv  = (const float*)d_in[3];
    const float* lng = (const float*)d_in[4];
    const float* lnb = (const float*)d_in[5];
    const float* W1  = (const float*)d_in[6];
    const float* b1  = (const float*)d_in[7];
    const float* W2  = (const float*)d_in[8];
    const float* b2  = (const float*)d_in[9];
    float* out = (float*)d_out;

    float *Qp, *Kp, *Vp, *X1, *H0, *H1;
    cudaGetSymbolAddress((void**)&Qp, g_Q);
    cudaGetSymbolAddress((void**)&Kp, g_K);
    cudaGetSymbolAddress((void**)&Vp, g_V);
    cudaGetSymbolAddress((void**)&X1, g_x1);
    cudaGetSymbolAddress((void**)&H0, g_h0);
    cudaGetSymbolAddress((void**)&H1, g_h1);

    const dim3 blk(256);

    // QKV projections (Q gets the 1/sqrt(DH) scale fused)
    sgemm_kernel<0><<<dim3(DD/128, MM/128), blk>>>(x, Wq, Qp, MM, DD, DD, nullptr, nullptr, 0.125f);
    sgemm_kernel<0><<<dim3(DD/128, MM/128), blk>>>(x, Wk, Kp, MM, DD, DD, nullptr, nullptr, 1.0f);
    sgemm_kernel<0><<<dim3(DD/128, MM/128), blk>>>(x, Wv, Vp, MM, DD, DD, nullptr, nullptr, 1.0f);

    // fused attention + residual
    cudaFuncSetAttribute(attention_kernel,
                         cudaFuncAttributeMaxDynamicSharedMemorySize, ATT_SMEM_BYTES);
    attention_kernel<<<dim3(SS/64, HH, BB), blk, ATT_SMEM_BYTES>>>(Qp, Kp, Vp, x, X1);

    // layernorm
    ln_kernel<<<MM, 256>>>(X1, lng, lnb, H0);

    // FFN
    sgemm_kernel<1><<<dim3(DF/128, MM/128), blk>>>(H0, W1, H1, MM, DF, DD, b1, nullptr, 1.0f);
    sgemm_kernel<2><<<dim3(DD/128, MM/128), blk>>>(H1, W2, out, MM, DD, DF, b2, X1, 1.0f);
}

// round 2
// speedup vs baseline: 1.5875x; 1.5875x over previous
#include <cuda_runtime.h>
#include <cstdint>

// ---------------- problem constants ----------------
#define BB 4
#define SS 1024
#define DD 1280
#define HH 20
#define DH 64
#define DF 5120
#define MM (BB*SS)          // 4096 rows

// ---------------- scratch (device globals; no cudaMalloc allowed) ----------------
__device__ float g_Q [MM*DD];
__device__ float g_K [MM*DD];
__device__ float g_V [MM*DD];
__device__ float g_x1[MM*DD];
__device__ float g_h0[MM*DD];
__device__ float g_h1[(size_t)MM*DF];

// ============================================================================
// TF32 tensor-core GEMM: 128x128 tile, BK=32, 256 threads (2m x 4n warps),
// warp tile 64x32 via m16n8k8 mma. Double-buffered smem with
// fragment-permuted layout so fragment loads are LDS.128 / LDS.64.
// MODE 0: C = alpha*(A@B);  MODE 1: relu(A@B+bias);  MODE 2: A@B+bias+resid
// ============================================================================
#define ABLK 132                       // padded 128-float block
#define BBLK 68                        // padded 64-float block
#define A_FLOATS (4*8*ABLK)            // 4224
#define B_FLOATS (4*16*BBLK)           // 4352
#define BUF_FLOATS (A_FLOATS + B_FLOATS)
#define GEMM_SMEM_BYTES (2*BUF_FLOATS*4)   // 68608 B

__device__ __forceinline__ float f2tf(float f) {
    uint32_t u;
    asm("cvt.rna.tf32.f32 %0, %1;" : "=r"(u) : "f"(f));
    return __uint_as_float(u);
}

__device__ __forceinline__ void mma_tf32(float c[4], const uint32_t a[4], const uint32_t b[2]) {
    asm volatile(
        "mma.sync.aligned.m16n8k8.row.col.f32.tf32.tf32.f32 "
        "{%0,%1,%2,%3}, {%4,%5,%6,%7}, {%8,%9}, {%0,%1,%2,%3};\n"
        : "+f"(c[0]), "+f"(c[1]), "+f"(c[2]), "+f"(c[3])
        : "r"(a[0]), "r"(a[1]), "r"(a[2]), "r"(a[3]), "r"(b[0]), "r"(b[1]));
}

template <int MODE>
__global__ void __launch_bounds__(256, 1)
gemm_tf32(const float* __restrict__ A, const float* __restrict__ Bm,
          float* __restrict__ C, int M, int N, int K,
          const float* __restrict__ bias, const float* __restrict__ resid,
          float alpha)
{
    extern __shared__ float sm[];
    float* Abuf[2] = { sm,            sm + BUF_FLOATS };
    float* Bbuf[2] = { sm + A_FLOATS, sm + BUF_FLOATS + A_FLOATS };

    const int t    = threadIdx.x;
    const int lane = t & 31;
    const int w    = t >> 5;
    const int wm   = w & 1;        // 2 warps in M
    const int wn   = w >> 1;       // 4 warps in N
    const int g    = lane >> 2;
    const int tg   = lane & 3;
    const int m0   = blockIdx.y * 128;
    const int n0   = blockIdx.x * 128;

    // ---- global loader indices ----
    const int ar = t >> 3;            // A row within pass (0..31), passes add 32
    const int ac = (t & 7) * 4;       // A k-col (0..28)
    const int bk = t >> 5;            // B k-row within pass (0..7), passes add 8
    const int bn = (t & 31) * 4;      // B n-col (0..124)

    const float* Ag = A  + (size_t)(m0 + ar) * K + ac;
    const float* Bg = Bm + (size_t)bk * N + (n0 + bn);

    // ---- STS permutation constants ----
    // A element (r,c): kc=c>>3, mt=r>>4, lane_s=(r&7)*4+(c&3), slot=((r&8)>>3)|((c&4)>>1)
    const int kcA   = ac >> 3;
    const int slotA = ((ar & 8) >> 3) | ((ac & 4) >> 1);
    const int rlA   = ar & 7;
    const int mtHi  = ar >> 4;
    // B element (k,n): kc=k>>3(=p), nt=n>>3, lane_b=(n&7)*4+(k&3), slot=(k&4)>>2
    const int ntB = bn >> 3;
    const int lbB = (bn & 7) * 4 + (bk & 3);
    const int slB = (bk & 4) >> 2;

    float4 aR[4], bR[4];

    // prologue: load tile 0
#pragma unroll
    for (int p = 0; p < 4; p++) aR[p] = *(const float4*)(Ag + (size_t)p * 32 * K);
#pragma unroll
    for (int p = 0; p < 4; p++) bR[p] = *(const float4*)(Bg + (size_t)p * 8 * N);

    float acc[4][4][4];
#pragma unroll
    for (int i = 0; i < 4; i++)
#pragma unroll
        for (int j = 0; j < 4; j++)
#pragma unroll
            for (int q = 0; q < 4; q++) acc[i][j][q] = 0.f;

    // scatter-store staged registers into permuted smem (with tf32 rounding)
    auto sts = [&](int buf) {
#pragma unroll
        for (int p = 0; p < 4; p++) {
            float va[4] = { aR[p].x, aR[p].y, aR[p].z, aR[p].w };
            float vb[4] = { bR[p].x, bR[p].y, bR[p].z, bR[p].w };
#pragma unroll
            for (int j = 0; j < 4; j++) {
                Abuf[buf][(kcA * 8 + p * 2 + mtHi) * ABLK + rlA * 16 + j * 4 + slotA] = f2tf(va[j]);
                Bbuf[buf][(p * 16 + ntB) * BBLK + (lbB + j * 4) * 2 + slB]            = f2tf(vb[j]);
            }
        }
    };

    sts(0);
    __syncthreads();

    const int KT = K >> 5;
    for (int kt = 0; kt < KT; kt++) {
        const int cur = kt & 1;
        if (kt + 1 < KT) {
            const float* Ag2 = Ag + (kt + 1) * 32;
            const float* Bg2 = Bg + (size_t)(kt + 1) * 32 * N;
#pragma unroll
            for (int p = 0; p < 4; p++) aR[p] = *(const float4*)(Ag2 + (size_t)p * 32 * K);
#pragma unroll
            for (int p = 0; p < 4; p++) bR[p] = *(const float4*)(Bg2 + (size_t)p * 8 * N);
        }

#pragma unroll
        for (int kc = 0; kc < 4; kc++) {
            uint32_t af[4][4], bf[4][2];
#pragma unroll
            for (int i = 0; i < 4; i++) {
                uint4 v = *(const uint4*)&Abuf[cur][(kc * 8 + wm * 4 + i) * ABLK + lane * 4];
                af[i][0] = v.x; af[i][1] = v.y; af[i][2] = v.z; af[i][3] = v.w;
            }
#pragma unroll
            for (int j = 0; j < 4; j++) {
                uint2 v = *(const uint2*)&Bbuf[cur][(kc * 16 + wn * 4 + j) * BBLK + lane * 2];
                bf[j][0] = v.x; bf[j][1] = v.y;
            }
#pragma unroll
            for (int i = 0; i < 4; i++)
#pragma unroll
                for (int j = 0; j < 4; j++)
                    mma_tf32(acc[i][j], af[i], bf[j]);
        }

        if (kt + 1 < KT) sts(1 - cur);
        __syncthreads();
    }

    // ---------------- epilogue ----------------
    const int mrow = m0 + wm * 64;
    const int ncol = n0 + wn * 32;
#pragma unroll
    for (int j = 0; j < 4; j++) {
        const int colj = ncol + j * 8 + tg * 2;
        float2 bv = make_float2(0.f, 0.f);
        if (MODE == 1 || MODE == 2) bv = *(const float2*)(bias + colj);
#pragma unroll
        for (int i = 0; i < 4; i++) {
            const int r0 = mrow + i * 16 + g;
            float2 v0 = make_float2(acc[i][j][0], acc[i][j][1]);
            float2 v1 = make_float2(acc[i][j][2], acc[i][j][3]);
            if (MODE == 0) {
                v0.x *= alpha; v0.y *= alpha; v1.x *= alpha; v1.y *= alpha;
            } else if (MODE == 1) {
                v0.x = fmaxf(v0.x + bv.x, 0.f); v0.y = fmaxf(v0.y + bv.y, 0.f);
                v1.x = fmaxf(v1.x + bv.x, 0.f); v1.y = fmaxf(v1.y + bv.y, 0.f);
            } else {
                float2 r0v = *(const float2*)(resid + (size_t)r0 * N + colj);
                float2 r1v = *(const float2*)(resid + (size_t)(r0 + 8) * N + colj);
                v0.x += bv.x + r0v.x; v0.y += bv.y + r0v.y;
                v1.x += bv.x + r1v.x; v1.y += bv.y + r1v.y;
            }
            *(float2*)(C + (size_t)r0 * N + colj)       = v0;
            *(float2*)(C + (size_t)(r0 + 8) * N + colj) = v1;
        }
    }
}

// ============================================================================
// Fused flash-style attention (unchanged from round 1). One block = (b,h,64 q).
// ============================================================================
#define ATT_SMEM_FLOATS (4*64*65 + 64*16 + 3*64)
#define ATT_SMEM_BYTES  (ATT_SMEM_FLOATS * 4)

__global__ __launch_bounds__(256, 1)
void attention_kernel(const float* __restrict__ Q, const float* __restrict__ Kmat,
                      const float* __restrict__ V, const float* __restrict__ X,
                      float* __restrict__ X1)
{
    extern __shared__ float sm[];
    float* Qs  = sm;
    float* Ks  = Qs + 64*65;
    float* Vs  = Ks + 64*65;
    float* Ps  = Vs + 64*65;
    float* red = Ps + 64*65;
    float* m_s = red + 64*16;
    float* l_s = m_s + 64;
    float* al_s= l_s + 64;

    const int tid = threadIdx.x;
    const int tx  = tid & 15;
    const int ty  = tid >> 4;
    const int b   = blockIdx.z;
    const int h   = blockIdx.y;
    const int qb  = blockIdx.x * 64;

    const size_t base = (size_t)b * SS * DD + (size_t)h * DH;

#pragma unroll
    for (int i = 0; i < 16; i++) {
        int e = i * 256 + tid;
        int q = e >> 6, d = e & 63;
        Qs[q * 65 + d] = Q[base + (size_t)(qb + q) * DD + d];
    }
    if (tid < 64) { m_s[tid] = -1e30f; l_s[tid] = 0.f; }
    float o[4][4];
#pragma unroll
    for (int i = 0; i < 4; i++)
#pragma unroll
        for (int j = 0; j < 4; j++) o[i][j] = 0.f;
    __syncthreads();

    for (int kt = 0; kt < SS; kt += 64) {
#pragma unroll
        for (int i = 0; i < 16; i++) {
            int e = i * 256 + tid;
            int r = e >> 6, d = e & 63;
            size_t ga = base + (size_t)(kt + r) * DD + d;
            Ks[r * 65 + d] = Kmat[ga];
            Vs[r * 65 + d] = V[ga];
        }
        __syncthreads();

        float s[4][4];
#pragma unroll
        for (int i = 0; i < 4; i++)
#pragma unroll
            for (int j = 0; j < 4; j++) s[i][j] = 0.f;

#pragma unroll 4
        for (int d = 0; d < 64; d++) {
            float a[4], bb[4];
#pragma unroll
            for (int i = 0; i < 4; i++) a[i]  = Qs[(ty*4 + i) * 65 + d];
#pragma unroll
            for (int j = 0; j < 4; j++) bb[j] = Ks[(tx*4 + j) * 65 + d];
#pragma unroll
            for (int i = 0; i < 4; i++)
#pragma unroll
                for (int j = 0; j < 4; j++)
                    s[i][j] += a[i] * bb[j];
        }

#pragma unroll
        for (int i = 0; i < 4; i++) {
            float mx = fmaxf(fmaxf(s[i][0], s[i][1]), fmaxf(s[i][2], s[i][3]));
            red[(ty*4 + i) * 16 + tx] = mx;
        }
        __syncthreads();
        if (tid < 64) {
            float mx = red[tid * 16];
#pragma unroll
            for (int j = 1; j < 16; j++) mx = fmaxf(mx, red[tid * 16 + j]);
            float mold = m_s[tid];
            float mnew = fmaxf(mold, mx);
            m_s[tid]  = mnew;
            al_s[tid] = __expf(mold - mnew);
        }
        __syncthreads();

#pragma unroll
        for (int i = 0; i < 4; i++) {
            int q = ty*4 + i;
            float mnew = m_s[q];
            float rs = 0.f;
#pragma unroll
            for (int j = 0; j < 4; j++) {
                float p = __expf(s[i][j] - mnew);
                Ps[(tx*4 + j) * 65 + q] = p;
                rs += p;
            }
            red[q * 16 + tx] = rs;
            float al = al_s[q];
#pragma unroll
            for (int j = 0; j < 4; j++) o[i][j] *= al;
        }
        __syncthreads();
        if (tid < 64) {
            float rs = 0.f;
#pragma unroll
            for (int j = 0; j < 16; j++) rs += red[tid * 16 + j];
            l_s[tid] = l_s[tid] * al_s[tid] + rs;
        }

#pragma unroll 4
        for (int k = 0; k < 64; k++) {
            float p[4], v[4];
#pragma unroll
            for (int i = 0; i < 4; i++) p[i] = Ps[k * 65 + ty*4 + i];
#pragma unroll
            for (int j = 0; j < 4; j++) v[j] = Vs[k * 65 + tx*4 + j];
#pragma unroll
            for (int i = 0; i < 4; i++)
#pragma unroll
                for (int j = 0; j < 4; j++)
                    o[i][j] += p[i] * v[j];
        }
        __syncthreads();
    }

#pragma unroll
    for (int i = 0; i < 4; i++) {
        int q = ty*4 + i;
        float inv = 1.f / l_s[q];
        size_t ga = base + (size_t)(qb + q) * DD + tx * 4;
        float4 xv = *(const float4*)(X + ga);
        float4 ov;
        ov.x = o[i][0]*inv + xv.x;
        ov.y = o[i][1]*inv + xv.y;
        ov.z = o[i][2]*inv + xv.z;
        ov.w = o[i][3]*inv + xv.w;
        *(float4*)(X1 + ga) = ov;
    }
}

// ============================================================================
// LayerNorm over D=1280. One block per row, 256 threads.
// ============================================================================
__global__ __launch_bounds__(256)
void ln_kernel(const float* __restrict__ X, const float* __restrict__ gam,
               const float* __restrict__ bet, float* __restrict__ Y)
{
    const int row = blockIdx.x;
    const float* xr = X + (size_t)row * DD;
    float v[5];
    float sum = 0.f, sq = 0.f;
#pragma unroll
    for (int i = 0; i < 5; i++) {
        v[i] = xr[threadIdx.x + i * 256];
        sum += v[i];
        sq  += v[i] * v[i];
    }
#pragma unroll
    for (int off = 16; off; off >>= 1) {
        sum += __shfl_xor_sync(0xffffffffu, sum, off);
        sq  += __shfl_xor_sync(0xffffffffu, sq , off);
    }
    __shared__ float sS[8], sQ[8];
    const int w = threadIdx.x >> 5, lane = threadIdx.x & 31;
    if (lane == 0) { sS[w] = sum; sQ[w] = sq; }
    __syncthreads();
    if (threadIdx.x == 0) {
        float a = 0.f, q = 0.f;
#pragma unroll
        for (int i = 0; i < 8; i++) { a += sS[i]; q += sQ[i]; }
        sS[0] = a; sQ[0] = q;
    }
    __syncthreads();
    const float mu   = sS[0] * (1.0f / DD);
    const float var  = sQ[0] * (1.0f / DD) - mu * mu;
    const float rstd = rsqrtf(var + 1e-5f);
    float* yr = Y + (size_t)row * DD;
#pragma unroll
    for (int i = 0; i < 5; i++) {
        int c = threadIdx.x + i * 256;
        yr[c] = (v[i] - mu) * rstd * gam[c] + bet[c];
    }
}

// ============================================================================
// launch
// ============================================================================
extern "C" void kernel_launch(void* const* d_in, const int* in_sizes, int n_in,
                              void* d_out, int out_size)
{
    const float* x   = (const float*)d_in[0];
    const float* Wq  = (const float*)d_in[1];
    const float* Wk  = (const float*)d_in[2];
    const float* Wv  = (const float*)d_in[3];
    const float* lng = (const float*)d_in[4];
    const float* lnb = (const float*)d_in[5];
    const float* W1  = (const float*)d_in[6];
    const float* b1  = (const float*)d_in[7];
    const float* W2  = (const float*)d_in[8];
    const float* b2  = (const float*)d_in[9];
    float* out = (float*)d_out;

    float *Qp, *Kp, *Vp, *X1, *H0, *H1;
    cudaGetSymbolAddress((void**)&Qp, g_Q);
    cudaGetSymbolAddress((void**)&Kp, g_K);
    cudaGetSymbolAddress((void**)&Vp, g_V);
    cudaGetSymbolAddress((void**)&X1, g_x1);
    cudaGetSymbolAddress((void**)&H0, g_h0);
    cudaGetSymbolAddress((void**)&H1, g_h1);

    cudaFuncSetAttribute(gemm_tf32<0>, cudaFuncAttributeMaxDynamicSharedMemorySize, GEMM_SMEM_BYTES);
    cudaFuncSetAttribute(gemm_tf32<1>, cudaFuncAttributeMaxDynamicSharedMemorySize, GEMM_SMEM_BYTES);
    cudaFuncSetAttribute(gemm_tf32<2>, cudaFuncAttributeMaxDynamicSharedMemorySize, GEMM_SMEM_BYTES);
    cudaFuncSetAttribute(attention_kernel, cudaFuncAttributeMaxDynamicSharedMemorySize, ATT_SMEM_BYTES);

    const dim3 blk(256);

    // QKV projections (Q gets the 1/sqrt(DH) scale fused)
    gemm_tf32<0><<<dim3(DD/128, MM/128), blk, GEMM_SMEM_BYTES>>>(x, Wq, Qp, MM, DD, DD, nullptr, nullptr, 0.125f);
    gemm_tf32<0><<<dim3(DD/128, MM/128), blk, GEMM_SMEM_BYTES>>>(x, Wk, Kp, MM, DD, DD, nullptr, nullptr, 1.0f);
    gemm_tf32<0><<<dim3(DD/128, MM/128), blk, GEMM_SMEM_BYTES>>>(x, Wv, Vp, MM, DD, DD, nullptr, nullptr, 1.0f);

    // fused attention + residual
    attention_kernel<<<dim3(SS/64, HH, BB), blk, ATT_SMEM_BYTES>>>(Qp, Kp, Vp, x, X1);

    // layernorm
    ln_kernel<<<MM, 256>>>(X1, lng, lnb, H0);

    // FFN
    gemm_tf32<1><<<dim3(DF/128, MM/128), blk, GEMM_SMEM_BYTES>>>(H0, W1, H1, MM, DF, DD, b1, nullptr, 1.0f);
    gemm_tf32<2><<<dim3(DD/128, MM/128), blk, GEMM_SMEM_BYTES>>>(H1, W2, out, MM, DD, DF, b2, X1, 1.0f);
}

// round 3
// speedup vs baseline: 1.9110x; 1.2038x over previous
#include <cuda_runtime.h>
#include <cstdint>

// ---------------- problem constants ----------------
#define BB 4
#define SS 1024
#define DD 1280
#define HH 20
#define DH 64
#define DF 5120
#define MM (BB*SS)          // 4096 rows
#define NQKV (3*DD)         // 3840

// ---------------- scratch (device globals; no cudaMalloc allowed) ----------------
__device__ float g_Wqkv[(size_t)DD*NQKV];    // concatenated [Wq|Wk|Wv]
__device__ float g_QKV [(size_t)MM*NQKV];    // fused qkv projections
__device__ float g_x1[MM*DD];
__device__ float g_h0[MM*DD];
__device__ float g_h1[(size_t)MM*DF];

#define ABLK 132
#define BBLK 68

__device__ __forceinline__ float f2tf(float f) {
    uint32_t u;
    asm("cvt.rna.tf32.f32 %0, %1;" : "=r"(u) : "f"(f));
    return __uint_as_float(u);
}

__device__ __forceinline__ void mma_tf32(float c[4], const uint32_t a[4], const uint32_t b[2]) {
    asm volatile(
        "mma.sync.aligned.m16n8k8.row.col.f32.tf32.tf32.f32 "
        "{%0,%1,%2,%3}, {%4,%5,%6,%7}, {%8,%9}, {%0,%1,%2,%3};\n"
        : "+f"(c[0]), "+f"(c[1]), "+f"(c[2]), "+f"(c[3])
        : "r"(a[0]), "r"(a[1]), "r"(a[2]), "r"(a[3]), "r"(b[0]), "r"(b[1]));
}

// ============================================================================
// TF32 tensor-core GEMM (validated round 2). 128x128 tile, BK=32, 256 thr.
// MODE 1: relu(A@B+bias); MODE 2: A@B+bias+resid; MODE 3: qkv (col<DD scaled)
// ============================================================================
#define A_FLOATS (4*8*ABLK)
#define B_FLOATS (4*16*BBLK)
#define BUF_FLOATS (A_FLOATS + B_FLOATS)
#define GEMM_SMEM_BYTES (2*BUF_FLOATS*4)

template <int MODE>
__global__ void __launch_bounds__(256, 1)
gemm_tf32(const float* __restrict__ A, const float* __restrict__ Bm,
          float* __restrict__ C, int M, int N, int K,
          const float* __restrict__ bias, const float* __restrict__ resid,
          float alpha)
{
    extern __shared__ float sm[];
    float* Abuf[2] = { sm,            sm + BUF_FLOATS };
    float* Bbuf[2] = { sm + A_FLOATS, sm + BUF_FLOATS + A_FLOATS };

    const int t    = threadIdx.x;
    const int lane = t & 31;
    const int w    = t >> 5;
    const int wm   = w & 1;
    const int wn   = w >> 1;
    const int g    = lane >> 2;
    const int tg   = lane & 3;
    const int m0   = blockIdx.y * 128;
    const int n0   = blockIdx.x * 128;

    const int ar = t >> 3;
    const int ac = (t & 7) * 4;
    const int bk = t >> 5;
    const int bn = (t & 31) * 4;

    const float* Ag = A  + (size_t)(m0 + ar) * K + ac;
    const float* Bg = Bm + (size_t)bk * N + (n0 + bn);

    const int kcA   = ac >> 3;
    const int slotA = ((ar & 8) >> 3) | ((ac & 4) >> 1);
    const int rlA   = ar & 7;
    const int mtHi  = ar >> 4;
    const int ntB = bn >> 3;
    const int lbB = (bn & 7) * 4 + (bk & 3);
    const int slB = (bk & 4) >> 2;

    float4 aR[4], bR[4];
#pragma unroll
    for (int p = 0; p < 4; p++) aR[p] = *(const float4*)(Ag + (size_t)p * 32 * K);
#pragma unroll
    for (int p = 0; p < 4; p++) bR[p] = *(const float4*)(Bg + (size_t)p * 8 * N);

    float acc[4][4][4];
#pragma unroll
    for (int i = 0; i < 4; i++)
#pragma unroll
        for (int j = 0; j < 4; j++)
#pragma unroll
            for (int q = 0; q < 4; q++) acc[i][j][q] = 0.f;

    auto sts = [&](int buf) {
#pragma unroll
        for (int p = 0; p < 4; p++) {
            float va[4] = { aR[p].x, aR[p].y, aR[p].z, aR[p].w };
            float vb[4] = { bR[p].x, bR[p].y, bR[p].z, bR[p].w };
#pragma unroll
            for (int j = 0; j < 4; j++) {
                Abuf[buf][(kcA * 8 + p * 2 + mtHi) * ABLK + rlA * 16 + j * 4 + slotA] = f2tf(va[j]);
                Bbuf[buf][(p * 16 + ntB) * BBLK + (lbB + j * 4) * 2 + slB]            = f2tf(vb[j]);
            }
        }
    };

    sts(0);
    __syncthreads();

    const int KT = K >> 5;
    for (int kt = 0; kt < KT; kt++) {
        const int cur = kt & 1;
        if (kt + 1 < KT) {
            const float* Ag2 = Ag + (kt + 1) * 32;
            const float* Bg2 = Bg + (size_t)(kt + 1) * 32 * N;
#pragma unroll
            for (int p = 0; p < 4; p++) aR[p] = *(const float4*)(Ag2 + (size_t)p * 32 * K);
#pragma unroll
            for (int p = 0; p < 4; p++) bR[p] = *(const float4*)(Bg2 + (size_t)p * 8 * N);
        }

#pragma unroll
        for (int kc = 0; kc < 4; kc++) {
            uint32_t af[4][4], bf[4][2];
#pragma unroll
            for (int i = 0; i < 4; i++) {
                uint4 v = *(const uint4*)&Abuf[cur][(kc * 8 + wm * 4 + i) * ABLK + lane * 4];
                af[i][0] = v.x; af[i][1] = v.y; af[i][2] = v.z; af[i][3] = v.w;
            }
#pragma unroll
            for (int j = 0; j < 4; j++) {
                uint2 v = *(const uint2*)&Bbuf[cur][(kc * 16 + wn * 4 + j) * BBLK + lane * 2];
                bf[j][0] = v.x; bf[j][1] = v.y;
            }
#pragma unroll
            for (int i = 0; i < 4; i++)
#pragma unroll
                for (int j = 0; j < 4; j++)
                    mma_tf32(acc[i][j], af[i], bf[j]);
        }

        if (kt + 1 < KT) sts(1 - cur);
        __syncthreads();
    }

    const int mrow = m0 + wm * 64;
    const int ncol = n0 + wn * 32;
#pragma unroll
    for (int j = 0; j < 4; j++) {
        const int colj = ncol + j * 8 + tg * 2;
        float2 bv = make_float2(0.f, 0.f);
        if (MODE == 1 || MODE == 2) bv = *(const float2*)(bias + colj);
        const float sc = (MODE == 3) ? ((colj < DD) ? 0.125f : 1.0f) : alpha;
#pragma unroll
        for (int i = 0; i < 4; i++) {
            const int r0 = mrow + i * 16 + g;
            float2 v0 = make_float2(acc[i][j][0], acc[i][j][1]);
            float2 v1 = make_float2(acc[i][j][2], acc[i][j][3]);
            if (MODE == 0 || MODE == 3) {
                v0.x *= sc; v0.y *= sc; v1.x *= sc; v1.y *= sc;
            } else if (MODE == 1) {
                v0.x = fmaxf(v0.x + bv.x, 0.f); v0.y = fmaxf(v0.y + bv.y, 0.f);
                v1.x = fmaxf(v1.x + bv.x, 0.f); v1.y = fmaxf(v1.y + bv.y, 0.f);
            } else {
                float2 r0v = *(const float2*)(resid + (size_t)r0 * N + colj);
                float2 r1v = *(const float2*)(resid + (size_t)(r0 + 8) * N + colj);
                v0.x += bv.x + r0v.x; v0.y += bv.y + r0v.y;
                v1.x += bv.x + r1v.x; v1.y += bv.y + r1v.y;
            }
            *(float2*)(C + (size_t)r0 * N + colj)       = v0;
            *(float2*)(C + (size_t)(r0 + 8) * N + colj) = v1;
        }
    }
}

// ============================================================================
// Weight concat: g_Wqkv = [Wq | Wk | Wv], 1280 x 3840
// ============================================================================
__global__ void concat_qkv(const float* __restrict__ Wq, const float* __restrict__ Wk,
                           const float* __restrict__ Wv, float* __restrict__ W)
{
    int i = blockIdx.x * 256 + threadIdx.x;              // float4 index
    if (i >= DD * (NQKV / 4)) return;
    int r  = i / (NQKV / 4);
    int c4 = i % (NQKV / 4);
    float4 v;
    if      (c4 < 320) v = ((const float4*)Wq)[r * 320 + c4];
    else if (c4 < 640) v = ((const float4*)Wk)[r * 320 + c4 - 320];
    else               v = ((const float4*)Wv)[r * 320 + c4 - 640];
    ((float4*)W)[i] = v;
}

// ============================================================================
// Tensor-core flash attention. Block = (qtile 64, h, b), 256 thr = 8 warps
// (4 in M x 2 in N). Key tile = 128. Q pre-scaled by 1/sqrt(DH).
// Writes X1 = attn_out + X.
// smem (floats): Qs 4224 | Ks 8704 | Vs 8704 | Ps 8448 | m 64 | l 64 | al 64 |
//                red_m 128 | red_s 128   => 30528 floats = 122112 B
// ============================================================================
#define ATT_SMEM_FLOATS 30528
#define ATT_SMEM_BYTES  (ATT_SMEM_FLOATS*4)

__global__ void __launch_bounds__(256, 1)
attention_tc(const float* __restrict__ QKV, const float* __restrict__ X,
             float* __restrict__ X1)
{
    extern __shared__ float sm[];
    float* Qs   = sm;                  // A-layout, M=64 (4 mt), K=64 (8 kc)
    float* Ks   = Qs + 4224;           // B-layout, k=64 (8 kc), n=128 (16 nt)
    float* Vs   = Ks + 8704;           // B-layout, k=128 (16 kc), n=64 (8 nt)
    float* Ps   = Vs + 8704;           // A-layout, M=64 (4 mt), K=128 (16 kc)
    float* m_s  = Ps + 8448;
    float* l_s  = m_s + 64;
    float* al_s = l_s + 64;
    float* red_m= al_s + 64;           // [row][wn] -> 128
    float* red_s= red_m + 128;         // [row][wn] -> 128

    const int t    = threadIdx.x;
    const int lane = t & 31;
    const int w    = t >> 5;
    const int wm   = w & 3;            // 4 warps in M (query rows)
    const int wn   = w >> 2;           // 2 warps in N
    const int g    = lane >> 2;
    const int tg   = lane & 3;

    const int qb   = blockIdx.x * 64;
    const int h    = blockIdx.y;
    const int b    = blockIdx.z;
    const int brow = b * SS;           // token row base

    // ---- load Q tile (64 x 64) into A-permuted smem ----
    {
        const float* Qg = QKV + (size_t)(brow + qb) * NQKV + h * DH;
#pragma unroll
        for (int i = 0; i < 4; i++) {
            int e4 = i * 256 + t;
            int q  = e4 >> 4;
            int d4 = (e4 & 15) * 4;
            float4 v = *(const float4*)(Qg + (size_t)q * NQKV + d4);
            float va[4] = { v.x, v.y, v.z, v.w };
            int blkB = (d4 >> 3) * 4 + (q >> 4);
            int base = blkB * 132 + (q & 7) * 16 + ((q & 8) >> 3) + ((d4 & 4) >> 1);
#pragma unroll
            for (int j = 0; j < 4; j++)
                Qs[base + j * 4] = f2tf(va[j]);
        }
    }
    if (t < 64) { m_s[t] = -1e30f; l_s[t] = 0.f; }

    float oacc[4][4];
#pragma unroll
    for (int i = 0; i < 4; i++)
#pragma unroll
        for (int j = 0; j < 4; j++) oacc[i][j] = 0.f;
    __syncthreads();

    const int row0 = wm * 16 + g;
    const int row1 = row0 + 8;

    for (int kb = 0; kb < SS; kb += 128) {
        // ---- load K,V tiles (128 x 64) into B-permuted smem ----
        {
            const float* Kg = QKV + (size_t)(brow + kb) * NQKV + DD     + h * DH;
            const float* Vg = QKV + (size_t)(brow + kb) * NQKV + 2 * DD + h * DH;
#pragma unroll
            for (int i = 0; i < 8; i++) {
                int e4 = i * 256 + t;
                int r  = e4 >> 4;
                int d4 = (e4 & 15) * 4;
                float4 kv = *(const float4*)(Kg + (size_t)r * NQKV + d4);
                float4 vv = *(const float4*)(Vg + (size_t)r * NQKV + d4);
                float ka[4] = { kv.x, kv.y, kv.z, kv.w };
                float va[4] = { vv.x, vv.y, vv.z, vv.w };
                // K: (k=d, n=r), NNT=16
                int kbase = ((d4 >> 3) * 16 + (r >> 3)) * 68 + (r & 7) * 8 + ((d4 & 4) >> 2);
                // V: (k=r, n=d), NNT=8
                int vbase = ((r >> 3) * 8 + (d4 >> 3)) * 68 + (d4 & 7) * 8 + (r & 3) * 2 + ((r & 4) >> 2);
#pragma unroll
                for (int j = 0; j < 4; j++) {
                    Ks[kbase + j * 2] = f2tf(ka[j]);   // lbB=(r&7)*4+j -> *2
                    Vs[vbase + j * 8] = f2tf(va[j]);   // lbB=((d4&7)+j)*4+(r&3) -> *2
                }
            }
        }
        __syncthreads();

        // ---- S = Q @ K^T : warp tile 16 x 64 ----
        float sacc[8][4];
#pragma unroll
        for (int j = 0; j < 8; j++)
#pragma unroll
            for (int q = 0; q < 4; q++) sacc[j][q] = 0.f;

#pragma unroll
        for (int kc = 0; kc < 8; kc++) {
            uint32_t af[4];
            uint4 av = *(const uint4*)&Qs[(kc * 4 + wm) * 132 + lane * 4];
            af[0] = av.x; af[1] = av.y; af[2] = av.z; af[3] = av.w;
#pragma unroll
            for (int j = 0; j < 8; j++) {
                uint32_t bf[2];
                uint2 bv = *(const uint2*)&Ks[(kc * 16 + wn * 8 + j) * 68 + lane * 2];
                bf[0] = bv.x; bf[1] = bv.y;
                mma_tf32(sacc[j], af, bf);
            }
        }

        // ---- softmax: row max ----
        float pm0 = -1e30f, pm1 = -1e30f;
#pragma unroll
        for (int j = 0; j < 8; j++) {
            pm0 = fmaxf(pm0, fmaxf(sacc[j][0], sacc[j][1]));
            pm1 = fmaxf(pm1, fmaxf(sacc[j][2], sacc[j][3]));
        }
        pm0 = fmaxf(pm0, __shfl_xor_sync(0xffffffffu, pm0, 1));
        pm0 = fmaxf(pm0, __shfl_xor_sync(0xffffffffu, pm0, 2));
        pm1 = fmaxf(pm1, __shfl_xor_sync(0xffffffffu, pm1, 1));
        pm1 = fmaxf(pm1, __shfl_xor_sync(0xffffffffu, pm1, 2));
        if (tg == 0) {
            red_m[row0 * 2 + wn] = pm0;
            red_m[row1 * 2 + wn] = pm1;
        }
        __syncthreads();
        if (t < 64) {
            float mold = m_s[t];
            float mnew = fmaxf(mold, fmaxf(red_m[t * 2], red_m[t * 2 + 1]));
            m_s[t]  = mnew;
            al_s[t] = __expf(mold - mnew);
        }
        __syncthreads();

        // ---- exp, store P (A-layout), row sums, rescale O ----
        const float mn0 = m_s[row0], mn1 = m_s[row1];
        const float al0 = al_s[row0], al1 = al_s[row1];
        float rs0 = 0.f, rs1 = 0.f;
        const int s2 = ((tg * 2) & 3) * 4 + (((tg * 2) & 4) >> 1);
#pragma unroll
        for (int j = 0; j < 8; j++) {
            float p00 = __expf(sacc[j][0] - mn0);
            float p01 = __expf(sacc[j][1] - mn0);
            float p10 = __expf(sacc[j][2] - mn1);
            float p11 = __expf(sacc[j][3] - mn1);
            rs0 += p00 + p01;
            rs1 += p10 + p11;
            int base = ((wn * 8 + j) * 4 + wm) * 132 + g * 16 + s2;
            Ps[base    ] = f2tf(p00);
            Ps[base + 4] = f2tf(p01);
            Ps[base + 1] = f2tf(p10);
            Ps[base + 5] = f2tf(p11);
        }
        rs0 += __shfl_xor_sync(0xffffffffu, rs0, 1);
        rs0 += __shfl_xor_sync(0xffffffffu, rs0, 2);
        rs1 += __shfl_xor_sync(0xffffffffu, rs1, 1);
        rs1 += __shfl_xor_sync(0xffffffffu, rs1, 2);
        if (tg == 0) {
            red_s[row0 * 2 + wn] = rs0;
            red_s[row1 * 2 + wn] = rs1;
        }
#pragma unroll
        for (int i = 0; i < 4; i++) {
            oacc[i][0] *= al0; oacc[i][1] *= al0;
            oacc[i][2] *= al1; oacc[i][3] *= al1;
        }
        __syncthreads();
        if (t < 64)
            l_s[t] = l_s[t] * al_s[t] + red_s[t * 2] + red_s[t * 2 + 1];

        // ---- O += P @ V : warp tile 16 x 32 ----
#pragma unroll
        for (int kc = 0; kc < 16; kc++) {
            uint32_t af[4];
            uint4 av = *(const uint4*)&Ps[(kc * 4 + wm) * 132 + lane * 4];
            af[0] = av.x; af[1] = av.y; af[2] = av.z; af[3] = av.w;
#pragma unroll
            for (int j = 0; j < 4; j++) {
                uint32_t bf[2];
                uint2 bv = *(const uint2*)&Vs[(kc * 8 + wn * 4 + j) * 68 + lane * 2];
                bf[0] = bv.x; bf[1] = bv.y;
                mma_tf32(oacc[j], af, bf);
            }
        }
        __syncthreads();   // Ks/Vs/Ps reused next iter; l_s stable after this
    }

    // ---- epilogue: X1 = O/l + X ----
    const float il0 = 1.f / l_s[row0];
    const float il1 = 1.f / l_s[row1];
    const size_t tok0 = (size_t)(brow + qb + row0);
    const size_t tok1 = (size_t)(brow + qb + row1);
#pragma unroll
    for (int j = 0; j < 4; j++) {
        const int col = h * DH + (wn * 4 + j) * 8 + tg * 2;
        float2 x0 = *(const float2*)(X + tok0 * DD + col);
        float2 x1 = *(const float2*)(X + tok1 * DD + col);
        float2 o0 = make_float2(oacc[j][0] * il0 + x0.x, oacc[j][1] * il0 + x0.y);
        float2 o1 = make_float2(oacc[j][2] * il1 + x1.x, oacc[j][3] * il1 + x1.y);
        *(float2*)(X1 + tok0 * DD + col) = o0;
        *(float2*)(X1 + tok1 * DD + col) = o1;
    }
}

// ============================================================================
// LayerNorm over D=1280. One block per row, 256 threads.
// ============================================================================
__global__ void __launch_bounds__(256)
ln_kernel(const float* __restrict__ X, const float* __restrict__ gam,
          const float* __restrict__ bet, float* __restrict__ Y)
{
    const int row = blockIdx.x;
    const float* xr = X + (size_t)row * DD;
    float v[5];
    float sum = 0.f, sq = 0.f;
#pragma unroll
    for (int i = 0; i < 5; i++) {
        v[i] = xr[threadIdx.x + i * 256];
        sum += v[i];
        sq  += v[i] * v[i];
    }
#pragma unroll
    for (int off = 16; off; off >>= 1) {
        sum += __shfl_xor_sync(0xffffffffu, sum, off);
        sq  += __shfl_xor_sync(0xffffffffu, sq , off);
    }
    __shared__ float sS[8], sQ[8];
    const int w = threadIdx.x >> 5, lane = threadIdx.x & 31;
    if (lane == 0) { sS[w] = sum; sQ[w] = sq; }
    __syncthreads();
    if (threadIdx.x == 0) {
        float a = 0.f, q = 0.f;
#pragma unroll
        for (int i = 0; i < 8; i++) { a += sS[i]; q += sQ[i]; }
        sS[0] = a; sQ[0] = q;
    }
    __syncthreads();
    const float mu   = sS[0] * (1.0f / DD);
    const float var  = sQ[0] * (1.0f / DD) - mu * mu;
    const float rstd = rsqrtf(var + 1e-5f);
    float* yr = Y + (size_t)row * DD;
#pragma unroll
    for (int i = 0; i < 5; i++) {
        int c = threadIdx.x + i * 256;
        yr[c] = (v[i] - mu) * rstd * gam[c] + bet[c];
    }
}

// ============================================================================
// launch
// ============================================================================
extern "C" void kernel_launch(void* const* d_in, const int* in_sizes, int n_in,
                              void* d_out, int out_size)
{
    const float* x   = (const float*)d_in[0];
    const float* Wq  = (const float*)d_in[1];
    const float* Wk  = (const float*)d_in[2];
    const float* Wv  = (const float*)d_in[3];
    const float* lng = (const float*)d_in[4];
    const float* lnb = (const float*)d_in[5];
    const float* W1  = (const float*)d_in[6];
    const float* b1  = (const float*)d_in[7];
    const float* W2  = (const float*)d_in[8];
    const float* b2  = (const float*)d_in[9];
    float* out = (float*)d_out;

    float *Wqkv, *QKV, *X1, *H0, *H1;
    cudaGetSymbolAddress((void**)&Wqkv, g_Wqkv);
    cudaGetSymbolAddress((void**)&QKV,  g_QKV);
    cudaGetSymbolAddress((void**)&X1,   g_x1);
    cudaGetSymbolAddress((void**)&H0,   g_h0);
    cudaGetSymbolAddress((void**)&H1,   g_h1);

    cudaFuncSetAttribute(gemm_tf32<1>, cudaFuncAttributeMaxDynamicSharedMemorySize, GEMM_SMEM_BYTES);
    cudaFuncSetAttribute(gemm_tf32<2>, cudaFuncAttributeMaxDynamicSharedMemorySize, GEMM_SMEM_BYTES);
    cudaFuncSetAttribute(gemm_tf32<3>, cudaFuncAttributeMaxDynamicSharedMemorySize, GEMM_SMEM_BYTES);
    cudaFuncSetAttribute(attention_tc, cudaFuncAttributeMaxDynamicSharedMemorySize, ATT_SMEM_BYTES);

    const dim3 blk(256);

    // weight concat + fused QKV projection (Q columns scaled by 1/sqrt(DH))
    concat_qkv<<<(DD * (NQKV/4) + 255) / 256, blk>>>(Wq, Wk, Wv, Wqkv);
    gemm_tf32<3><<<dim3(NQKV/128, MM/128), blk, GEMM_SMEM_BYTES>>>(x, Wqkv, QKV, MM, NQKV, DD, nullptr, nullptr, 1.0f);

    // fused tensor-core attention + residual
    attention_tc<<<dim3(SS/64, HH, BB), blk, ATT_SMEM_BYTES>>>(QKV, x, X1);

    // layernorm
    ln_kernel<<<MM, 256>>>(X1, lng, lnb, H0);

    // FFN
    gemm_tf32<1><<<dim3(DF/128, MM/128), blk, GEMM_SMEM_BYTES>>>(H0, W1, H1, MM, DF, DD, b1, nullptr, 1.0f);
    gemm_tf32<2><<<dim3(DD/128, MM/128), blk, GEMM_SMEM_BYTES>>>(H1, W2, out, MM, DD, DF, b2, X1, 1.0f);
}

// round 4
// speedup vs baseline: 2.3459x; 1.2275x over previous
#include <cuda_runtime.h>
#include <cstdint>

// ---------------- problem constants ----------------
#define BB 4
#define SS 1024
#define DD 1280
#define HH 20
#define DH 64
#define DF 5120
#define MM (BB*SS)          // 4096 rows
#define NQKV (3*DD)         // 3840

// ---------------- scratch (device globals; no cudaMalloc allowed) ----------------
__device__ float g_Wqkv[(size_t)DD*NQKV];    // concatenated [Wq|Wk|Wv]
__device__ float g_QKV [(size_t)MM*NQKV];    // fused qkv projections
__device__ float g_x1[MM*DD];
__device__ float g_h0[MM*DD];
__device__ float g_h1[(size_t)MM*DF];

#define ABLK 132
#define BBLK 68

__device__ __forceinline__ float f2tf(float f) {
    uint32_t u;
    asm("cvt.rna.tf32.f32 %0, %1;" : "=r"(u) : "f"(f));
    return __uint_as_float(u);
}

__device__ __forceinline__ void mma_tf32(float c[4], const uint32_t a[4], const uint32_t b[2]) {
    asm volatile(
        "mma.sync.aligned.m16n8k8.row.col.f32.tf32.tf32.f32 "
        "{%0,%1,%2,%3}, {%4,%5,%6,%7}, {%8,%9}, {%0,%1,%2,%3};\n"
        : "+f"(c[0]), "+f"(c[1]), "+f"(c[2]), "+f"(c[3])
        : "r"(a[0]), "r"(a[1]), "r"(a[2]), "r"(a[3]), "r"(b[0]), "r"(b[1]));
}

// ============================================================================
// TF32 tensor-core GEMM. 128x128 tile, BK=32, 256 thr, now 2 CTAs/SM.
// MODE 1: relu(A@B+bias); MODE 2: A@B+bias+resid; MODE 3: qkv (col<DD scaled)
// ============================================================================
#define A_FLOATS (4*8*ABLK)
#define B_FLOATS (4*16*BBLK)
#define BUF_FLOATS (A_FLOATS + B_FLOATS)
#define GEMM_SMEM_BYTES (2*BUF_FLOATS*4)

template <int MODE>
__global__ void __launch_bounds__(256, 2)
gemm_tf32(const float* __restrict__ A, const float* __restrict__ Bm,
          float* __restrict__ C, int M, int N, int K,
          const float* __restrict__ bias, const float* __restrict__ resid,
          float alpha)
{
    extern __shared__ float sm[];
    float* Abuf[2] = { sm,            sm + BUF_FLOATS };
    float* Bbuf[2] = { sm + A_FLOATS, sm + BUF_FLOATS + A_FLOATS };

    const int t    = threadIdx.x;
    const int lane = t & 31;
    const int w    = t >> 5;
    const int wm   = w & 1;
    const int wn   = w >> 1;
    const int g    = lane >> 2;
    const int tg   = lane & 3;
    const int m0   = blockIdx.y * 128;
    const int n0   = blockIdx.x * 128;

    const int ar = t >> 3;
    const int ac = (t & 7) * 4;
    const int bk = t >> 5;
    const int bn = (t & 31) * 4;

    const float* Ag = A  + (size_t)(m0 + ar) * K + ac;
    const float* Bg = Bm + (size_t)bk * N + (n0 + bn);

    const int kcA   = ac >> 3;
    const int slotA = ((ar & 8) >> 3) | ((ac & 4) >> 1);
    const int rlA   = ar & 7;
    const int mtHi  = ar >> 4;
    const int ntB = bn >> 3;
    const int lbB = (bn & 7) * 4 + (bk & 3);
    const int slB = (bk & 4) >> 2;

    float4 aR[4], bR[4];
#pragma unroll
    for (int p = 0; p < 4; p++) aR[p] = *(const float4*)(Ag + (size_t)p * 32 * K);
#pragma unroll
    for (int p = 0; p < 4; p++) bR[p] = *(const float4*)(Bg + (size_t)p * 8 * N);

    float acc[4][4][4];
#pragma unroll
    for (int i = 0; i < 4; i++)
#pragma unroll
        for (int j = 0; j < 4; j++)
#pragma unroll
            for (int q = 0; q < 4; q++) acc[i][j][q] = 0.f;

    auto sts = [&](int buf) {
#pragma unroll
        for (int p = 0; p < 4; p++) {
            float va[4] = { aR[p].x, aR[p].y, aR[p].z, aR[p].w };
            float vb[4] = { bR[p].x, bR[p].y, bR[p].z, bR[p].w };
#pragma unroll
            for (int j = 0; j < 4; j++) {
                Abuf[buf][(kcA * 8 + p * 2 + mtHi) * ABLK + rlA * 16 + j * 4 + slotA] = f2tf(va[j]);
                Bbuf[buf][(p * 16 + ntB) * BBLK + (lbB + j * 4) * 2 + slB]            = f2tf(vb[j]);
            }
        }
    };

    sts(0);
    __syncthreads();

    const int KT = K >> 5;
    for (int kt = 0; kt < KT; kt++) {
        const int cur = kt & 1;
        if (kt + 1 < KT) {
            const float* Ag2 = Ag + (kt + 1) * 32;
            const float* Bg2 = Bg + (size_t)(kt + 1) * 32 * N;
#pragma unroll
            for (int p = 0; p < 4; p++) aR[p] = *(const float4*)(Ag2 + (size_t)p * 32 * K);
#pragma unroll
            for (int p = 0; p < 4; p++) bR[p] = *(const float4*)(Bg2 + (size_t)p * 8 * N);
        }

#pragma unroll
        for (int kc = 0; kc < 4; kc++) {
            uint32_t af[4][4], bf[4][2];
#pragma unroll
            for (int i = 0; i < 4; i++) {
                uint4 v = *(const uint4*)&Abuf[cur][(kc * 8 + wm * 4 + i) * ABLK + lane * 4];
                af[i][0] = v.x; af[i][1] = v.y; af[i][2] = v.z; af[i][3] = v.w;
            }
#pragma unroll
            for (int j = 0; j < 4; j++) {
                uint2 v = *(const uint2*)&Bbuf[cur][(kc * 16 + wn * 4 + j) * BBLK + lane * 2];
                bf[j][0] = v.x; bf[j][1] = v.y;
            }
#pragma unroll
            for (int i = 0; i < 4; i++)
#pragma unroll
                for (int j = 0; j < 4; j++)
                    mma_tf32(acc[i][j], af[i], bf[j]);
        }

        if (kt + 1 < KT) sts(1 - cur);
        __syncthreads();
    }

    const int mrow = m0 + wm * 64;
    const int ncol = n0 + wn * 32;
#pragma unroll
    for (int j = 0; j < 4; j++) {
        const int colj = ncol + j * 8 + tg * 2;
        float2 bv = make_float2(0.f, 0.f);
        if (MODE == 1 || MODE == 2) bv = *(const float2*)(bias + colj);
        const float sc = (MODE == 3) ? ((colj < DD) ? 0.125f : 1.0f) : alpha;
#pragma unroll
        for (int i = 0; i < 4; i++) {
            const int r0 = mrow + i * 16 + g;
            float2 v0 = make_float2(acc[i][j][0], acc[i][j][1]);
            float2 v1 = make_float2(acc[i][j][2], acc[i][j][3]);
            if (MODE == 0 || MODE == 3) {
                v0.x *= sc; v0.y *= sc; v1.x *= sc; v1.y *= sc;
            } else if (MODE == 1) {
                v0.x = fmaxf(v0.x + bv.x, 0.f); v0.y = fmaxf(v0.y + bv.y, 0.f);
                v1.x = fmaxf(v1.x + bv.x, 0.f); v1.y = fmaxf(v1.y + bv.y, 0.f);
            } else {
                float2 r0v = *(const float2*)(resid + (size_t)r0 * N + colj);
                float2 r1v = *(const float2*)(resid + (size_t)(r0 + 8) * N + colj);
                v0.x += bv.x + r0v.x; v0.y += bv.y + r0v.y;
                v1.x += bv.x + r1v.x; v1.y += bv.y + r1v.y;
            }
            *(float2*)(C + (size_t)r0 * N + colj)       = v0;
            *(float2*)(C + (size_t)(r0 + 8) * N + colj) = v1;
        }
    }
}

// ============================================================================
// Weight concat: g_Wqkv = [Wq | Wk | Wv], 1280 x 3840
// ============================================================================
__global__ void concat_qkv(const float* __restrict__ Wq, const float* __restrict__ Wk,
                           const float* __restrict__ Wv, float* __restrict__ W)
{
    int i = blockIdx.x * 256 + threadIdx.x;
    if (i >= DD * (NQKV / 4)) return;
    int r  = i / (NQKV / 4);
    int c4 = i % (NQKV / 4);
    float4 v;
    if      (c4 < 320) v = ((const float4*)Wq)[r * 320 + c4];
    else if (c4 < 640) v = ((const float4*)Wk)[r * 320 + c4 - 320];
    else               v = ((const float4*)Wv)[r * 320 + c4 - 640];
    ((float4*)W)[i] = v;
}

// ============================================================================
// Tensor-core flash attention. Block = (qtile 64, h, b), 256 thr = 8 warps
// (4 in M x 2 in N). Key tile = 64 (smem 70.4KB -> 2 CTAs/SM).
// smem (floats): Qs 4224 | Ks 4352 | Vs 4352 | Ps 4224 | aux 448 = 17600
// ============================================================================
#define ATT_SMEM_FLOATS 17600
#define ATT_SMEM_BYTES  (ATT_SMEM_FLOATS*4)

__global__ void __launch_bounds__(256, 2)
attention_tc(const float* __restrict__ QKV, const float* __restrict__ X,
             float* __restrict__ X1)
{
    extern __shared__ float sm[];
    float* Qs   = sm;                  // A-layout, M=64 (4 mt), K=64 (8 kc)
    float* Ks   = Qs + 4224;           // B-layout, k=64 (8 kc), n=64 (8 nt)
    float* Vs   = Ks + 4352;           // B-layout, k=64 (8 kc), n=64 (8 nt)
    float* Ps   = Vs + 4352;           // A-layout, M=64 (4 mt), K=64 (8 kc)
    float* m_s  = Ps + 4224;
    float* l_s  = m_s + 64;
    float* al_s = l_s + 64;
    float* red_m= al_s + 64;           // [row][wn] -> 128
    float* red_s= red_m + 128;         // [row][wn] -> 128

    const int t    = threadIdx.x;
    const int lane = t & 31;
    const int w    = t >> 5;
    const int wm   = w & 3;            // 4 warps in M (query rows)
    const int wn   = w >> 2;           // 2 warps in N
    const int g    = lane >> 2;
    const int tg   = lane & 3;

    const int qb   = blockIdx.x * 64;
    const int h    = blockIdx.y;
    const int b    = blockIdx.z;
    const int brow = b * SS;

    // ---- load Q tile (64 x 64) into A-permuted smem ----
    {
        const float* Qg = QKV + (size_t)(brow + qb) * NQKV + h * DH;
#pragma unroll
        for (int i = 0; i < 4; i++) {
            int e4 = i * 256 + t;
            int q  = e4 >> 4;
            int d4 = (e4 & 15) * 4;
            float4 v = *(const float4*)(Qg + (size_t)q * NQKV + d4);
            float va[4] = { v.x, v.y, v.z, v.w };
            int blkB = (d4 >> 3) * 4 + (q >> 4);
            int base = blkB * 132 + (q & 7) * 16 + ((q & 8) >> 3) + ((d4 & 4) >> 1);
#pragma unroll
            for (int j = 0; j < 4; j++)
                Qs[base + j * 4] = f2tf(va[j]);
        }
    }
    if (t < 64) { m_s[t] = -1e30f; l_s[t] = 0.f; }

    float oacc[4][4];
#pragma unroll
    for (int i = 0; i < 4; i++)
#pragma unroll
        for (int j = 0; j < 4; j++) oacc[i][j] = 0.f;
    __syncthreads();

    const int row0 = wm * 16 + g;
    const int row1 = row0 + 8;

    for (int kb = 0; kb < SS; kb += 64) {
        // ---- load K,V tiles (64 x 64) into B-permuted smem ----
        {
            const float* Kg = QKV + (size_t)(brow + kb) * NQKV + DD     + h * DH;
            const float* Vg = QKV + (size_t)(brow + kb) * NQKV + 2 * DD + h * DH;
#pragma unroll
            for (int i = 0; i < 4; i++) {
                int e4 = i * 256 + t;
                int r  = e4 >> 4;
                int d4 = (e4 & 15) * 4;
                float4 kv = *(const float4*)(Kg + (size_t)r * NQKV + d4);
                float4 vv = *(const float4*)(Vg + (size_t)r * NQKV + d4);
                float ka[4] = { kv.x, kv.y, kv.z, kv.w };
                float va[4] = { vv.x, vv.y, vv.z, vv.w };
                // K: (k=d, n=r), 8 nt
                int kbase = ((d4 >> 3) * 8 + (r >> 3)) * 68 + (r & 7) * 8 + ((d4 & 4) >> 2);
                // V: (k=r, n=d), 8 nt
                int vbase = ((r >> 3) * 8 + (d4 >> 3)) * 68 + (d4 & 7) * 8 + (r & 3) * 2 + ((r & 4) >> 2);
#pragma unroll
                for (int j = 0; j < 4; j++) {
                    Ks[kbase + j * 2] = f2tf(ka[j]);
                    Vs[vbase + j * 8] = f2tf(va[j]);
                }
            }
        }
        __syncthreads();

        // ---- S = Q @ K^T : warp tile 16 x 32 ----
        float sacc[4][4];
#pragma unroll
        for (int j = 0; j < 4; j++)
#pragma unroll
            for (int q = 0; q < 4; q++) sacc[j][q] = 0.f;

#pragma unroll
        for (int kc = 0; kc < 8; kc++) {
            uint32_t af[4];
            uint4 av = *(const uint4*)&Qs[(kc * 4 + wm) * 132 + lane * 4];
            af[0] = av.x; af[1] = av.y; af[2] = av.z; af[3] = av.w;
#pragma unroll
            for (int j = 0; j < 4; j++) {
                uint32_t bf[2];
                uint2 bv = *(const uint2*)&Ks[(kc * 8 + wn * 4 + j) * 68 + lane * 2];
                bf[0] = bv.x; bf[1] = bv.y;
                mma_tf32(sacc[j], af, bf);
            }
        }

        // ---- softmax: row max ----
        float pm0 = -1e30f, pm1 = -1e30f;
#pragma unroll
        for (int j = 0; j < 4; j++) {
            pm0 = fmaxf(pm0, fmaxf(sacc[j][0], sacc[j][1]));
            pm1 = fmaxf(pm1, fmaxf(sacc[j][2], sacc[j][3]));
        }
        pm0 = fmaxf(pm0, __shfl_xor_sync(0xffffffffu, pm0, 1));
        pm0 = fmaxf(pm0, __shfl_xor_sync(0xffffffffu, pm0, 2));
        pm1 = fmaxf(pm1, __shfl_xor_sync(0xffffffffu, pm1, 1));
        pm1 = fmaxf(pm1, __shfl_xor_sync(0xffffffffu, pm1, 2));
        if (tg == 0) {
            red_m[row0 * 2 + wn] = pm0;
            red_m[row1 * 2 + wn] = pm1;
        }
        __syncthreads();
        if (t < 64) {
            float mold = m_s[t];
            float mnew = fmaxf(mold, fmaxf(red_m[t * 2], red_m[t * 2 + 1]));
            m_s[t]  = mnew;
            al_s[t] = __expf(mold - mnew);
        }
        __syncthreads();

        // ---- exp, store P (A-layout), row sums, rescale O ----
        const float mn0 = m_s[row0], mn1 = m_s[row1];
        const float al0 = al_s[row0], al1 = al_s[row1];
        float rs0 = 0.f, rs1 = 0.f;
        const int s2 = ((tg * 2) & 3) * 4 + (((tg * 2) & 4) >> 1);
#pragma unroll
        for (int j = 0; j < 4; j++) {
            float p00 = __expf(sacc[j][0] - mn0);
            float p01 = __expf(sacc[j][1] - mn0);
            float p10 = __expf(sacc[j][2] - mn1);
            float p11 = __expf(sacc[j][3] - mn1);
            rs0 += p00 + p01;
            rs1 += p10 + p11;
            int base = ((wn * 4 + j) * 4 + wm) * 132 + g * 16 + s2;
            Ps[base    ] = f2tf(p00);
            Ps[base + 4] = f2tf(p01);
            Ps[base + 1] = f2tf(p10);
            Ps[base + 5] = f2tf(p11);
        }
        rs0 += __shfl_xor_sync(0xffffffffu, rs0, 1);
        rs0 += __shfl_xor_sync(0xffffffffu, rs0, 2);
        rs1 += __shfl_xor_sync(0xffffffffu, rs1, 1);
        rs1 += __shfl_xor_sync(0xffffffffu, rs1, 2);
        if (tg == 0) {
            red_s[row0 * 2 + wn] = rs0;
            red_s[row1 * 2 + wn] = rs1;
        }
#pragma unroll
        for (int i = 0; i < 4; i++) {
            oacc[i][0] *= al0; oacc[i][1] *= al0;
            oacc[i][2] *= al1; oacc[i][3] *= al1;
        }
        __syncthreads();
        if (t < 64)
            l_s[t] = l_s[t] * al_s[t] + red_s[t * 2] + red_s[t * 2 + 1];

        // ---- O += P @ V : warp tile 16 x 32 ----
#pragma unroll
        for (int kc = 0; kc < 8; kc++) {
            uint32_t af[4];
            uint4 av = *(const uint4*)&Ps[(kc * 4 + wm) * 132 + lane * 4];
            af[0] = av.x; af[1] = av.y; af[2] = av.z; af[3] = av.w;
#pragma unroll
            for (int j = 0; j < 4; j++) {
                uint32_t bf[2];
                uint2 bv = *(const uint2*)&Vs[(kc * 8 + wn * 4 + j) * 68 + lane * 2];
                bf[0] = bv.x; bf[1] = bv.y;
                mma_tf32(oacc[j], af, bf);
            }
        }
        __syncthreads();
    }

    // ---- epilogue: X1 = O/l + X ----
    const float il0 = 1.f / l_s[row0];
    const float il1 = 1.f / l_s[row1];
    const size_t tok0 = (size_t)(brow + qb + row0);
    const size_t tok1 = (size_t)(brow + qb + row1);
#pragma unroll
    for (int j = 0; j < 4; j++) {
        const int col = h * DH + (wn * 4 + j) * 8 + tg * 2;
        float2 x0 = *(const float2*)(X + tok0 * DD + col);
        float2 x1 = *(const float2*)(X + tok1 * DD + col);
        float2 o0 = make_float2(oacc[j][0] * il0 + x0.x, oacc[j][1] * il0 + x0.y);
        float2 o1 = make_float2(oacc[j][2] * il1 + x1.x, oacc[j][3] * il1 + x1.y);
        *(float2*)(X1 + tok0 * DD + col) = o0;
        *(float2*)(X1 + tok1 * DD + col) = o1;
    }
}

// ============================================================================
// LayerNorm over D=1280. One block per row, 256 threads.
// ============================================================================
__global__ void __launch_bounds__(256)
ln_kernel(const float* __restrict__ X, const float* __restrict__ gam,
          const float* __restrict__ bet, float* __restrict__ Y)
{
    const int row = blockIdx.x;
    const float* xr = X + (size_t)row * DD;
    float v[5];
    float sum = 0.f, sq = 0.f;
#pragma unroll
    for (int i = 0; i < 5; i++) {
        v[i] = xr[threadIdx.x + i * 256];
        sum += v[i];
        sq  += v[i] * v[i];
    }
#pragma unroll
    for (int off = 16; off; off >>= 1) {
        sum += __shfl_xor_sync(0xffffffffu, sum, off);
        sq  += __shfl_xor_sync(0xffffffffu, sq , off);
    }
    __shared__ float sS[8], sQ[8];
    const int w = threadIdx.x >> 5, lane = threadIdx.x & 31;
    if (lane == 0) { sS[w] = sum; sQ[w] = sq; }
    __syncthreads();
    if (threadIdx.x == 0) {
        float a = 0.f, q = 0.f;
#pragma unroll
        for (int i = 0; i < 8; i++) { a += sS[i]; q += sQ[i]; }
        sS[0] = a; sQ[0] = q;
    }
    __syncthreads();
    const float mu   = sS[0] * (1.0f / DD);
    const float var  = sQ[0] * (1.0f / DD) - mu * mu;
    const float rstd = rsqrtf(var + 1e-5f);
    float* yr = Y + (size_t)row * DD;
#pragma unroll
    for (int i = 0; i < 5; i++) {
        int c = threadIdx.x + i * 256;
        yr[c] = (v[i] - mu) * rstd * gam[c] + bet[c];
    }
}

// ============================================================================
// launch
// ============================================================================
extern "C" void kernel_launch(void* const* d_in, const int* in_sizes, int n_in,
                              void* d_out, int out_size)
{
    const float* x   = (const float*)d_in[0];
    const float* Wq  = (const float*)d_in[1];
    const float* Wk  = (const float*)d_in[2];
    const float* Wv  = (const float*)d_in[3];
    const float* lng = (const float*)d_in[4];
    const float* lnb = (const float*)d_in[5];
    const float* W1  = (const float*)d_in[6];
    const float* b1  = (const float*)d_in[7];
    const float* W2  = (const float*)d_in[8];
    const float* b2  = (const float*)d_in[9];
    float* out = (float*)d_out;

    float *Wqkv, *QKV, *X1, *H0, *H1;
    cudaGetSymbolAddress((void**)&Wqkv, g_Wqkv);
    cudaGetSymbolAddress((void**)&QKV,  g_QKV);
    cudaGetSymbolAddress((void**)&X1,   g_x1);
    cudaGetSymbolAddress((void**)&H0,   g_h0);
    cudaGetSymbolAddress((void**)&H1,   g_h1);

    cudaFuncSetAttribute(gemm_tf32<1>, cudaFuncAttributeMaxDynamicSharedMemorySize, GEMM_SMEM_BYTES);
    cudaFuncSetAttribute(gemm_tf32<2>, cudaFuncAttributeMaxDynamicSharedMemorySize, GEMM_SMEM_BYTES);
    cudaFuncSetAttribute(gemm_tf32<3>, cudaFuncAttributeMaxDynamicSharedMemorySize, GEMM_SMEM_BYTES);
    cudaFuncSetAttribute(attention_tc, cudaFuncAttributeMaxDynamicSharedMemorySize, ATT_SMEM_BYTES);

    const dim3 blk(256);

    // weight concat + fused QKV projection (Q columns scaled by 1/sqrt(DH))
    concat_qkv<<<(DD * (NQKV/4) + 255) / 256, blk>>>(Wq, Wk, Wv, Wqkv);
    gemm_tf32<3><<<dim3(NQKV/128, MM/128), blk, GEMM_SMEM_BYTES>>>(x, Wqkv, QKV, MM, NQKV, DD, nullptr, nullptr, 1.0f);

    // fused tensor-core attention + residual
    attention_tc<<<dim3(SS/64, HH, BB), blk, ATT_SMEM_BYTES>>>(QKV, x, X1);

    // layernorm
    ln_kernel<<<MM, 256>>>(X1, lng, lnb, H0);

    // FFN
    gemm_tf32<1><<<dim3(DF/128, MM/128), blk, GEMM_SMEM_BYTES>>>(H0, W1, H1, MM, DF, DD, b1, nullptr, 1.0f);
    gemm_tf32<2><<<dim3(DD/128, MM/128), blk, GEMM_SMEM_BYTES>>>(H1, W2, out, MM, DD, DF, b2, X1, 1.0f);
}

// round 6
// speedup vs baseline: 3.7772x; 1.6101x over previous
#include <cuda_runtime.h>
#include <cstdint>

// ---------------- problem constants ----------------
#define BB 4
#define SS 1024
#define DD 1280
#define HH 20
#define DH 64
#define DF 5120
#define MM (BB*SS)          // 4096 rows
#define NQKV (3*DD)         // 3840

// ---------------- scratch (device globals; no cudaMalloc allowed) ----------------
__device__ float g_xr  [(size_t)MM*DD];      // tf32-rounded x
__device__ float g_Wqkv[(size_t)DD*NQKV];    // concat + rounded (+Q scale)
__device__ float g_W1r [(size_t)DD*DF];
__device__ float g_W2r [(size_t)DF*DD];
__device__ float g_QKV [(size_t)MM*NQKV];
__device__ float g_x1  [MM*DD];
__device__ float g_h0  [MM*DD];              // rounded LN output
__device__ float g_h1  [(size_t)MM*DF];      // rounded FFN1 output

__device__ __forceinline__ float f2tf(float f) {
    uint32_t u;
    asm("cvt.rna.tf32.f32 %0, %1;" : "=r"(u) : "f"(f));
    return __uint_as_float(u);
}

__device__ __forceinline__ void mma_tf32(float c[4], const uint32_t a[4], const uint32_t b[2]) {
    asm volatile(
        "mma.sync.aligned.m16n8k8.row.col.f32.tf32.tf32.f32 "
        "{%0,%1,%2,%3}, {%4,%5,%6,%7}, {%8,%9}, {%0,%1,%2,%3};\n"
        : "+f"(c[0]), "+f"(c[1]), "+f"(c[2]), "+f"(c[3])
        : "r"(a[0]), "r"(a[1]), "r"(a[2]), "r"(a[3]), "r"(b[0]), "r"(b[1]));
}

__device__ __forceinline__ uint32_t smem_u32(const void* p) {
    uint32_t a;
    asm("{ .reg .u64 t; cvta.to.shared.u64 t, %1; cvt.u32.u64 %0, t; }" : "=r"(a) : "l"(p));
    return a;
}

#define CP_ASYNC16(sm, gp) \
    asm volatile("cp.async.cg.shared.global [%0], [%1], 16;" :: "r"(sm), "l"(gp) : "memory")
#define CP_COMMIT() asm volatile("cp.async.commit_group;" ::: "memory")
#define CP_WAIT0()  asm volatile("cp.async.wait_group 0;" ::: "memory")

// ============================================================================
// Pre-rounding kernels (inputs already tf32-exact => GEMM needs no cvt)
// ============================================================================
__global__ void round_tf32(const float* __restrict__ in, float* __restrict__ out, int n4)
{
    int i = blockIdx.x * 256 + threadIdx.x;
    if (i >= n4) return;
    float4 v = ((const float4*)in)[i];
    v.x = f2tf(v.x); v.y = f2tf(v.y); v.z = f2tf(v.z); v.w = f2tf(v.w);
    ((float4*)out)[i] = v;
}

// concat [Wq|Wk|Wv] -> [DD][NQKV], rounded; Q columns pre-scaled by 1/8 (exact)
__global__ void concat_round(const float* __restrict__ Wq, const float* __restrict__ Wk,
                             const float* __restrict__ Wv, float* __restrict__ W)
{
    int i = blockIdx.x * 256 + threadIdx.x;
    if (i >= DD * (NQKV / 4)) return;
    int r  = i / (NQKV / 4);
    int c4 = i % (NQKV / 4);
    float4 v; float sc = 1.0f;
    if      (c4 < 320) { v = ((const float4*)Wq)[r * 320 + c4];       sc = 0.125f; }
    else if (c4 < 640) { v = ((const float4*)Wk)[r * 320 + c4 - 320]; }
    else               { v = ((const float4*)Wv)[r * 320 + c4 - 640]; }
    v.x = f2tf(v.x * sc); v.y = f2tf(v.y * sc); v.z = f2tf(v.z * sc); v.w = f2tf(v.w * sc);
    ((float4*)W)[i] = v;
}

// ============================================================================
// TF32 GEMM, cp.async 2-stage, linear smem, scattered conflict-free LDS.32.
// Tile 128x128, BK=32, 256 thr (2m x 4n warps, warp 64x32), 2 CTAs/SM.
// Inputs MUST be tf32-pre-rounded. MODE 0: C=AB; 1: round(relu(AB+bias));
// MODE 2: AB+bias+resid.
// ============================================================================
#define AS_STRIDE 36            // (36g+tg) mod 32 = 4g+tg -> conflict-free
#define BS_STRIDE 136           // (136tg+g) mod 32 = 8tg+g -> conflict-free
#define A_ST (128*AS_STRIDE)    // 4608 floats
#define B_ST (32*BS_STRIDE)     // 4352 floats
#define STG  (A_ST + B_ST)      // 8960 floats
#define G_SMEM_BYTES (2*STG*4)  // 71680 B

template <int MODE>
__global__ void __launch_bounds__(256, 2)
gemm_tf32(const float* __restrict__ A, const float* __restrict__ Bm,
          float* __restrict__ C, int M, int N, int K,
          const float* __restrict__ bias, const float* __restrict__ resid)
{
    extern __shared__ float smf[];
    const uint32_t smb = smem_u32(smf);

    const int t    = threadIdx.x;
    const int lane = t & 31;
    const int w    = t >> 5;
    const int wm   = w & 1;
    const int wn   = w >> 1;
    const int g    = lane >> 2;
    const int tg   = lane & 3;
    const int m0   = blockIdx.y * 128;
    const int n0   = blockIdx.x * 128;

    // cp.async source/dest (per-thread)
    const int arow = t >> 3;              // +32 per chunk
    const int acol = (t & 7) * 4;
    const int bkr  = t >> 5;              // +8 per chunk
    const int bnc  = (t & 31) * 4;
    const float* Ag0 = A  + (size_t)(m0 + arow) * K + acol;
    const float* Bg0 = Bm + (size_t)bkr * N + n0 + bnc;
    const uint32_t Asd = smb + (uint32_t)((arow * AS_STRIDE + acol) * 4);
    const uint32_t Bsd = smb + (uint32_t)((A_ST + bkr * BS_STRIDE + bnc) * 4);

    auto issue = [&](int kt, int buf) {
        const uint32_t bo = (uint32_t)(buf * STG * 4);
        const float* Ag = Ag0 + kt * 32;
        const float* Bg = Bg0 + (size_t)(kt * 32) * N;
#pragma unroll
        for (int p = 0; p < 4; p++)
            CP_ASYNC16(Asd + bo + p * 32 * AS_STRIDE * 4, Ag + (size_t)p * 32 * K);
#pragma unroll
        for (int p = 0; p < 4; p++)
            CP_ASYNC16(Bsd + bo + p * 8 * BS_STRIDE * 4, Bg + (size_t)p * 8 * N);
        CP_COMMIT();
    };

    float acc[4][4][4];
#pragma unroll
    for (int i = 0; i < 4; i++)
#pragma unroll
        for (int j = 0; j < 4; j++)
#pragma unroll
            for (int q = 0; q < 4; q++) acc[i][j][q] = 0.f;

    issue(0, 0);

    const int KT = K >> 5;
    for (int kt = 0; kt < KT; kt++) {
        CP_WAIT0();
        __syncthreads();
        if (kt + 1 < KT) issue(kt + 1, (kt + 1) & 1);

        const float* As = smf + (kt & 1) * STG;
        const float* Bs = As + A_ST;
#pragma unroll
        for (int kc = 0; kc < 4; kc++) {
            uint32_t af[4][4], bf[4][2];
            const int c = kc * 8 + tg;
#pragma unroll
            for (int i = 0; i < 4; i++) {
                const int r = wm * 64 + i * 16 + g;
                af[i][0] = __float_as_uint(As[r * AS_STRIDE + c]);
                af[i][1] = __float_as_uint(As[(r + 8) * AS_STRIDE + c]);
                af[i][2] = __float_as_uint(As[r * AS_STRIDE + c + 4]);
                af[i][3] = __float_as_uint(As[(r + 8) * AS_STRIDE + c + 4]);
            }
#pragma unroll
            for (int j = 0; j < 4; j++) {
                const int n = wn * 32 + j * 8 + g;
                bf[j][0] = __float_as_uint(Bs[c * BS_STRIDE + n]);
                bf[j][1] = __float_as_uint(Bs[(c + 4) * BS_STRIDE + n]);
            }
#pragma unroll
            for (int i = 0; i < 4; i++)
#pragma unroll
                for (int j = 0; j < 4; j++)
                    mma_tf32(acc[i][j], af[i], bf[j]);
        }
        __syncthreads();
    }

    // ---------------- epilogue ----------------
    const int mrow = m0 + wm * 64;
    const int ncol = n0 + wn * 32;
#pragma unroll
    for (int j = 0; j < 4; j++) {
        const int colj = ncol + j * 8 + tg * 2;
        float2 bv = make_float2(0.f, 0.f);
        if (MODE == 1 || MODE == 2) bv = *(const float2*)(bias + colj);
#pragma unroll
        for (int i = 0; i < 4; i++) {
            const int r0 = mrow + i * 16 + g;
            float2 v0 = make_float2(acc[i][j][0], acc[i][j][1]);
            float2 v1 = make_float2(acc[i][j][2], acc[i][j][3]);
            if (MODE == 1) {
                v0.x = f2tf(fmaxf(v0.x + bv.x, 0.f)); v0.y = f2tf(fmaxf(v0.y + bv.y, 0.f));
                v1.x = f2tf(fmaxf(v1.x + bv.x, 0.f)); v1.y = f2tf(fmaxf(v1.y + bv.y, 0.f));
            } else if (MODE == 2) {
                float2 r0v = *(const float2*)(resid + (size_t)r0 * N + colj);
                float2 r1v = *(const float2*)(resid + (size_t)(r0 + 8) * N + colj);
                v0.x += bv.x + r0v.x; v0.y += bv.y + r0v.y;
                v1.x += bv.x + r1v.x; v1.y += bv.y + r1v.y;
            }
            *(float2*)(C + (size_t)r0 * N + colj)       = v0;
            *(float2*)(C + (size_t)(r0 + 8) * N + colj) = v1;
        }
    }
}

// ============================================================================
// Tensor-core flash attention (validated round 4). Block = (qtile 64, h, b).
// ============================================================================
#define ATT_SMEM_FLOATS 17600
#define ATT_SMEM_BYTES  (ATT_SMEM_FLOATS*4)

__global__ void __launch_bounds__(256, 2)
attention_tc(const float* __restrict__ QKV, const float* __restrict__ X,
             float* __restrict__ X1)
{
    extern __shared__ float sm[];
    float* Qs   = sm;
    float* Ks   = Qs + 4224;
    float* Vs   = Ks + 4352;
    float* Ps   = Vs + 4352;
    float* m_s  = Ps + 4224;
    float* l_s  = m_s + 64;
    float* al_s = l_s + 64;
    float* red_m= al_s + 64;
    float* red_s= red_m + 128;

    const int t    = threadIdx.x;
    const int lane = t & 31;
    const int w    = t >> 5;
    const int wm   = w & 3;
    const int wn   = w >> 2;
    const int g    = lane >> 2;
    const int tg   = lane & 3;

    const int qb   = blockIdx.x * 64;
    const int h    = blockIdx.y;
    const int b    = blockIdx.z;
    const int brow = b * SS;

    {
        const float* Qg = QKV + (size_t)(brow + qb) * NQKV + h * DH;
#pragma unroll
        for (int i = 0; i < 4; i++) {
            int e4 = i * 256 + t;
            int q  = e4 >> 4;
            int d4 = (e4 & 15) * 4;
            float4 v = *(const float4*)(Qg + (size_t)q * NQKV + d4);
            float va[4] = { v.x, v.y, v.z, v.w };
            int blkB = (d4 >> 3) * 4 + (q >> 4);
            int base = blkB * 132 + (q & 7) * 16 + ((q & 8) >> 3) + ((d4 & 4) >> 1);
#pragma unroll
            for (int j = 0; j < 4; j++)
                Qs[base + j * 4] = f2tf(va[j]);
        }
    }
    if (t < 64) { m_s[t] = -1e30f; l_s[t] = 0.f; }

    float oacc[4][4];
#pragma unroll
    for (int i = 0; i < 4; i++)
#pragma unroll
        for (int j = 0; j < 4; j++) oacc[i][j] = 0.f;
    __syncthreads();

    const int row0 = wm * 16 + g;
    const int row1 = row0 + 8;

    for (int kb = 0; kb < SS; kb += 64) {
        {
            const float* Kg = QKV + (size_t)(brow + kb) * NQKV + DD     + h * DH;
            const float* Vg = QKV + (size_t)(brow + kb) * NQKV + 2 * DD + h * DH;
#pragma unroll
            for (int i = 0; i < 4; i++) {
                int e4 = i * 256 + t;
                int r  = e4 >> 4;
                int d4 = (e4 & 15) * 4;
                float4 kv = *(const float4*)(Kg + (size_t)r * NQKV + d4);
                float4 vv = *(const float4*)(Vg + (size_t)r * NQKV + d4);
                float ka[4] = { kv.x, kv.y, kv.z, kv.w };
                float va[4] = { vv.x, vv.y, vv.z, vv.w };
                int kbase = ((d4 >> 3) * 8 + (r >> 3)) * 68 + (r & 7) * 8 + ((d4 & 4) >> 2);
                int vbase = ((r >> 3) * 8 + (d4 >> 3)) * 68 + (d4 & 7) * 8 + (r & 3) * 2 + ((r & 4) >> 2);
#pragma unroll
                for (int j = 0; j < 4; j++) {
                    Ks[kbase + j * 2] = f2tf(ka[j]);
                    Vs[vbase + j * 8] = f2tf(va[j]);
                }
            }
        }
        __syncthreads();

        float sacc[4][4];
#pragma unroll
        for (int j = 0; j < 4; j++)
#pragma unroll
            for (int q = 0; q < 4; q++) sacc[j][q] = 0.f;

#pragma unroll
        for (int kc = 0; kc < 8; kc++) {
            uint32_t af[4];
            uint4 av = *(const uint4*)&Qs[(kc * 4 + wm) * 132 + lane * 4];
            af[0] = av.x; af[1] = av.y; af[2] = av.z; af[3] = av.w;
#pragma unroll
            for (int j = 0; j < 4; j++) {
                uint32_t bf[2];
                uint2 bv = *(const uint2*)&Ks[(kc * 8 + wn * 4 + j) * 68 + lane * 2];
                bf[0] = bv.x; bf[1] = bv.y;
                mma_tf32(sacc[j], af, bf);
            }
        }

        float pm0 = -1e30f, pm1 = -1e30f;
#pragma unroll
        for (int j = 0; j < 4; j++) {
            pm0 = fmaxf(pm0, fmaxf(sacc[j][0], sacc[j][1]));
            pm1 = fmaxf(pm1, fmaxf(sacc[j][2], sacc[j][3]));
        }
        pm0 = fmaxf(pm0, __shfl_xor_sync(0xffffffffu, pm0, 1));
        pm0 = fmaxf(pm0, __shfl_xor_sync(0xffffffffu, pm0, 2));
        pm1 = fmaxf(pm1, __shfl_xor_sync(0xffffffffu, pm1, 1));
        pm1 = fmaxf(pm1, __shfl_xor_sync(0xffffffffu, pm1, 2));
        if (tg == 0) {
            red_m[row0 * 2 + wn] = pm0;
            red_m[row1 * 2 + wn] = pm1;
        }
        __syncthreads();
        if (t < 64) {
            float mold = m_s[t];
            float mnew = fmaxf(mold, fmaxf(red_m[t * 2], red_m[t * 2 + 1]));
            m_s[t]  = mnew;
            al_s[t] = __expf(mold - mnew);
        }
        __syncthreads();

        const float mn0 = m_s[row0], mn1 = m_s[row1];
        const float al0 = al_s[row0], al1 = al_s[row1];
        float rs0 = 0.f, rs1 = 0.f;
        const int s2 = ((tg * 2) & 3) * 4 + (((tg * 2) & 4) >> 1);
#pragma unroll
        for (int j = 0; j < 4; j++) {
            float p00 = __expf(sacc[j][0] - mn0);
            float p01 = __expf(sacc[j][1] - mn0);
            float p10 = __expf(sacc[j][2] - mn1);
            float p11 = __expf(sacc[j][3] - mn1);
            rs0 += p00 + p01;
            rs1 += p10 + p11;
            int base = ((wn * 4 + j) * 4 + wm) * 132 + g * 16 + s2;
            Ps[base    ] = f2tf(p00);
            Ps[base + 4] = f2tf(p01);
            Ps[base + 1] = f2tf(p10);
            Ps[base + 5] = f2tf(p11);
        }
        rs0 += __shfl_xor_sync(0xffffffffu, rs0, 1);
        rs0 += __shfl_xor_sync(0xffffffffu, rs0, 2);
        rs1 += __shfl_xor_sync(0xffffffffu, rs1, 1);
        rs1 += __shfl_xor_sync(0xffffffffu, rs1, 2);
        if (tg == 0) {
            red_s[row0 * 2 + wn] = rs0;
            red_s[row1 * 2 + wn] = rs1;
        }
#pragma unroll
        for (int i = 0; i < 4; i++) {
            oacc[i][0] *= al0; oacc[i][1] *= al0;
            oacc[i][2] *= al1; oacc[i][3] *= al1;
        }
        __syncthreads();
        if (t < 64)
            l_s[t] = l_s[t] * al_s[t] + red_s[t * 2] + red_s[t * 2 + 1];

#pragma unroll
        for (int kc = 0; kc < 8; kc++) {
            uint32_t af[4];
            uint4 av = *(const uint4*)&Ps[(kc * 4 + wm) * 132 + lane * 4];
            af[0] = av.x; af[1] = av.y; af[2] = av.z; af[3] = av.w;
#pragma unroll
            for (int j = 0; j < 4; j++) {
                uint32_t bf[2];
                uint2 bv = *(const uint2*)&Vs[(kc * 8 + wn * 4 + j) * 68 + lane * 2];
                bf[0] = bv.x; bf[1] = bv.y;
                mma_tf32(oacc[j], af, bf);
            }
        }
        __syncthreads();
    }

    const float il0 = 1.f / l_s[row0];
    const float il1 = 1.f / l_s[row1];
    const size_t tok0 = (size_t)(brow + qb + row0);
    const size_t tok1 = (size_t)(brow + qb + row1);
#pragma unroll
    for (int j = 0; j < 4; j++) {
        const int col = h * DH + (wn * 4 + j) * 8 + tg * 2;
        float2 x0 = *(const float2*)(X + tok0 * DD + col);
        float2 x1 = *(const float2*)(X + tok1 * DD + col);
        float2 o0 = make_float2(oacc[j][0] * il0 + x0.x, oacc[j][1] * il0 + x0.y);
        float2 o1 = make_float2(oacc[j][2] * il1 + x1.x, oacc[j][3] * il1 + x1.y);
        *(float2*)(X1 + tok0 * DD + col) = o0;
        *(float2*)(X1 + tok1 * DD + col) = o1;
    }
}

// ============================================================================
// LayerNorm over D=1280; output tf32-pre-rounded for the FFN1 GEMM.
// ============================================================================
__global__ void __launch_bounds__(256)
ln_kernel(const float* __restrict__ X, const float* __restrict__ gam,
          const float* __restrict__ bet, float* __restrict__ Y)
{
    const int row = blockIdx.x;
    const float* xr = X + (size_t)row * DD;
    float v[5];
    float sum = 0.f, sq = 0.f;
#pragma unroll
    for (int i = 0; i < 5; i++) {
        v[i] = xr[threadIdx.x + i * 256];
        sum += v[i];
        sq  += v[i] * v[i];
    }
#pragma unroll
    for (int off = 16; off; off >>= 1) {
        sum += __shfl_xor_sync(0xffffffffu, sum, off);
        sq  += __shfl_xor_sync(0xffffffffu, sq , off);
    }
    __shared__ float sS[8], sQ[8];
    const int w = threadIdx.x >> 5, lane = threadIdx.x & 31;
    if (lane == 0) { sS[w] = sum; sQ[w] = sq; }
    __syncthreads();
    if (threadIdx.x == 0) {
        float a = 0.f, q = 0.f;
#pragma unroll
        for (int i = 0; i < 8; i++) { a += sS[i]; q += sQ[i]; }
        sS[0] = a; sQ[0] = q;
    }
    __syncthreads();
    const float mu   = sS[0] * (1.0f / DD);
    const float var  = sQ[0] * (1.0f / DD) - mu * mu;
    const float rstd = rsqrtf(var + 1e-5f);
    float* yr = Y + (size_t)row * DD;
#pragma unroll
    for (int i = 0; i < 5; i++) {
        int c = threadIdx.x + i * 256;
        yr[c] = f2tf((v[i] - mu) * rstd * gam[c] + bet[c]);
    }
}

// ============================================================================
// launch
// ============================================================================
extern "C" void kernel_launch(void* const* d_in, const int* in_sizes, int n_in,
                              void* d_out, int out_size)
{
    const float* x   = (const float*)d_in[0];
    const float* Wq  = (const float*)d_in[1];
    const float* Wk  = (const float*)d_in[2];
    const float* Wv  = (const float*)d_in[3];
    const float* lng = (const float*)d_in[4];
    const float* lnb = (const float*)d_in[5];
    const float* W1  = (const float*)d_in[6];
    const float* b1  = (const float*)d_in[7];
    const float* W2  = (const float*)d_in[8];
    const float* b2  = (const float*)d_in[9];
    float* out = (float*)d_out;

    float *XR, *Wqkv, *W1r, *W2r, *QKV, *X1, *H0, *H1;
    cudaGetSymbolAddress((void**)&XR,   g_xr);
    cudaGetSymbolAddress((void**)&Wqkv, g_Wqkv);
    cudaGetSymbolAddress((void**)&W1r,  g_W1r);
    cudaGetSymbolAddress((void**)&W2r,  g_W2r);
    cudaGetSymbolAddress((void**)&QKV,  g_QKV);
    cudaGetSymbolAddress((void**)&X1,   g_x1);
    cudaGetSymbolAddress((void**)&H0,   g_h0);
    cudaGetSymbolAddress((void**)&H1,   g_h1);

    cudaFuncSetAttribute(gemm_tf32<0>, cudaFuncAttributeMaxDynamicSharedMemorySize, G_SMEM_BYTES);
    cudaFuncSetAttribute(gemm_tf32<1>, cudaFuncAttributeMaxDynamicSharedMemorySize, G_SMEM_BYTES);
    cudaFuncSetAttribute(gemm_tf32<2>, cudaFuncAttributeMaxDynamicSharedMemorySize, G_SMEM_BYTES);
    cudaFuncSetAttribute(attention_tc, cudaFuncAttributeMaxDynamicSharedMemorySize, ATT_SMEM_BYTES);

    const dim3 blk(256);

    // pre-round inputs/weights to tf32 (exact for the GEMMs)
    round_tf32<<<(MM*DD/4 + 255)/256, blk>>>(x, XR, MM*DD/4);
    concat_round<<<(DD*(NQKV/4) + 255)/256, blk>>>(Wq, Wk, Wv, Wqkv);
    round_tf32<<<((int)((size_t)DD*DF/4) + 255)/256, blk>>>(W1, W1r, (int)((size_t)DD*DF/4));
    round_tf32<<<((int)((size_t)DF*DD/4) + 255)/256, blk>>>(W2, W2r, (int)((size_t)DF*DD/4));

    // QKV projection
    gemm_tf32<0><<<dim3(NQKV/128, MM/128), blk, G_SMEM_BYTES>>>(XR, Wqkv, QKV, MM, NQKV, DD, nullptr, nullptr);

    // fused tensor-core attention + residual
    attention_tc<<<dim3(SS/64, HH, BB), blk, ATT_SMEM_BYTES>>>(QKV, x, X1);

    // layernorm (rounded output)
    ln_kernel<<<MM, 256>>>(X1, lng, lnb, H0);

    // FFN
    gemm_tf32<1><<<dim3(DF/128, MM/128), blk, G_SMEM_BYTES>>>(H0, W1r, H1, MM, DF, DD, b1, nullptr);
    gemm_tf32<2><<<dim3(DD/128, MM/128), blk, G_SMEM_BYTES>>>(H1, W2r, out, MM, DD, DF, b2, X1);
}

// round 7
// speedup vs baseline: 4.0838x; 1.0812x over previous
#include <cuda_runtime.h>
#include <cstdint>

// ---------------- problem constants ----------------
#define BB 4
#define SS 1024
#define DD 1280
#define HH 20
#define DH 64
#define DF 5120
#define MM (BB*SS)          // 4096 rows
#define NQKV (3*DD)         // 3840

// ---------------- scratch (device globals) ----------------
__device__ float g_xr  [(size_t)MM*DD];
__device__ float g_Wqkv[(size_t)DD*NQKV];
__device__ float g_W1r [(size_t)DD*DF];
__device__ float g_W2r [(size_t)DF*DD];
__device__ float g_QKV [(size_t)MM*NQKV];   // tf32-rounded by GEMM epilogue
__device__ float g_x1  [MM*DD];
__device__ float g_h0  [MM*DD];
__device__ float g_h1  [(size_t)MM*DF];

__device__ __forceinline__ float f2tf(float f) {
    uint32_t u;
    asm("cvt.rna.tf32.f32 %0, %1;" : "=r"(u) : "f"(f));
    return __uint_as_float(u);
}

__device__ __forceinline__ void mma_tf32(float c[4], const uint32_t a[4], const uint32_t b[2]) {
    asm volatile(
        "mma.sync.aligned.m16n8k8.row.col.f32.tf32.tf32.f32 "
        "{%0,%1,%2,%3}, {%4,%5,%6,%7}, {%8,%9}, {%0,%1,%2,%3};\n"
        : "+f"(c[0]), "+f"(c[1]), "+f"(c[2]), "+f"(c[3])
        : "r"(a[0]), "r"(a[1]), "r"(a[2]), "r"(a[3]), "r"(b[0]), "r"(b[1]));
}

__device__ __forceinline__ uint32_t smem_u32(const void* p) {
    uint32_t a;
    asm("{ .reg .u64 t; cvta.to.shared.u64 t, %1; cvt.u32.u64 %0, t; }" : "=r"(a) : "l"(p));
    return a;
}

#define CP_ASYNC16(sm, gp) \
    asm volatile("cp.async.cg.shared.global [%0], [%1], 16;" :: "r"(sm), "l"(gp) : "memory")
#define CP_COMMIT() asm volatile("cp.async.commit_group;" ::: "memory")
#define CP_WAIT0()  asm volatile("cp.async.wait_group 0;" ::: "memory")

// ============================================================================
// Pre-rounding kernels
// ============================================================================
__global__ void round_tf32(const float* __restrict__ in, float* __restrict__ out, int n4)
{
    int i = blockIdx.x * 256 + threadIdx.x;
    if (i >= n4) return;
    float4 v = ((const float4*)in)[i];
    v.x = f2tf(v.x); v.y = f2tf(v.y); v.z = f2tf(v.z); v.w = f2tf(v.w);
    ((float4*)out)[i] = v;
}

__global__ void concat_round(const float* __restrict__ Wq, const float* __restrict__ Wk,
                             const float* __restrict__ Wv, float* __restrict__ W)
{
    int i = blockIdx.x * 256 + threadIdx.x;
    if (i >= DD * (NQKV / 4)) return;
    int r  = i / (NQKV / 4);
    int c4 = i % (NQKV / 4);
    float4 v; float sc = 1.0f;
    if      (c4 < 320) { v = ((const float4*)Wq)[r * 320 + c4];       sc = 0.125f; }
    else if (c4 < 640) { v = ((const float4*)Wk)[r * 320 + c4 - 320]; }
    else               { v = ((const float4*)Wv)[r * 320 + c4 - 640]; }
    v.x = f2tf(v.x * sc); v.y = f2tf(v.y * sc); v.z = f2tf(v.z * sc); v.w = f2tf(v.w * sc);
    ((float4*)W)[i] = v;
}

// ============================================================================
// TF32 GEMM, cp.async 2-stage, linear smem, conflict-free scattered LDS.32.
// MTILE x 128 tile, BK=32, 256 thr (2m x 4n warps). MTILE=128 -> 2 CTAs/SM,
// MTILE=64 -> 3 CTAs/SM (tail-friendly for small grids).
// MODE 0: C=round(AB); 1: round(relu(AB+bias)); 2: AB+bias+resid.
// ============================================================================
#define AS_STRIDE 36
#define BS_STRIDE 136
#define B_ST (32*BS_STRIDE)
#define G_SMEM(MT) (2*((MT)*AS_STRIDE + B_ST)*4)

template <int MODE, int MTILE>
__global__ void __launch_bounds__(256, (MTILE == 128) ? 2 : 3)
gemm_tf32(const float* __restrict__ A, const float* __restrict__ Bm,
          float* __restrict__ C, int M, int N, int K,
          const float* __restrict__ bias, const float* __restrict__ resid)
{
    constexpr int NI   = MTILE / 32;          // m-subtiles per warp
    constexpr int A_ST = MTILE * AS_STRIDE;
    constexpr int STG  = A_ST + B_ST;

    extern __shared__ float smf[];
    const uint32_t smb = smem_u32(smf);

    const int t    = threadIdx.x;
    const int lane = t & 31;
    const int w    = t >> 5;
    const int wm   = w & 1;
    const int wn   = w >> 1;
    const int g    = lane >> 2;
    const int tg   = lane & 3;
    const int m0   = blockIdx.y * MTILE;
    const int n0   = blockIdx.x * 128;

    const int arow = t >> 3;              // +32 per chunk (NI chunks)
    const int acol = (t & 7) * 4;
    const int bkr  = t >> 5;              // +8 per chunk (4 chunks)
    const int bnc  = (t & 31) * 4;
    const float* Ag0 = A  + (size_t)(m0 + arow) * K + acol;
    const float* Bg0 = Bm + (size_t)bkr * N + n0 + bnc;
    const uint32_t Asd = smb + (uint32_t)((arow * AS_STRIDE + acol) * 4);
    const uint32_t Bsd = smb + (uint32_t)((A_ST + bkr * BS_STRIDE + bnc) * 4);

    auto issue = [&](int kt, int buf) {
        const uint32_t bo = (uint32_t)(buf * STG * 4);
        const float* Ag = Ag0 + kt * 32;
        const float* Bg = Bg0 + (size_t)(kt * 32) * N;
#pragma unroll
        for (int p = 0; p < NI; p++)
            CP_ASYNC16(Asd + bo + p * 32 * AS_STRIDE * 4, Ag + (size_t)p * 32 * K);
#pragma unroll
        for (int p = 0; p < 4; p++)
            CP_ASYNC16(Bsd + bo + p * 8 * BS_STRIDE * 4, Bg + (size_t)p * 8 * N);
        CP_COMMIT();
    };

    float acc[NI][4][4];
#pragma unroll
    for (int i = 0; i < NI; i++)
#pragma unroll
        for (int j = 0; j < 4; j++)
#pragma unroll
            for (int q = 0; q < 4; q++) acc[i][j][q] = 0.f;

    issue(0, 0);

    const int KT = K >> 5;
    for (int kt = 0; kt < KT; kt++) {
        CP_WAIT0();
        __syncthreads();
        if (kt + 1 < KT) issue(kt + 1, (kt + 1) & 1);

        const float* As = smf + (kt & 1) * STG;
        const float* Bs = As + A_ST;
#pragma unroll
        for (int kc = 0; kc < 4; kc++) {
            uint32_t af[NI][4], bf[4][2];
            const int c = kc * 8 + tg;
#pragma unroll
            for (int i = 0; i < NI; i++) {
                const int r = wm * (MTILE / 2) + i * 16 + g;
                af[i][0] = __float_as_uint(As[r * AS_STRIDE + c]);
                af[i][1] = __float_as_uint(As[(r + 8) * AS_STRIDE + c]);
                af[i][2] = __float_as_uint(As[r * AS_STRIDE + c + 4]);
                af[i][3] = __float_as_uint(As[(r + 8) * AS_STRIDE + c + 4]);
            }
#pragma unroll
            for (int j = 0; j < 4; j++) {
                const int n = wn * 32 + j * 8 + g;
                bf[j][0] = __float_as_uint(Bs[c * BS_STRIDE + n]);
                bf[j][1] = __float_as_uint(Bs[(c + 4) * BS_STRIDE + n]);
            }
#pragma unroll
            for (int i = 0; i < NI; i++)
#pragma unroll
                for (int j = 0; j < 4; j++)
                    mma_tf32(acc[i][j], af[i], bf[j]);
        }
        __syncthreads();
    }

    // ---------------- epilogue ----------------
    const int mrow = m0 + wm * (MTILE / 2);
    const int ncol = n0 + wn * 32;
#pragma unroll
    for (int j = 0; j < 4; j++) {
        const int colj = ncol + j * 8 + tg * 2;
        float2 bv = make_float2(0.f, 0.f);
        if (MODE == 1 || MODE == 2) bv = *(const float2*)(bias + colj);
#pragma unroll
        for (int i = 0; i < NI; i++) {
            const int r0 = mrow + i * 16 + g;
            float2 v0 = make_float2(acc[i][j][0], acc[i][j][1]);
            float2 v1 = make_float2(acc[i][j][2], acc[i][j][3]);
            if (MODE == 0) {
                v0.x = f2tf(v0.x); v0.y = f2tf(v0.y);
                v1.x = f2tf(v1.x); v1.y = f2tf(v1.y);
            } else if (MODE == 1) {
                v0.x = f2tf(fmaxf(v0.x + bv.x, 0.f)); v0.y = f2tf(fmaxf(v0.y + bv.y, 0.f));
                v1.x = f2tf(fmaxf(v1.x + bv.x, 0.f)); v1.y = f2tf(fmaxf(v1.y + bv.y, 0.f));
            } else {
                float2 r0v = *(const float2*)(resid + (size_t)r0 * N + colj);
                float2 r1v = *(const float2*)(resid + (size_t)(r0 + 8) * N + colj);
                v0.x += bv.x + r0v.x; v0.y += bv.y + r0v.y;
                v1.x += bv.x + r1v.x; v1.y += bv.y + r1v.y;
            }
            *(float2*)(C + (size_t)r0 * N + colj)       = v0;
            *(float2*)(C + (size_t)(r0 + 8) * N + colj) = v1;
        }
    }
}

// ============================================================================
// Flash attention v2: cp.async double-buffered K/V, zero cvt in hot path
// (QKV pre-rounded by GEMM epilogue). Block = (qtile 64, h, b), 256 thr,
// 8 warps = 4m x 2n. Key tile 64.
// smem floats: Qs[64*68] | Ks[2][64*68] | Vs[2][64*72] | Ps[64*68] | aux 448
// ============================================================================
#define OFF_K  4352
#define OFF_V  13056
#define OFF_P  22272
#define OFF_AX 26624
#define ATT_SMEM_FLOATS 27072
#define ATT_SMEM_BYTES  (ATT_SMEM_FLOATS*4)

__global__ void __launch_bounds__(256, 2)
attention_tc(const float* __restrict__ QKV, const float* __restrict__ X,
             float* __restrict__ X1)
{
    extern __shared__ float sm[];
    const uint32_t smb = smem_u32(sm);
    float* Qs   = sm;
    float* Ps   = sm + OFF_P;
    float* m_s  = sm + OFF_AX;
    float* l_s  = m_s + 64;
    float* al_s = l_s + 64;
    float* red_m= al_s + 64;   // [row][wn]
    float* red_s= red_m + 128;

    const int t    = threadIdx.x;
    const int lane = t & 31;
    const int w    = t >> 5;
    const int wm   = w & 3;
    const int wn   = w >> 2;
    const int g    = lane >> 2;
    const int tg   = lane & 3;

    const int qb   = blockIdx.x * 64;
    const int h    = blockIdx.y;
    const int b    = blockIdx.z;
    const int brow = b * SS;

    const int rr = t >> 4;               // 0..15, +16 per pass
    const int d4 = (t & 15) * 4;

    const float* Qg = QKV + (size_t)(brow + qb) * NQKV + h * DH;
    auto issueKV = [&](int kb, int buf) {
        const float* Kg = QKV + (size_t)(brow + kb) * NQKV + DD     + h * DH;
        const float* Vg = QKV + (size_t)(brow + kb) * NQKV + 2 * DD + h * DH;
        const uint32_t kd = smb + (uint32_t)((OFF_K + buf * 4352) * 4);
        const uint32_t vd = smb + (uint32_t)((OFF_V + buf * 4608) * 4);
#pragma unroll
        for (int p = 0; p < 4; p++) {
            int r = rr + p * 16;
            CP_ASYNC16(kd + (uint32_t)((r * 68 + d4) * 4), Kg + (size_t)r * NQKV + d4);
        }
#pragma unroll
        for (int p = 0; p < 4; p++) {
            int r = rr + p * 16;
            CP_ASYNC16(vd + (uint32_t)((r * 72 + d4) * 4), Vg + (size_t)r * NQKV + d4);
        }
        CP_COMMIT();
    };

    // prologue: Q + first K/V tile in one group
#pragma unroll
    for (int p = 0; p < 4; p++) {
        int r = rr + p * 16;
        CP_ASYNC16(smb + (uint32_t)((r * 68 + d4) * 4), Qg + (size_t)r * NQKV + d4);
    }
    issueKV(0, 0);

    if (t < 64) { m_s[t] = -1e30f; l_s[t] = 0.f; }
    float oacc[4][4];
#pragma unroll
    for (int i = 0; i < 4; i++)
#pragma unroll
        for (int j = 0; j < 4; j++) oacc[i][j] = 0.f;

    const int row0 = wm * 16 + g;
    const int row1 = row0 + 8;

    for (int kt = 0; kt < SS / 64; kt++) {
        CP_WAIT0();
        __syncthreads();
        if (kt + 1 < SS / 64) issueKV((kt + 1) * 64, (kt + 1) & 1);

        const float* Ks = sm + OFF_K + (kt & 1) * 4352;
        const float* Vs = sm + OFF_V + (kt & 1) * 4608;

        // ---- S = Q K^T : warp tile 16 x 32 ----
        float sacc[4][4];
#pragma unroll
        for (int j = 0; j < 4; j++)
#pragma unroll
            for (int q = 0; q < 4; q++) sacc[j][q] = 0.f;

#pragma unroll
        for (int kc = 0; kc < 8; kc++) {
            const int c = kc * 8 + tg;
            uint32_t af[4];
            af[0] = __float_as_uint(Qs[row0 * 68 + c]);
            af[1] = __float_as_uint(Qs[row1 * 68 + c]);
            af[2] = __float_as_uint(Qs[row0 * 68 + c + 4]);
            af[3] = __float_as_uint(Qs[row1 * 68 + c + 4]);
#pragma unroll
            for (int j = 0; j < 4; j++) {
                const int n = wn * 32 + j * 8 + g;
                uint32_t bf[2];
                bf[0] = __float_as_uint(Ks[n * 68 + c]);
                bf[1] = __float_as_uint(Ks[n * 68 + c + 4]);
                mma_tf32(sacc[j], af, bf);
            }
        }

        // ---- softmax: row max ----
        float pm0 = -1e30f, pm1 = -1e30f;
#pragma unroll
        for (int j = 0; j < 4; j++) {
            pm0 = fmaxf(pm0, fmaxf(sacc[j][0], sacc[j][1]));
            pm1 = fmaxf(pm1, fmaxf(sacc[j][2], sacc[j][3]));
        }
        pm0 = fmaxf(pm0, __shfl_xor_sync(0xffffffffu, pm0, 1));
        pm0 = fmaxf(pm0, __shfl_xor_sync(0xffffffffu, pm0, 2));
        pm1 = fmaxf(pm1, __shfl_xor_sync(0xffffffffu, pm1, 1));
        pm1 = fmaxf(pm1, __shfl_xor_sync(0xffffffffu, pm1, 2));
        if (tg == 0) {
            red_m[row0 * 2 + wn] = pm0;
            red_m[row1 * 2 + wn] = pm1;
        }
        __syncthreads();
        if (t < 64) {
            float mold = m_s[t];
            float mnew = fmaxf(mold, fmaxf(red_m[t * 2], red_m[t * 2 + 1]));
            m_s[t]  = mnew;
            al_s[t] = __expf(mold - mnew);
        }
        __syncthreads();

        // ---- exp, store P, row sums, rescale O ----
        const float mn0 = m_s[row0], mn1 = m_s[row1];
        const float al0 = al_s[row0], al1 = al_s[row1];
        float rs0 = 0.f, rs1 = 0.f;
#pragma unroll
        for (int j = 0; j < 4; j++) {
            float p00 = __expf(sacc[j][0] - mn0);
            float p01 = __expf(sacc[j][1] - mn0);
            float p10 = __expf(sacc[j][2] - mn1);
            float p11 = __expf(sacc[j][3] - mn1);
            rs0 += p00 + p01;
            rs1 += p10 + p11;
            const int col = wn * 32 + j * 8 + tg * 2;
            *(float2*)&Ps[row0 * 68 + col] = make_float2(f2tf(p00), f2tf(p01));
            *(float2*)&Ps[row1 * 68 + col] = make_float2(f2tf(p10), f2tf(p11));
        }
        rs0 += __shfl_xor_sync(0xffffffffu, rs0, 1);
        rs0 += __shfl_xor_sync(0xffffffffu, rs0, 2);
        rs1 += __shfl_xor_sync(0xffffffffu, rs1, 1);
        rs1 += __shfl_xor_sync(0xffffffffu, rs1, 2);
        if (tg == 0) {
            red_s[row0 * 2 + wn] = rs0;
            red_s[row1 * 2 + wn] = rs1;
        }
#pragma unroll
        for (int i = 0; i < 4; i++) {
            oacc[i][0] *= al0; oacc[i][1] *= al0;
            oacc[i][2] *= al1; oacc[i][3] *= al1;
        }
        __syncthreads();
        if (t < 64)
            l_s[t] = l_s[t] * al_s[t] + red_s[t * 2] + red_s[t * 2 + 1];

        // ---- O += P @ V ----
#pragma unroll
        for (int kc = 0; kc < 8; kc++) {
            const int c = kc * 8 + tg;
            uint32_t af[4];
            af[0] = __float_as_uint(Ps[row0 * 68 + c]);
            af[1] = __float_as_uint(Ps[row1 * 68 + c]);
            af[2] = __float_as_uint(Ps[row0 * 68 + c + 4]);
            af[3] = __float_as_uint(Ps[row1 * 68 + c + 4]);
#pragma unroll
            for (int j = 0; j < 4; j++) {
                const int n = wn * 32 + j * 8 + g;
                uint32_t bf[2];
                bf[0] = __float_as_uint(Vs[c * 72 + n]);
                bf[1] = __float_as_uint(Vs[(c + 4) * 72 + n]);
                mma_tf32(oacc[j], af, bf);
            }
        }
        __syncthreads();
    }

    // ---- epilogue: X1 = O/l + X ----
    const float il0 = 1.f / l_s[row0];
    const float il1 = 1.f / l_s[row1];
    const size_t tok0 = (size_t)(brow + qb + row0);
    const size_t tok1 = (size_t)(brow + qb + row1);
#pragma unroll
    for (int j = 0; j < 4; j++) {
        const int col = h * DH + wn * 32 + j * 8 + tg * 2;
        float2 x0 = *(const float2*)(X + tok0 * DD + col);
        float2 x1 = *(const float2*)(X + tok1 * DD + col);
        float2 o0 = make_float2(oacc[j][0] * il0 + x0.x, oacc[j][1] * il0 + x0.y);
        float2 o1 = make_float2(oacc[j][2] * il1 + x1.x, oacc[j][3] * il1 + x1.y);
        *(float2*)(X1 + tok0 * DD + col) = o0;
        *(float2*)(X1 + tok1 * DD + col) = o1;
    }
}

// ============================================================================
// LayerNorm over D=1280; tf32-rounded output.
// ============================================================================
__global__ void __launch_bounds__(256)
ln_kernel(const float* __restrict__ X, const float* __restrict__ gam,
          const float* __restrict__ bet, float* __restrict__ Y)
{
    const int row = blockIdx.x;
    const float* xr = X + (size_t)row * DD;
    float v[5];
    float sum = 0.f, sq = 0.f;
#pragma unroll
    for (int i = 0; i < 5; i++) {
        v[i] = xr[threadIdx.x + i * 256];
        sum += v[i];
        sq  += v[i] * v[i];
    }
#pragma unroll
    for (int off = 16; off; off >>= 1) {
        sum += __shfl_xor_sync(0xffffffffu, sum, off);
        sq  += __shfl_xor_sync(0xffffffffu, sq , off);
    }
    __shared__ float sS[8], sQ[8];
    const int w = threadIdx.x >> 5, lane = threadIdx.x & 31;
    if (lane == 0) { sS[w] = sum; sQ[w] = sq; }
    __syncthreads();
    if (threadIdx.x == 0) {
        float a = 0.f, q = 0.f;
#pragma unroll
        for (int i = 0; i < 8; i++) { a += sS[i]; q += sQ[i]; }
        sS[0] = a; sQ[0] = q;
    }
    __syncthreads();
    const float mu   = sS[0] * (1.0f / DD);
    const float var  = sQ[0] * (1.0f / DD) - mu * mu;
    const float rstd = rsqrtf(var + 1e-5f);
    float* yr = Y + (size_t)row * DD;
#pragma unroll
    for (int i = 0; i < 5; i++) {
        int c = threadIdx.x + i * 256;
        yr[c] = f2tf((v[i] - mu) * rstd * gam[c] + bet[c]);
    }
}

// ============================================================================
// launch
// ============================================================================
extern "C" void kernel_launch(void* const* d_in, const int* in_sizes, int n_in,
                              void* d_out, int out_size)
{
    const float* x   = (const float*)d_in[0];
    const float* Wq  = (const float*)d_in[1];
    const float* Wk  = (const float*)d_in[2];
    const float* Wv  = (const float*)d_in[3];
    const float* lng = (const float*)d_in[4];
    const float* lnb = (const float*)d_in[5];
    const float* W1  = (const float*)d_in[6];
    const float* b1  = (const float*)d_in[7];
    const float* W2  = (const float*)d_in[8];
    const float* b2  = (const float*)d_in[9];
    float* out = (float*)d_out;

    float *XR, *Wqkv, *W1r, *W2r, *QKV, *X1, *H0, *H1;
    cudaGetSymbolAddress((void**)&XR,   g_xr);
    cudaGetSymbolAddress((void**)&Wqkv, g_Wqkv);
    cudaGetSymbolAddress((void**)&W1r,  g_W1r);
    cudaGetSymbolAddress((void**)&W2r,  g_W2r);
    cudaGetSymbolAddress((void**)&QKV,  g_QKV);
    cudaGetSymbolAddress((void**)&X1,   g_x1);
    cudaGetSymbolAddress((void**)&H0,   g_h0);
    cudaGetSymbolAddress((void**)&H1,   g_h1);

    cudaFuncSetAttribute((const void*)gemm_tf32<0,64>,  cudaFuncAttributeMaxDynamicSharedMemorySize, G_SMEM(64));
    cudaFuncSetAttribute((const void*)gemm_tf32<1,128>, cudaFuncAttributeMaxDynamicSharedMemorySize, G_SMEM(128));
    cudaFuncSetAttribute((const void*)gemm_tf32<2,64>,  cudaFuncAttributeMaxDynamicSharedMemorySize, G_SMEM(64));
    cudaFuncSetAttribute((const void*)attention_tc,     cudaFuncAttributeMaxDynamicSharedMemorySize, ATT_SMEM_BYTES);

    const dim3 blk(256);

    // pre-round inputs/weights to tf32
    round_tf32<<<(MM*DD/4 + 255)/256, blk>>>(x, XR, MM*DD/4);
    concat_round<<<(DD*(NQKV/4) + 255)/256, blk>>>(Wq, Wk, Wv, Wqkv);
    round_tf32<<<((int)((size_t)DD*DF/4) + 255)/256, blk>>>(W1, W1r, (int)((size_t)DD*DF/4));
    round_tf32<<<((int)((size_t)DF*DD/4) + 255)/256, blk>>>(W2, W2r, (int)((size_t)DF*DD/4));

    // QKV projection (rounded output feeds attention directly)
    gemm_tf32<0,64><<<dim3(NQKV/128, MM/64), blk, G_SMEM(64)>>>(XR, Wqkv, QKV, MM, NQKV, DD, nullptr, nullptr);

    // fused attention + residual
    attention_tc<<<dim3(SS/64, HH, BB), blk, ATT_SMEM_BYTES>>>(QKV, x, X1);

    // layernorm (rounded output)
    ln_kernel<<<MM, 256>>>(X1, lng, lnb, H0);

    // FFN
    gemm_tf32<1,128><<<dim3(DF/128, MM/128), blk, G_SMEM(128)>>>(H0, W1r, H1, MM, DF, DD, b1, nullptr);
    gemm_tf32<2,64><<<dim3(DD/128, MM/64), blk, G_SMEM(64)>>>(H1, W2r, out, MM, DD, DF, b2, X1);
}

// round 8
// speedup vs baseline: 6.1932x; 1.5165x over previous
#include <cuda_runtime.h>
#include <cuda_fp16.h>
#include <cstdint>

// ---------------- problem constants ----------------
#define BB 4
#define SS 1024
#define DD 1280
#define HH 20
#define DH 64
#define DF 5120
#define MM (BB*SS)          // 4096 rows
#define NQKV (3*DD)         // 3840

// ---------------- scratch (device globals) ----------------
__device__ __half g_x16  [(size_t)MM*DD];       // fp16 x (GEMM A)
__device__ __half g_Wqkv [(size_t)NQKV*DD];     // [N][K] fp16, Q rows pre-scaled
__device__ __half g_W1t  [(size_t)DF*DD];       // [DF][DD] fp16
__device__ __half g_W2t  [(size_t)DD*DF];       // [DD][DF] fp16
__device__ float  g_QKV  [(size_t)MM*NQKV];     // tf32-rounded fp32 (attention input)
__device__ float  g_x1   [MM*DD];
__device__ __half g_h0   [MM*DD];               // LN out fp16
__device__ __half g_h1   [(size_t)MM*DF];       // FFN1 out fp16

__device__ __forceinline__ float f2tf(float f) {
    uint32_t u;
    asm("cvt.rna.tf32.f32 %0, %1;" : "=r"(u) : "f"(f));
    return __uint_as_float(u);
}

__device__ __forceinline__ void mma_tf32(float c[4], const uint32_t a[4], const uint32_t b[2]) {
    asm volatile(
        "mma.sync.aligned.m16n8k8.row.col.f32.tf32.tf32.f32 "
        "{%0,%1,%2,%3}, {%4,%5,%6,%7}, {%8,%9}, {%0,%1,%2,%3};\n"
        : "+f"(c[0]), "+f"(c[1]), "+f"(c[2]), "+f"(c[3])
        : "r"(a[0]), "r"(a[1]), "r"(a[2]), "r"(a[3]), "r"(b[0]), "r"(b[1]));
}

__device__ __forceinline__ void mma_f16(float c[4], const uint32_t a[4], const uint32_t b[2]) {
    asm volatile(
        "mma.sync.aligned.m16n8k16.row.col.f32.f16.f16.f32 "
        "{%0,%1,%2,%3}, {%4,%5,%6,%7}, {%8,%9}, {%0,%1,%2,%3};\n"
        : "+f"(c[0]), "+f"(c[1]), "+f"(c[2]), "+f"(c[3])
        : "r"(a[0]), "r"(a[1]), "r"(a[2]), "r"(a[3]), "r"(b[0]), "r"(b[1]));
}

__device__ __forceinline__ uint32_t smem_u32(const void* p) {
    uint32_t a;
    asm("{ .reg .u64 t; cvta.to.shared.u64 t, %1; cvt.u32.u64 %0, t; }" : "=r"(a) : "l"(p));
    return a;
}

#define CP_ASYNC16(sm, gp) \
    asm volatile("cp.async.cg.shared.global [%0], [%1], 16;" :: "r"(sm), "l"(gp) : "memory")
#define CP_COMMIT() asm volatile("cp.async.commit_group;" ::: "memory")
#define CP_WAIT0()  asm volatile("cp.async.wait_group 0;" ::: "memory")

// ============================================================================
// Prep kernels
// ============================================================================
__global__ void to_half(const float* __restrict__ in, __half* __restrict__ out, int n4)
{
    int i = blockIdx.x * 256 + threadIdx.x;
    if (i >= n4) return;
    float4 v = ((const float4*)in)[i];
    __half2 h0 = __floats2half2_rn(v.x, v.y);
    __half2 h1 = __floats2half2_rn(v.z, v.w);
    ((__half2*)out)[i * 2]     = h0;
    ((__half2*)out)[i * 2 + 1] = h1;
}

// transpose + convert: src [K][N] fp32 -> dst [N][K] fp16 (x scale)
__global__ void thalf(const float* __restrict__ src, int K, int N,
                      __half* __restrict__ dst, float scale)
{
    __shared__ float s[32][33];
    const int tx = threadIdx.x, ty = threadIdx.y;
    const int n0 = blockIdx.x * 32, k0 = blockIdx.y * 32;
#pragma unroll
    for (int i = 0; i < 4; i++)
        s[ty + i * 8][tx] = src[(size_t)(k0 + ty + i * 8) * N + n0 + tx];
    __syncthreads();
#pragma unroll
    for (int i = 0; i < 4; i++)
        dst[(size_t)(n0 + ty + i * 8) * K + k0 + tx] =
            __float2half_rn(s[tx][ty + i * 8] * scale);
}

// ============================================================================
// FP16 GEMM (m16n8k16, fp32 accum), cp.async 2-stage, linear smem.
// Tile MTILE x 128, BK=64, 256 thr (2m x 4n warps, warp (MTILE/2) x 32).
// A fp16 [M][K]; B fp16 [N][K] (pre-transposed). Rows padded 64->72 halves
// (36 words == 4 mod 32 -> all fragment LDS.32 conflict-free).
// MODE 0: C=f2tf(AB) fp32; MODE 1: C16=half(relu(AB+bias)); MODE 2: C=AB+bias+resid.
// ============================================================================
#define HR 72                   // halves per smem row
#define BH_ST (128*HR)          // B tile halves
#define G16_SMEM(MT) (2*((MT)*HR + BH_ST)*2)

template <int MODE, int MTILE>
__global__ void __launch_bounds__(256, (MTILE == 128) ? 2 : 3)
gemm_f16(const __half* __restrict__ A, const __half* __restrict__ Bm,
         float* __restrict__ C, __half* __restrict__ C16, int M, int N, int K,
         const float* __restrict__ bias, const float* __restrict__ resid)
{
    constexpr int NI   = MTILE / 32;
    constexpr int PA   = MTILE / 32;      // A cp.async passes (32 rows each)
    constexpr int A_ST = MTILE * HR;      // halves
    constexpr int STG  = A_ST + BH_ST;    // halves per buffer

    extern __shared__ __half smh[];
    const uint32_t smb = smem_u32(smh);

    const int t    = threadIdx.x;
    const int lane = t & 31;
    const int w    = t >> 5;
    const int wm   = w & 1;
    const int wn   = w >> 1;
    const int g    = lane >> 2;
    const int tg   = lane & 3;
    const int m0   = blockIdx.y * MTILE;
    const int n0   = blockIdx.x * 128;

    const int ldr = t >> 3;               // row 0..31 (+32/pass)
    const int ldc = (t & 7) * 8;          // halves (16B chunk)
    const __half* Ag0 = A  + (size_t)(m0 + ldr) * K + ldc;
    const __half* Bg0 = Bm + (size_t)(n0 + ldr) * K + ldc;
    const uint32_t Asd = smb + (uint32_t)((ldr * HR + ldc) * 2);
    const uint32_t Bsd = smb + (uint32_t)((A_ST + ldr * HR + ldc) * 2);

    auto issue = [&](int kt, int buf) {
        const uint32_t bo = (uint32_t)(buf * STG * 2);
        const __half* Ag = Ag0 + kt * 64;
        const __half* Bg = Bg0 + kt * 64;
#pragma unroll
        for (int p = 0; p < PA; p++)
            CP_ASYNC16(Asd + bo + p * 32 * HR * 2, Ag + (size_t)p * 32 * K);
#pragma unroll
        for (int p = 0; p < 4; p++)
            CP_ASYNC16(Bsd + bo + p * 32 * HR * 2, Bg + (size_t)p * 32 * K);
        CP_COMMIT();
    };

    float acc[NI][4][4];
#pragma unroll
    for (int i = 0; i < NI; i++)
#pragma unroll
        for (int j = 0; j < 4; j++)
#pragma unroll
            for (int q = 0; q < 4; q++) acc[i][j][q] = 0.f;

    issue(0, 0);

    const int KT = K >> 6;
    for (int kt = 0; kt < KT; kt++) {
        CP_WAIT0();
        __syncthreads();
        if (kt + 1 < KT) issue(kt + 1, (kt + 1) & 1);

        const __half* As = smh + (kt & 1) * STG;
        const __half* Bs = As + A_ST;
#pragma unroll
        for (int ks = 0; ks < 4; ks++) {
            const int co = ks * 16 + tg * 2;     // half offset in row
            uint32_t af[NI][4], bf[4][2];
#pragma unroll
            for (int i = 0; i < NI; i++) {
                const int r = wm * (MTILE / 2) + i * 16 + g;
                af[i][0] = *(const uint32_t*)&As[r * HR + co];
                af[i][1] = *(const uint32_t*)&As[(r + 8) * HR + co];
                af[i][2] = *(const uint32_t*)&As[r * HR + co + 8];
                af[i][3] = *(const uint32_t*)&As[(r + 8) * HR + co + 8];
            }
#pragma unroll
            for (int j = 0; j < 4; j++) {
                const int n = wn * 32 + j * 8 + g;
                bf[j][0] = *(const uint32_t*)&Bs[n * HR + co];
                bf[j][1] = *(const uint32_t*)&Bs[n * HR + co + 8];
            }
#pragma unroll
            for (int i = 0; i < NI; i++)
#pragma unroll
                for (int j = 0; j < 4; j++)
                    mma_f16(acc[i][j], af[i], bf[j]);
        }
        __syncthreads();
    }

    // ---------------- epilogue ----------------
    const int mrow = m0 + wm * (MTILE / 2);
    const int ncol = n0 + wn * 32;
#pragma unroll
    for (int j = 0; j < 4; j++) {
        const int colj = ncol + j * 8 + tg * 2;
        float2 bv = make_float2(0.f, 0.f);
        if (MODE == 1 || MODE == 2) bv = *(const float2*)(bias + colj);
#pragma unroll
        for (int i = 0; i < NI; i++) {
            const int r0 = mrow + i * 16 + g;
            float2 v0 = make_float2(acc[i][j][0], acc[i][j][1]);
            float2 v1 = make_float2(acc[i][j][2], acc[i][j][3]);
            if (MODE == 0) {
                v0.x = f2tf(v0.x); v0.y = f2tf(v0.y);
                v1.x = f2tf(v1.x); v1.y = f2tf(v1.y);
                *(float2*)(C + (size_t)r0 * N + colj)       = v0;
                *(float2*)(C + (size_t)(r0 + 8) * N + colj) = v1;
            } else if (MODE == 1) {
                __half2 h0 = __floats2half2_rn(fmaxf(v0.x + bv.x, 0.f), fmaxf(v0.y + bv.y, 0.f));
                __half2 h1 = __floats2half2_rn(fmaxf(v1.x + bv.x, 0.f), fmaxf(v1.y + bv.y, 0.f));
                *(__half2*)(C16 + (size_t)r0 * N + colj)       = h0;
                *(__half2*)(C16 + (size_t)(r0 + 8) * N + colj) = h1;
            } else {
                float2 r0v = *(const float2*)(resid + (size_t)r0 * N + colj);
                float2 r1v = *(const float2*)(resid + (size_t)(r0 + 8) * N + colj);
                v0.x += bv.x + r0v.x; v0.y += bv.y + r0v.y;
                v1.x += bv.x + r1v.x; v1.y += bv.y + r1v.y;
                *(float2*)(C + (size_t)r0 * N + colj)       = v0;
                *(float2*)(C + (size_t)(r0 + 8) * N + colj) = v1;
            }
        }
    }
}

// ============================================================================
// Flash attention (validated round 7, unchanged): tf32, fp32 QKV input.
// ============================================================================
#define OFF_K  4352
#define OFF_V  13056
#define OFF_P  22272
#define OFF_AX 26624
#define ATT_SMEM_FLOATS 27072
#define ATT_SMEM_BYTES  (ATT_SMEM_FLOATS*4)

__global__ void __launch_bounds__(256, 2)
attention_tc(const float* __restrict__ QKV, const float* __restrict__ X,
             float* __restrict__ X1)
{
    extern __shared__ float sm[];
    const uint32_t smb = smem_u32(sm);
    float* Qs   = sm;
    float* Ps   = sm + OFF_P;
    float* m_s  = sm + OFF_AX;
    float* l_s  = m_s + 64;
    float* al_s = l_s + 64;
    float* red_m= al_s + 64;
    float* red_s= red_m + 128;

    const int t    = threadIdx.x;
    const int lane = t & 31;
    const int w    = t >> 5;
    const int wm   = w & 3;
    const int wn   = w >> 2;
    const int g    = lane >> 2;
    const int tg   = lane & 3;

    const int qb   = blockIdx.x * 64;
    const int h    = blockIdx.y;
    const int b    = blockIdx.z;
    const int brow = b * SS;

    const int rr = t >> 4;
    const int d4 = (t & 15) * 4;

    const float* Qg = QKV + (size_t)(brow + qb) * NQKV + h * DH;
    auto issueKV = [&](int kb, int buf) {
        const float* Kg = QKV + (size_t)(brow + kb) * NQKV + DD     + h * DH;
        const float* Vg = QKV + (size_t)(brow + kb) * NQKV + 2 * DD + h * DH;
        const uint32_t kd = smb + (uint32_t)((OFF_K + buf * 4352) * 4);
        const uint32_t vd = smb + (uint32_t)((OFF_V + buf * 4608) * 4);
#pragma unroll
        for (int p = 0; p < 4; p++) {
            int r = rr + p * 16;
            CP_ASYNC16(kd + (uint32_t)((r * 68 + d4) * 4), Kg + (size_t)r * NQKV + d4);
        }
#pragma unroll
        for (int p = 0; p < 4; p++) {
            int r = rr + p * 16;
            CP_ASYNC16(vd + (uint32_t)((r * 72 + d4) * 4), Vg + (size_t)r * NQKV + d4);
        }
        CP_COMMIT();
    };

#pragma unroll
    for (int p = 0; p < 4; p++) {
        int r = rr + p * 16;
        CP_ASYNC16(smb + (uint32_t)((r * 68 + d4) * 4), Qg + (size_t)r * NQKV + d4);
    }
    issueKV(0, 0);

    if (t < 64) { m_s[t] = -1e30f; l_s[t] = 0.f; }
    float oacc[4][4];
#pragma unroll
    for (int i = 0; i < 4; i++)
#pragma unroll
        for (int j = 0; j < 4; j++) oacc[i][j] = 0.f;

    const int row0 = wm * 16 + g;
    const int row1 = row0 + 8;

    for (int kt = 0; kt < SS / 64; kt++) {
        CP_WAIT0();
        __syncthreads();
        if (kt + 1 < SS / 64) issueKV((kt + 1) * 64, (kt + 1) & 1);

        const float* Ks = sm + OFF_K + (kt & 1) * 4352;
        const float* Vs = sm + OFF_V + (kt & 1) * 4608;

        float sacc[4][4];
#pragma unroll
        for (int j = 0; j < 4; j++)
#pragma unroll
            for (int q = 0; q < 4; q++) sacc[j][q] = 0.f;

#pragma unroll
        for (int kc = 0; kc < 8; kc++) {
            const int c = kc * 8 + tg;
            uint32_t af[4];
            af[0] = __float_as_uint(Qs[row0 * 68 + c]);
            af[1] = __float_as_uint(Qs[row1 * 68 + c]);
            af[2] = __float_as_uint(Qs[row0 * 68 + c + 4]);
            af[3] = __float_as_uint(Qs[row1 * 68 + c + 4]);
#pragma unroll
            for (int j = 0; j < 4; j++) {
                const int n = wn * 32 + j * 8 + g;
                uint32_t bf[2];
                bf[0] = __float_as_uint(Ks[n * 68 + c]);
                bf[1] = __float_as_uint(Ks[n * 68 + c + 4]);
                mma_tf32(sacc[j], af, bf);
            }
        }

        float pm0 = -1e30f, pm1 = -1e30f;
#pragma unroll
        for (int j = 0; j < 4; j++) {
            pm0 = fmaxf(pm0, fmaxf(sacc[j][0], sacc[j][1]));
            pm1 = fmaxf(pm1, fmaxf(sacc[j][2], sacc[j][3]));
        }
        pm0 = fmaxf(pm0, __shfl_xor_sync(0xffffffffu, pm0, 1));
        pm0 = fmaxf(pm0, __shfl_xor_sync(0xffffffffu, pm0, 2));
        pm1 = fmaxf(pm1, __shfl_xor_sync(0xffffffffu, pm1, 1));
        pm1 = fmaxf(pm1, __shfl_xor_sync(0xffffffffu, pm1, 2));
        if (tg == 0) {
            red_m[row0 * 2 + wn] = pm0;
            red_m[row1 * 2 + wn] = pm1;
        }
        __syncthreads();
        if (t < 64) {
            float mold = m_s[t];
            float mnew = fmaxf(mold, fmaxf(red_m[t * 2], red_m[t * 2 + 1]));
            m_s[t]  = mnew;
            al_s[t] = __expf(mold - mnew);
        }
        __syncthreads();

        const float mn0 = m_s[row0], mn1 = m_s[row1];
        const float al0 = al_s[row0], al1 = al_s[row1];
        float rs0 = 0.f, rs1 = 0.f;
#pragma unroll
        for (int j = 0; j < 4; j++) {
            float p00 = __expf(sacc[j][0] - mn0);
            float p01 = __expf(sacc[j][1] - mn0);
            float p10 = __expf(sacc[j][2] - mn1);
            float p11 = __expf(sacc[j][3] - mn1);
            rs0 += p00 + p01;
            rs1 += p10 + p11;
            const int col = wn * 32 + j * 8 + tg * 2;
            *(float2*)&Ps[row0 * 68 + col] = make_float2(f2tf(p00), f2tf(p01));
            *(float2*)&Ps[row1 * 68 + col] = make_float2(f2tf(p10), f2tf(p11));
        }
        rs0 += __shfl_xor_sync(0xffffffffu, rs0, 1);
        rs0 += __shfl_xor_sync(0xffffffffu, rs0, 2);
        rs1 += __shfl_xor_sync(0xffffffffu, rs1, 1);
        rs1 += __shfl_xor_sync(0xffffffffu, rs1, 2);
        if (tg == 0) {
            red_s[row0 * 2 + wn] = rs0;
            red_s[row1 * 2 + wn] = rs1;
        }
#pragma unroll
        for (int i = 0; i < 4; i++) {
            oacc[i][0] *= al0; oacc[i][1] *= al0;
            oacc[i][2] *= al1; oacc[i][3] *= al1;
        }
        __syncthreads();
        if (t < 64)
            l_s[t] = l_s[t] * al_s[t] + red_s[t * 2] + red_s[t * 2 + 1];

#pragma unroll
        for (int kc = 0; kc < 8; kc++) {
            const int c = kc * 8 + tg;
            uint32_t af[4];
            af[0] = __float_as_uint(Ps[row0 * 68 + c]);
            af[1] = __float_as_uint(Ps[row1 * 68 + c]);
            af[2] = __float_as_uint(Ps[row0 * 68 + c + 4]);
            af[3] = __float_as_uint(Ps[row1 * 68 + c + 4]);
#pragma unroll
            for (int j = 0; j < 4; j++) {
                const int n = wn * 32 + j * 8 + g;
                uint32_t bf[2];
                bf[0] = __float_as_uint(Vs[c * 72 + n]);
                bf[1] = __float_as_uint(Vs[(c + 4) * 72 + n]);
                mma_tf32(oacc[j], af, bf);
            }
        }
        __syncthreads();
    }

    const float il0 = 1.f / l_s[row0];
    const float il1 = 1.f / l_s[row1];
    const size_t tok0 = (size_t)(brow + qb + row0);
    const size_t tok1 = (size_t)(brow + qb + row1);
#pragma unroll
    for (int j = 0; j < 4; j++) {
        const int col = h * DH + wn * 32 + j * 8 + tg * 2;
        float2 x0 = *(const float2*)(X + tok0 * DD + col);
        float2 x1 = *(const float2*)(X + tok1 * DD + col);
        float2 o0 = make_float2(oacc[j][0] * il0 + x0.x, oacc[j][1] * il0 + x0.y);
        float2 o1 = make_float2(oacc[j][2] * il1 + x1.x, oacc[j][3] * il1 + x1.y);
        *(float2*)(X1 + tok0 * DD + col) = o0;
        *(float2*)(X1 + tok1 * DD + col) = o1;
    }
}

// ============================================================================
// LayerNorm over D=1280; emits fp16 for the FFN1 GEMM.
// ============================================================================
__global__ void __launch_bounds__(256)
ln_kernel(const float* __restrict__ X, const float* __restrict__ gam,
          const float* __restrict__ bet, __half* __restrict__ Y)
{
    const int row = blockIdx.x;
    const float* xr = X + (size_t)row * DD;
    float v[5];
    float sum = 0.f, sq = 0.f;
#pragma unroll
    for (int i = 0; i < 5; i++) {
        v[i] = xr[threadIdx.x + i * 256];
        sum += v[i];
        sq  += v[i] * v[i];
    }
#pragma unroll
    for (int off = 16; off; off >>= 1) {
        sum += __shfl_xor_sync(0xffffffffu, sum, off);
        sq  += __shfl_xor_sync(0xffffffffu, sq , off);
    }
    __shared__ float sS[8], sQ[8];
    const int w = threadIdx.x >> 5, lane = threadIdx.x & 31;
    if (lane == 0) { sS[w] = sum; sQ[w] = sq; }
    __syncthreads();
    if (threadIdx.x == 0) {
        float a = 0.f, q = 0.f;
#pragma unroll
        for (int i = 0; i < 8; i++) { a += sS[i]; q += sQ[i]; }
        sS[0] = a; sQ[0] = q;
    }
    __syncthreads();
    const float mu   = sS[0] * (1.0f / DD);
    const float var  = sQ[0] * (1.0f / DD) - mu * mu;
    const float rstd = rsqrtf(var + 1e-5f);
    __half* yr = Y + (size_t)row * DD;
#pragma unroll
    for (int i = 0; i < 5; i++) {
        int c = threadIdx.x + i * 256;
        yr[c] = __float2half_rn((v[i] - mu) * rstd * gam[c] + bet[c]);
    }
}

// ============================================================================
// launch
// ============================================================================
extern "C" void kernel_launch(void* const* d_in, const int* in_sizes, int n_in,
                              void* d_out, int out_size)
{
    const float* x   = (const float*)d_in[0];
    const float* Wq  = (const float*)d_in[1];
    const float* Wk  = (const float*)d_in[2];
    const float* Wv  = (const float*)d_in[3];
    const float* lng = (const float*)d_in[4];
    const float* lnb = (const float*)d_in[5];
    const float* W1  = (const float*)d_in[6];
    const float* b1  = (const float*)d_in[7];
    const float* W2  = (const float*)d_in[8];
    const float* b2  = (const float*)d_in[9];
    float* out = (float*)d_out;

    __half *X16, *Wqkv, *W1t, *W2t, *H0, *H1;
    float *QKV, *X1;
    cudaGetSymbolAddress((void**)&X16,  g_x16);
    cudaGetSymbolAddress((void**)&Wqkv, g_Wqkv);
    cudaGetSymbolAddress((void**)&W1t,  g_W1t);
    cudaGetSymbolAddress((void**)&W2t,  g_W2t);
    cudaGetSymbolAddress((void**)&QKV,  g_QKV);
    cudaGetSymbolAddress((void**)&X1,   g_x1);
    cudaGetSymbolAddress((void**)&H0,   g_h0);
    cudaGetSymbolAddress((void**)&H1,   g_h1);

    cudaFuncSetAttribute((const void*)gemm_f16<0,64>,  cudaFuncAttributeMaxDynamicSharedMemorySize, G16_SMEM(64));
    cudaFuncSetAttribute((const void*)gemm_f16<1,128>, cudaFuncAttributeMaxDynamicSharedMemorySize, G16_SMEM(128));
    cudaFuncSetAttribute((const void*)gemm_f16<2,64>,  cudaFuncAttributeMaxDynamicSharedMemorySize, G16_SMEM(64));
    cudaFuncSetAttribute((const void*)attention_tc,    cudaFuncAttributeMaxDynamicSharedMemorySize, ATT_SMEM_BYTES);

    const dim3 blk(256);
    const dim3 tb(32, 8);

    // prep: activations -> fp16; weights -> transposed fp16 (Q scale baked in)
    to_half<<<(MM*DD/4 + 255)/256, blk>>>(x, X16, MM*DD/4);
    thalf<<<dim3(DD/32, DD/32), tb>>>(Wq, DD, DD, Wqkv,                     0.125f);
    thalf<<<dim3(DD/32, DD/32), tb>>>(Wk, DD, DD, Wqkv + (size_t)DD*DD,     1.0f);
    thalf<<<dim3(DD/32, DD/32), tb>>>(Wv, DD, DD, Wqkv + (size_t)2*DD*DD,   1.0f);
    thalf<<<dim3(DF/32, DD/32), tb>>>(W1, DD, DF, W1t, 1.0f);
    thalf<<<dim3(DD/32, DF/32), tb>>>(W2, DF, DD, W2t, 1.0f);

    // QKV projection (fp16 mma; writes tf32-rounded fp32 for attention)
    gemm_f16<0,64><<<dim3(NQKV/128, MM/64), blk, G16_SMEM(64)>>>(
        X16, Wqkv, QKV, nullptr, MM, NQKV, DD, nullptr, nullptr);

    // fused attention + residual (tf32)
    attention_tc<<<dim3(SS/64, HH, BB), blk, ATT_SMEM_BYTES>>>(QKV, x, X1);

    // layernorm -> fp16
    ln_kernel<<<MM, 256>>>(X1, lng, lnb, H0);

    // FFN (fp16 mma)
    gemm_f16<1,128><<<dim3(DF/128, MM/128), blk, G16_SMEM(128)>>>(
        H0, W1t, nullptr, H1, MM, DF, DD, b1, nullptr);
    gemm_f16<2,64><<<dim3(DD/128, MM/64), blk, G16_SMEM(64)>>>(
        H1, W2t, out, nullptr, MM, DD, DF, b2, X1);
}

// round 9
// speedup vs baseline: 7.0002x; 1.1303x over previous
#include <cuda_runtime.h>
#include <cuda_fp16.h>
#include <cstdint>

// ---------------- problem constants ----------------
#define BB 4
#define SS 1024
#define DD 1280
#define HH 20
#define DH 64
#define DF 5120
#define MM (BB*SS)          // 4096 rows
#define NQKV (3*DD)         // 3840

// ---------------- scratch (device globals) ----------------
__device__ __half g_x16  [(size_t)MM*DD];
__device__ __half g_Wqkv [(size_t)NQKV*DD];     // [N][K] fp16, Q rows pre-scaled
__device__ __half g_W1t  [(size_t)DF*DD];
__device__ __half g_W2t  [(size_t)DD*DF];
__device__ __half g_QKV16[(size_t)MM*NQKV];     // fp16 qkv (attention input)
__device__ float  g_x1   [MM*DD];
__device__ __half g_h0   [MM*DD];
__device__ __half g_h1   [(size_t)MM*DF];

__device__ __forceinline__ void mma_f16(float c[4], const uint32_t a[4], const uint32_t b[2]) {
    asm volatile(
        "mma.sync.aligned.m16n8k16.row.col.f32.f16.f16.f32 "
        "{%0,%1,%2,%3}, {%4,%5,%6,%7}, {%8,%9}, {%0,%1,%2,%3};\n"
        : "+f"(c[0]), "+f"(c[1]), "+f"(c[2]), "+f"(c[3])
        : "r"(a[0]), "r"(a[1]), "r"(a[2]), "r"(a[3]), "r"(b[0]), "r"(b[1]));
}

__device__ __forceinline__ uint32_t smem_u32(const void* p) {
    uint32_t a;
    asm("{ .reg .u64 t; cvta.to.shared.u64 t, %1; cvt.u32.u64 %0, t; }" : "=r"(a) : "l"(p));
    return a;
}

#define CP_ASYNC16(sm, gp) \
    asm volatile("cp.async.cg.shared.global [%0], [%1], 16;" :: "r"(sm), "l"(gp) : "memory")
#define CP_COMMIT() asm volatile("cp.async.commit_group;" ::: "memory")
#define CP_WAIT0()  asm volatile("cp.async.wait_group 0;" ::: "memory")

#define LDSM_T4(r0, r1, r2, r3, addr) \
    asm volatile("ldmatrix.sync.aligned.m8n8.x4.trans.shared.b16 {%0,%1,%2,%3}, [%4];" \
                 : "=r"(r0), "=r"(r1), "=r"(r2), "=r"(r3) : "r"(addr))

// ============================================================================
// Prep kernels
// ============================================================================
__global__ void to_half(const float* __restrict__ in, __half* __restrict__ out, int n4)
{
    int i = blockIdx.x * 256 + threadIdx.x;
    if (i >= n4) return;
    float4 v = ((const float4*)in)[i];
    ((__half2*)out)[i * 2]     = __floats2half2_rn(v.x, v.y);
    ((__half2*)out)[i * 2 + 1] = __floats2half2_rn(v.z, v.w);
}

// transpose + convert: src [K][N] fp32 -> dst [N][K] fp16 (x scale)
__global__ void thalf(const float* __restrict__ src, int K, int N,
                      __half* __restrict__ dst, float scale)
{
    __shared__ float s[32][33];
    const int tx = threadIdx.x, ty = threadIdx.y;
    const int n0 = blockIdx.x * 32, k0 = blockIdx.y * 32;
#pragma unroll
    for (int i = 0; i < 4; i++)
        s[ty + i * 8][tx] = src[(size_t)(k0 + ty + i * 8) * N + n0 + tx];
    __syncthreads();
#pragma unroll
    for (int i = 0; i < 4; i++)
        dst[(size_t)(n0 + ty + i * 8) * K + k0 + tx] =
            __float2half_rn(s[tx][ty + i * 8] * scale);
}

// ============================================================================
// FP16 GEMM (m16n8k16, fp32 accum), cp.async 2-stage, linear smem.
// MODE 0: C16 = half(AB); MODE 1: C16 = half(relu(AB+bias)); MODE 2: C = AB+bias+resid
// ============================================================================
#define HR 72
#define BH_ST (128*HR)
#define G16_SMEM(MT) (2*((MT)*HR + BH_ST)*2)

template <int MODE, int MTILE>
__global__ void __launch_bounds__(256, (MTILE == 128) ? 2 : 3)
gemm_f16(const __half* __restrict__ A, const __half* __restrict__ Bm,
         float* __restrict__ C, __half* __restrict__ C16, int M, int N, int K,
         const float* __restrict__ bias, const float* __restrict__ resid)
{
    constexpr int NI   = MTILE / 32;
    constexpr int PA   = MTILE / 32;
    constexpr int A_ST = MTILE * HR;
    constexpr int STG  = A_ST + BH_ST;

    extern __shared__ __half smh[];
    const uint32_t smb = smem_u32(smh);

    const int t    = threadIdx.x;
    const int lane = t & 31;
    const int w    = t >> 5;
    const int wm   = w & 1;
    const int wn   = w >> 1;
    const int g    = lane >> 2;
    const int tg   = lane & 3;
    const int m0   = blockIdx.y * MTILE;
    const int n0   = blockIdx.x * 128;

    const int ldr = t >> 3;
    const int ldc = (t & 7) * 8;
    const __half* Ag0 = A  + (size_t)(m0 + ldr) * K + ldc;
    const __half* Bg0 = Bm + (size_t)(n0 + ldr) * K + ldc;
    const uint32_t Asd = smb + (uint32_t)((ldr * HR + ldc) * 2);
    const uint32_t Bsd = smb + (uint32_t)((A_ST + ldr * HR + ldc) * 2);

    auto issue = [&](int kt, int buf) {
        const uint32_t bo = (uint32_t)(buf * STG * 2);
        const __half* Ag = Ag0 + kt * 64;
        const __half* Bg = Bg0 + kt * 64;
#pragma unroll
        for (int p = 0; p < PA; p++)
            CP_ASYNC16(Asd + bo + p * 32 * HR * 2, Ag + (size_t)p * 32 * K);
#pragma unroll
        for (int p = 0; p < 4; p++)
            CP_ASYNC16(Bsd + bo + p * 32 * HR * 2, Bg + (size_t)p * 32 * K);
        CP_COMMIT();
    };

    float acc[NI][4][4];
#pragma unroll
    for (int i = 0; i < NI; i++)
#pragma unroll
        for (int j = 0; j < 4; j++)
#pragma unroll
            for (int q = 0; q < 4; q++) acc[i][j][q] = 0.f;

    issue(0, 0);

    const int KT = K >> 6;
    for (int kt = 0; kt < KT; kt++) {
        CP_WAIT0();
        __syncthreads();
        if (kt + 1 < KT) issue(kt + 1, (kt + 1) & 1);

        const __half* As = smh + (kt & 1) * STG;
        const __half* Bs = As + A_ST;
#pragma unroll
        for (int ks = 0; ks < 4; ks++) {
            const int co = ks * 16 + tg * 2;
            uint32_t af[NI][4], bf[4][2];
#pragma unroll
            for (int i = 0; i < NI; i++) {
                const int r = wm * (MTILE / 2) + i * 16 + g;
                af[i][0] = *(const uint32_t*)&As[r * HR + co];
                af[i][1] = *(const uint32_t*)&As[(r + 8) * HR + co];
                af[i][2] = *(const uint32_t*)&As[r * HR + co + 8];
                af[i][3] = *(const uint32_t*)&As[(r + 8) * HR + co + 8];
            }
#pragma unroll
            for (int j = 0; j < 4; j++) {
                const int n = wn * 32 + j * 8 + g;
                bf[j][0] = *(const uint32_t*)&Bs[n * HR + co];
                bf[j][1] = *(const uint32_t*)&Bs[n * HR + co + 8];
            }
#pragma unroll
            for (int i = 0; i < NI; i++)
#pragma unroll
                for (int j = 0; j < 4; j++)
                    mma_f16(acc[i][j], af[i], bf[j]);
        }
        __syncthreads();
    }

    // ---------------- epilogue ----------------
    const int mrow = m0 + wm * (MTILE / 2);
    const int ncol = n0 + wn * 32;
#pragma unroll
    for (int j = 0; j < 4; j++) {
        const int colj = ncol + j * 8 + tg * 2;
        float2 bv = make_float2(0.f, 0.f);
        if (MODE == 1 || MODE == 2) bv = *(const float2*)(bias + colj);
#pragma unroll
        for (int i = 0; i < NI; i++) {
            const int r0 = mrow + i * 16 + g;
            float2 v0 = make_float2(acc[i][j][0], acc[i][j][1]);
            float2 v1 = make_float2(acc[i][j][2], acc[i][j][3]);
            if (MODE == 0) {
                *(__half2*)(C16 + (size_t)r0 * N + colj)       = __floats2half2_rn(v0.x, v0.y);
                *(__half2*)(C16 + (size_t)(r0 + 8) * N + colj) = __floats2half2_rn(v1.x, v1.y);
            } else if (MODE == 1) {
                __half2 h0 = __floats2half2_rn(fmaxf(v0.x + bv.x, 0.f), fmaxf(v0.y + bv.y, 0.f));
                __half2 h1 = __floats2half2_rn(fmaxf(v1.x + bv.x, 0.f), fmaxf(v1.y + bv.y, 0.f));
                *(__half2*)(C16 + (size_t)r0 * N + colj)       = h0;
                *(__half2*)(C16 + (size_t)(r0 + 8) * N + colj) = h1;
            } else {
                float2 r0v = *(const float2*)(resid + (size_t)r0 * N + colj);
                float2 r1v = *(const float2*)(resid + (size_t)(r0 + 8) * N + colj);
                v0.x += bv.x + r0v.x; v0.y += bv.y + r0v.y;
                v1.x += bv.x + r1v.x; v1.y += bv.y + r1v.y;
                *(float2*)(C + (size_t)r0 * N + colj)       = v0;
                *(float2*)(C + (size_t)(r0 + 8) * N + colj) = v1;
            }
        }
    }
}

// ============================================================================
// Flash attention v3: full fp16 mma (m16n8k16), cp.async double-buffered K/V.
// Block = (qtile 64, h, b), 256 thr, 8 warps = 4m x 2n. Key tile 64.
// smem halves (row stride 72): Qs[64] | Ks[2][64] | Vs[2][64] | Ps[64] | aux
// V B-fragments via ldmatrix.x4.trans.b16.
// ============================================================================
#define HR2 72
#define TILE_H (64*HR2)               // 4608 halves
#define OFF_K2 TILE_H
#define OFF_V2 (OFF_K2 + 2*TILE_H)
#define OFF_P2 (OFF_V2 + 2*TILE_H)
#define ATT_HALVES (OFF_P2 + TILE_H)  // 27648
#define ATT_SMEM_BYTES (ATT_HALVES*2 + 448*4)

__global__ void __launch_bounds__(256, 2)
attention_tc(const __half* __restrict__ QKV, const float* __restrict__ X,
             float* __restrict__ X1)
{
    extern __shared__ __half smh[];
    const uint32_t smb = smem_u32(smh);
    __half* Qs  = smh;
    __half* Ps  = smh + OFF_P2;
    float* aux  = (float*)(smh + ATT_HALVES);
    float* m_s  = aux;
    float* l_s  = m_s + 64;
    float* al_s = l_s + 64;
    float* red_m= al_s + 64;
    float* red_s= red_m + 128;

    const int t    = threadIdx.x;
    const int lane = t & 31;
    const int w    = t >> 5;
    const int wm   = w & 3;
    const int wn   = w >> 2;
    const int g    = lane >> 2;
    const int tg   = lane & 3;

    const int qb   = blockIdx.x * 64;
    const int h    = blockIdx.y;
    const int b    = blockIdx.z;
    const int brow = b * SS;

    const int ldr = t >> 3;               // 0..31, +32 second pass
    const int ldc = (t & 7) * 8;          // halves

    const __half* Qg = QKV + (size_t)(brow + qb) * NQKV + h * DH;
    auto issueKV = [&](int kb, int buf) {
        const __half* Kg = QKV + (size_t)(brow + kb) * NQKV + DD     + h * DH;
        const __half* Vg = QKV + (size_t)(brow + kb) * NQKV + 2 * DD + h * DH;
        const uint32_t kd = smb + (uint32_t)((OFF_K2 + buf * TILE_H) * 2);
        const uint32_t vd = smb + (uint32_t)((OFF_V2 + buf * TILE_H) * 2);
#pragma unroll
        for (int p = 0; p < 2; p++) {
            int r = ldr + p * 32;
            CP_ASYNC16(kd + (uint32_t)((r * HR2 + ldc) * 2), Kg + (size_t)r * NQKV + ldc);
            CP_ASYNC16(vd + (uint32_t)((r * HR2 + ldc) * 2), Vg + (size_t)r * NQKV + ldc);
        }
        CP_COMMIT();
    };

    // prologue: Q + first K/V in one group
#pragma unroll
    for (int p = 0; p < 2; p++) {
        int r = ldr + p * 32;
        CP_ASYNC16(smb + (uint32_t)((r * HR2 + ldc) * 2), Qg + (size_t)r * NQKV + ldc);
    }
    issueKV(0, 0);

    if (t < 64) { m_s[t] = -1e30f; l_s[t] = 0.f; }
    float oacc[4][4];
#pragma unroll
    for (int i = 0; i < 4; i++)
#pragma unroll
        for (int j = 0; j < 4; j++) oacc[i][j] = 0.f;

    const int row0 = wm * 16 + g;
    const int row1 = row0 + 8;

    // ldmatrix per-lane V offset: sel bit0 -> k+8, bit1 -> n+8
    const int lrow = lane & 7;
    const int sel  = lane >> 3;
    const int vlo  = ((sel & 1) * 8 + lrow) * HR2 + (sel >> 1) * 8;  // halves

    for (int kt = 0; kt < SS / 64; kt++) {
        CP_WAIT0();
        __syncthreads();
        if (kt + 1 < SS / 64) issueKV((kt + 1) * 64, (kt + 1) & 1);

        const __half* Ks = smh + OFF_K2 + (kt & 1) * TILE_H;
        const uint32_t vsb = smb + (uint32_t)((OFF_V2 + (kt & 1) * TILE_H) * 2);

        // ---- S = Q K^T ----
        float sacc[4][4];
#pragma unroll
        for (int j = 0; j < 4; j++)
#pragma unroll
            for (int q = 0; q < 4; q++) sacc[j][q] = 0.f;

#pragma unroll
        for (int kc = 0; kc < 4; kc++) {
            const int co = kc * 16 + tg * 2;
            uint32_t af[4];
            af[0] = *(const uint32_t*)&Qs[row0 * HR2 + co];
            af[1] = *(const uint32_t*)&Qs[row1 * HR2 + co];
            af[2] = *(const uint32_t*)&Qs[row0 * HR2 + co + 8];
            af[3] = *(const uint32_t*)&Qs[row1 * HR2 + co + 8];
#pragma unroll
            for (int j = 0; j < 4; j++) {
                const int n = wn * 32 + j * 8 + g;
                uint32_t bf[2];
                bf[0] = *(const uint32_t*)&Ks[n * HR2 + co];
                bf[1] = *(const uint32_t*)&Ks[n * HR2 + co + 8];
                mma_f16(sacc[j], af, bf);
            }
        }

        // ---- softmax: row max ----
        float pm0 = -1e30f, pm1 = -1e30f;
#pragma unroll
        for (int j = 0; j < 4; j++) {
            pm0 = fmaxf(pm0, fmaxf(sacc[j][0], sacc[j][1]));
            pm1 = fmaxf(pm1, fmaxf(sacc[j][2], sacc[j][3]));
        }
        pm0 = fmaxf(pm0, __shfl_xor_sync(0xffffffffu, pm0, 1));
        pm0 = fmaxf(pm0, __shfl_xor_sync(0xffffffffu, pm0, 2));
        pm1 = fmaxf(pm1, __shfl_xor_sync(0xffffffffu, pm1, 1));
        pm1 = fmaxf(pm1, __shfl_xor_sync(0xffffffffu, pm1, 2));
        if (tg == 0) {
            red_m[row0 * 2 + wn] = pm0;
            red_m[row1 * 2 + wn] = pm1;
        }
        __syncthreads();
        if (t < 64) {
            float mold = m_s[t];
            float mnew = fmaxf(mold, fmaxf(red_m[t * 2], red_m[t * 2 + 1]));
            m_s[t]  = mnew;
            al_s[t] = __expf(mold - mnew);
        }
        __syncthreads();

        // ---- exp, store P (fp16), row sums, rescale O ----
        const float mn0 = m_s[row0], mn1 = m_s[row1];
        const float al0 = al_s[row0], al1 = al_s[row1];
        float rs0 = 0.f, rs1 = 0.f;
#pragma unroll
        for (int j = 0; j < 4; j++) {
            float p00 = __expf(sacc[j][0] - mn0);
            float p01 = __expf(sacc[j][1] - mn0);
            float p10 = __expf(sacc[j][2] - mn1);
            float p11 = __expf(sacc[j][3] - mn1);
            rs0 += p00 + p01;
            rs1 += p10 + p11;
            const int col = wn * 32 + j * 8 + tg * 2;
            *(__half2*)&Ps[row0 * HR2 + col] = __floats2half2_rn(p00, p01);
            *(__half2*)&Ps[row1 * HR2 + col] = __floats2half2_rn(p10, p11);
        }
        rs0 += __shfl_xor_sync(0xffffffffu, rs0, 1);
        rs0 += __shfl_xor_sync(0xffffffffu, rs0, 2);
        rs1 += __shfl_xor_sync(0xffffffffu, rs1, 1);
        rs1 += __shfl_xor_sync(0xffffffffu, rs1, 2);
        if (tg == 0) {
            red_s[row0 * 2 + wn] = rs0;
            red_s[row1 * 2 + wn] = rs1;
        }
#pragma unroll
        for (int i = 0; i < 4; i++) {
            oacc[i][0] *= al0; oacc[i][1] *= al0;
            oacc[i][2] *= al1; oacc[i][3] *= al1;
        }
        __syncthreads();
        if (t < 64)
            l_s[t] = l_s[t] * al_s[t] + red_s[t * 2] + red_s[t * 2 + 1];

        // ---- O += P @ V (V via ldmatrix.trans) ----
#pragma unroll
        for (int kc = 0; kc < 4; kc++) {
            const int co = kc * 16 + tg * 2;
            uint32_t af[4];
            af[0] = *(const uint32_t*)&Ps[row0 * HR2 + co];
            af[1] = *(const uint32_t*)&Ps[row1 * HR2 + co];
            af[2] = *(const uint32_t*)&Ps[row0 * HR2 + co + 8];
            af[3] = *(const uint32_t*)&Ps[row1 * HR2 + co + 8];
#pragma unroll
            for (int jp = 0; jp < 2; jp++) {
                uint32_t r0, r1, r2, r3;
                const uint32_t va = vsb +
                    (uint32_t)((kc * 16 * HR2 + wn * 32 + jp * 16 + vlo) * 2);
                LDSM_T4(r0, r1, r2, r3, va);
                uint32_t bf0[2] = { r0, r1 };
                uint32_t bf1[2] = { r2, r3 };
                mma_f16(oacc[jp * 2],     af, bf0);
                mma_f16(oacc[jp * 2 + 1], af, bf1);
            }
        }
        __syncthreads();
    }

    // ---- epilogue: X1 = O/l + X ----
    const float il0 = 1.f / l_s[row0];
    const float il1 = 1.f / l_s[row1];
    const size_t tok0 = (size_t)(brow + qb + row0);
    const size_t tok1 = (size_t)(brow + qb + row1);
#pragma unroll
    for (int j = 0; j < 4; j++) {
        const int col = h * DH + wn * 32 + j * 8 + tg * 2;
        float2 x0 = *(const float2*)(X + tok0 * DD + col);
        float2 x1 = *(const float2*)(X + tok1 * DD + col);
        float2 o0 = make_float2(oacc[j][0] * il0 + x0.x, oacc[j][1] * il0 + x0.y);
        float2 o1 = make_float2(oacc[j][2] * il1 + x1.x, oacc[j][3] * il1 + x1.y);
        *(float2*)(X1 + tok0 * DD + col) = o0;
        *(float2*)(X1 + tok1 * DD + col) = o1;
    }
}

// ============================================================================
// LayerNorm over D=1280; emits fp16 for the FFN1 GEMM.
// ============================================================================
__global__ void __launch_bounds__(256)
ln_kernel(const float* __restrict__ X, const float* __restrict__ gam,
          const float* __restrict__ bet, __half* __restrict__ Y)
{
    const int row = blockIdx.x;
    const float* xr = X + (size_t)row * DD;
    float v[5];
    float sum = 0.f, sq = 0.f;
#pragma unroll
    for (int i = 0; i < 5; i++) {
        v[i] = xr[threadIdx.x + i * 256];
        sum += v[i];
        sq  += v[i] * v[i];
    }
#pragma unroll
    for (int off = 16; off; off >>= 1) {
        sum += __shfl_xor_sync(0xffffffffu, sum, off);
        sq  += __shfl_xor_sync(0xffffffffu, sq , off);
    }
    __shared__ float sS[8], sQ[8];
    const int w = threadIdx.x >> 5, lane = threadIdx.x & 31;
    if (lane == 0) { sS[w] = sum; sQ[w] = sq; }
    __syncthreads();
    if (threadIdx.x == 0) {
        float a = 0.f, q = 0.f;
#pragma unroll
        for (int i = 0; i < 8; i++) { a += sS[i]; q += sQ[i]; }
        sS[0] = a; sQ[0] = q;
    }
    __syncthreads();
    const float mu   = sS[0] * (1.0f / DD);
    const float var  = sQ[0] * (1.0f / DD) - mu * mu;
    const float rstd = rsqrtf(var + 1e-5f);
    __half* yr = Y + (size_t)row * DD;
#pragma unroll
    for (int i = 0; i < 5; i++) {
        int c = threadIdx.x + i * 256;
        yr[c] = __float2half_rn((v[i] - mu) * rstd * gam[c] + bet[c]);
    }
}

// ============================================================================
// launch
// ============================================================================
extern "C" void kernel_launch(void* const* d_in, const int* in_sizes, int n_in,
                              void* d_out, int out_size)
{
    const float* x   = (const float*)d_in[0];
    const float* Wq  = (const float*)d_in[1];
    const float* Wk  = (const float*)d_in[2];
    const float* Wv  = (const float*)d_in[3];
    const float* lng = (const float*)d_in[4];
    const float* lnb = (const float*)d_in[5];
    const float* W1  = (const float*)d_in[6];
    const float* b1  = (const float*)d_in[7];
    const float* W2  = (const float*)d_in[8];
    const float* b2  = (const float*)d_in[9];
    float* out = (float*)d_out;

    __half *X16, *Wqkv, *W1t, *W2t, *QKV16, *H0, *H1;
    float *X1;
    cudaGetSymbolAddress((void**)&X16,   g_x16);
    cudaGetSymbolAddress((void**)&Wqkv,  g_Wqkv);
    cudaGetSymbolAddress((void**)&W1t,   g_W1t);
    cudaGetSymbolAddress((void**)&W2t,   g_W2t);
    cudaGetSymbolAddress((void**)&QKV16, g_QKV16);
    cudaGetSymbolAddress((void**)&X1,    g_x1);
    cudaGetSymbolAddress((void**)&H0,    g_h0);
    cudaGetSymbolAddress((void**)&H1,    g_h1);

    cudaFuncSetAttribute((const void*)gemm_f16<0,64>,  cudaFuncAttributeMaxDynamicSharedMemorySize, G16_SMEM(64));
    cudaFuncSetAttribute((const void*)gemm_f16<1,128>, cudaFuncAttributeMaxDynamicSharedMemorySize, G16_SMEM(128));
    cudaFuncSetAttribute((const void*)gemm_f16<2,128>, cudaFuncAttributeMaxDynamicSharedMemorySize, G16_SMEM(128));
    cudaFuncSetAttribute((const void*)attention_tc,    cudaFuncAttributeMaxDynamicSharedMemorySize, ATT_SMEM_BYTES);

    const dim3 blk(256);
    const dim3 tb(32, 8);

    // prep
    to_half<<<(MM*DD/4 + 255)/256, blk>>>(x, X16, MM*DD/4);
    thalf<<<dim3(DD/32, DD/32), tb>>>(Wq, DD, DD, Wqkv,                   0.125f);
    thalf<<<dim3(DD/32, DD/32), tb>>>(Wk, DD, DD, Wqkv + (size_t)DD*DD,   1.0f);
    thalf<<<dim3(DD/32, DD/32), tb>>>(Wv, DD, DD, Wqkv + (size_t)2*DD*DD, 1.0f);
    thalf<<<dim3(DF/32, DD/32), tb>>>(W1, DD, DF, W1t, 1.0f);
    thalf<<<dim3(DD/32, DF/32), tb>>>(W2, DF, DD, W2t, 1.0f);

    // QKV projection -> fp16
    gemm_f16<0,64><<<dim3(NQKV/128, MM/64), blk, G16_SMEM(64)>>>(
        X16, Wqkv, nullptr, QKV16, MM, NQKV, DD, nullptr, nullptr);

    // fused fp16 attention + residual
    attention_tc<<<dim3(SS/64, HH, BB), blk, ATT_SMEM_BYTES>>>(QKV16, x, X1);

    // layernorm -> fp16
    ln_kernel<<<MM, 256>>>(X1, lng, lnb, H0);

    // FFN
    gemm_f16<1,128><<<dim3(DF/128, MM/128), blk, G16_SMEM(128)>>>(
        H0, W1t, nullptr, H1, MM, DF, DD, b1, nullptr);
    gemm_f16<2,128><<<dim3(DD/128, MM/128), blk, G16_SMEM(128)>>>(
        H1, W2t, out, nullptr, MM, DD, DF, b2, X1);
}

// round 10
// speedup vs baseline: 7.4600x; 1.0657x over previous
#include <cuda_runtime.h>
#include <cuda_fp16.h>
#include <cstdint>

// ---------------- problem constants ----------------
#define BB 4
#define SS 1024
#define DD 1280
#define HH 20
#define DH 64
#define DF 5120
#define MM (BB*SS)          // 4096 rows
#define NQKV (3*DD)         // 3840

// ---------------- scratch (device globals) ----------------
__device__ __half g_x16  [(size_t)MM*DD];
__device__ __half g_Wqkv [(size_t)NQKV*DD];     // [N][K] fp16, Q rows pre-scaled
__device__ __half g_W1t  [(size_t)DF*DD];
__device__ __half g_W2t  [(size_t)DD*DF];
__device__ __half g_QKV16[(size_t)MM*NQKV];
__device__ float  g_x1   [MM*DD];
__device__ __half g_h0   [MM*DD];
__device__ __half g_h1   [(size_t)MM*DF];

__device__ __forceinline__ void mma_f16(float c[4], const uint32_t a[4], const uint32_t b[2]) {
    asm volatile(
        "mma.sync.aligned.m16n8k16.row.col.f32.f16.f16.f32 "
        "{%0,%1,%2,%3}, {%4,%5,%6,%7}, {%8,%9}, {%0,%1,%2,%3};\n"
        : "+f"(c[0]), "+f"(c[1]), "+f"(c[2]), "+f"(c[3])
        : "r"(a[0]), "r"(a[1]), "r"(a[2]), "r"(a[3]), "r"(b[0]), "r"(b[1]));
}

__device__ __forceinline__ uint32_t smem_u32(const void* p) {
    uint32_t a;
    asm("{ .reg .u64 t; cvta.to.shared.u64 t, %1; cvt.u32.u64 %0, t; }" : "=r"(a) : "l"(p));
    return a;
}

#define CP_ASYNC16(sm, gp) \
    asm volatile("cp.async.cg.shared.global [%0], [%1], 16;" :: "r"(sm), "l"(gp) : "memory")
#define CP_COMMIT() asm volatile("cp.async.commit_group;" ::: "memory")
#define CP_WAIT0()  asm volatile("cp.async.wait_group 0;" ::: "memory")

#define LDSM_T4(r0, r1, r2, r3, addr) \
    asm volatile("ldmatrix.sync.aligned.m8n8.x4.trans.shared.b16 {%0,%1,%2,%3}, [%4];" \
                 : "=r"(r0), "=r"(r1), "=r"(r2), "=r"(r3) : "r"(addr))

// ============================================================================
// Prep kernels
// ============================================================================
__global__ void to_half(const float* __restrict__ in, __half* __restrict__ out, int n4)
{
    int i = blockIdx.x * 256 + threadIdx.x;
    if (i >= n4) return;
    float4 v = ((const float4*)in)[i];
    ((__half2*)out)[i * 2]     = __floats2half2_rn(v.x, v.y);
    ((__half2*)out)[i * 2 + 1] = __floats2half2_rn(v.z, v.w);
}

// transpose + convert: src [K][N] fp32 -> dst [N][K] fp16 (x scale)
__global__ void thalf(const float* __restrict__ src, int K, int N,
                      __half* __restrict__ dst, float scale)
{
    __shared__ float s[32][33];
    const int tx = threadIdx.x, ty = threadIdx.y;
    const int n0 = blockIdx.x * 32, k0 = blockIdx.y * 32;
#pragma unroll
    for (int i = 0; i < 4; i++)
        s[ty + i * 8][tx] = src[(size_t)(k0 + ty + i * 8) * N + n0 + tx];
    __syncthreads();
#pragma unroll
    for (int i = 0; i < 4; i++)
        dst[(size_t)(n0 + ty + i * 8) * K + k0 + tx] =
            __float2half_rn(s[tx][ty + i * 8] * scale);
}

// fused Wq/Wk/Wv transpose+convert (z selects source; Q rows scaled 1/8)
__global__ void thalf_qkv(const float* __restrict__ Wq, const float* __restrict__ Wk,
                          const float* __restrict__ Wv, __half* __restrict__ dst)
{
    __shared__ float s[32][33];
    const int tx = threadIdx.x, ty = threadIdx.y;
    const int n0 = blockIdx.x * 32, k0 = blockIdx.y * 32;
    const int z  = blockIdx.z;
    const float* src = (z == 0) ? Wq : (z == 1) ? Wk : Wv;
    const float scale = (z == 0) ? 0.125f : 1.0f;
    __half* d = dst + (size_t)z * DD * DD;
#pragma unroll
    for (int i = 0; i < 4; i++)
        s[ty + i * 8][tx] = src[(size_t)(k0 + ty + i * 8) * DD + n0 + tx];
    __syncthreads();
#pragma unroll
    for (int i = 0; i < 4; i++)
        d[(size_t)(n0 + ty + i * 8) * DD + k0 + tx] =
            __float2half_rn(s[tx][ty + i * 8] * scale);
}

// ============================================================================
// FP16 GEMM (m16n8k16, fp32 accum), cp.async 2-stage, linear smem (validated).
// MODE 0: C16 = half(AB); MODE 1: C16 = half(relu(AB+bias)); MODE 2: C = AB+bias+resid
// ============================================================================
#define HR 72
#define BH_ST (128*HR)
#define G16_SMEM(MT) (2*((MT)*HR + BH_ST)*2)

template <int MODE, int MTILE>
__global__ void __launch_bounds__(256, (MTILE == 128) ? 2 : 3)
gemm_f16(const __half* __restrict__ A, const __half* __restrict__ Bm,
         float* __restrict__ C, __half* __restrict__ C16, int M, int N, int K,
         const float* __restrict__ bias, const float* __restrict__ resid)
{
    constexpr int NI   = MTILE / 32;
    constexpr int PA   = MTILE / 32;
    constexpr int A_ST = MTILE * HR;
    constexpr int STG  = A_ST + BH_ST;

    extern __shared__ __half smh[];
    const uint32_t smb = smem_u32(smh);

    const int t    = threadIdx.x;
    const int lane = t & 31;
    const int w    = t >> 5;
    const int wm   = w & 1;
    const int wn   = w >> 1;
    const int g    = lane >> 2;
    const int tg   = lane & 3;
    const int m0   = blockIdx.y * MTILE;
    const int n0   = blockIdx.x * 128;

    const int ldr = t >> 3;
    const int ldc = (t & 7) * 8;
    const __half* Ag0 = A  + (size_t)(m0 + ldr) * K + ldc;
    const __half* Bg0 = Bm + (size_t)(n0 + ldr) * K + ldc;
    const uint32_t Asd = smb + (uint32_t)((ldr * HR + ldc) * 2);
    const uint32_t Bsd = smb + (uint32_t)((A_ST + ldr * HR + ldc) * 2);

    auto issue = [&](int kt, int buf) {
        const uint32_t bo = (uint32_t)(buf * STG * 2);
        const __half* Ag = Ag0 + kt * 64;
        const __half* Bg = Bg0 + kt * 64;
#pragma unroll
        for (int p = 0; p < PA; p++)
            CP_ASYNC16(Asd + bo + p * 32 * HR * 2, Ag + (size_t)p * 32 * K);
#pragma unroll
        for (int p = 0; p < 4; p++)
            CP_ASYNC16(Bsd + bo + p * 32 * HR * 2, Bg + (size_t)p * 32 * K);
        CP_COMMIT();
    };

    float acc[NI][4][4];
#pragma unroll
    for (int i = 0; i < NI; i++)
#pragma unroll
        for (int j = 0; j < 4; j++)
#pragma unroll
            for (int q = 0; q < 4; q++) acc[i][j][q] = 0.f;

    issue(0, 0);

    const int KT = K >> 6;
    for (int kt = 0; kt < KT; kt++) {
        CP_WAIT0();
        __syncthreads();
        if (kt + 1 < KT) issue(kt + 1, (kt + 1) & 1);

        const __half* As = smh + (kt & 1) * STG;
        const __half* Bs = As + A_ST;
#pragma unroll
        for (int ks = 0; ks < 4; ks++) {
            const int co = ks * 16 + tg * 2;
            uint32_t af[NI][4], bf[4][2];
#pragma unroll
            for (int i = 0; i < NI; i++) {
                const int r = wm * (MTILE / 2) + i * 16 + g;
                af[i][0] = *(const uint32_t*)&As[r * HR + co];
                af[i][1] = *(const uint32_t*)&As[(r + 8) * HR + co];
                af[i][2] = *(const uint32_t*)&As[r * HR + co + 8];
                af[i][3] = *(const uint32_t*)&As[(r + 8) * HR + co + 8];
            }
#pragma unroll
            for (int j = 0; j < 4; j++) {
                const int n = wn * 32 + j * 8 + g;
                bf[j][0] = *(const uint32_t*)&Bs[n * HR + co];
                bf[j][1] = *(const uint32_t*)&Bs[n * HR + co + 8];
            }
#pragma unroll
            for (int i = 0; i < NI; i++)
#pragma unroll
                for (int j = 0; j < 4; j++)
                    mma_f16(acc[i][j], af[i], bf[j]);
        }
        __syncthreads();
    }

    // ---------------- epilogue ----------------
    const int mrow = m0 + wm * (MTILE / 2);
    const int ncol = n0 + wn * 32;
#pragma unroll
    for (int j = 0; j < 4; j++) {
        const int colj = ncol + j * 8 + tg * 2;
        float2 bv = make_float2(0.f, 0.f);
        if (MODE == 1 || MODE == 2) bv = *(const float2*)(bias + colj);
#pragma unroll
        for (int i = 0; i < NI; i++) {
            const int r0 = mrow + i * 16 + g;
            float2 v0 = make_float2(acc[i][j][0], acc[i][j][1]);
            float2 v1 = make_float2(acc[i][j][2], acc[i][j][3]);
            if (MODE == 0) {
                *(__half2*)(C16 + (size_t)r0 * N + colj)       = __floats2half2_rn(v0.x, v0.y);
                *(__half2*)(C16 + (size_t)(r0 + 8) * N + colj) = __floats2half2_rn(v1.x, v1.y);
            } else if (MODE == 1) {
                __half2 h0 = __floats2half2_rn(fmaxf(v0.x + bv.x, 0.f), fmaxf(v0.y + bv.y, 0.f));
                __half2 h1 = __floats2half2_rn(fmaxf(v1.x + bv.x, 0.f), fmaxf(v1.y + bv.y, 0.f));
                *(__half2*)(C16 + (size_t)r0 * N + colj)       = h0;
                *(__half2*)(C16 + (size_t)(r0 + 8) * N + colj) = h1;
            } else {
                float2 r0v = *(const float2*)(resid + (size_t)r0 * N + colj);
                float2 r1v = *(const float2*)(resid + (size_t)(r0 + 8) * N + colj);
                v0.x += bv.x + r0v.x; v0.y += bv.y + r0v.y;
                v1.x += bv.x + r1v.x; v1.y += bv.y + r1v.y;
                *(float2*)(C + (size_t)r0 * N + colj)       = v0;
                *(float2*)(C + (size_t)(r0 + 8) * N + colj) = v1;
            }
        }
    }
}

// ============================================================================
// Flash attention v4: FA2-style register softmax. qtile 128, 8 warps all-M
// (16 rows each, full 64-key range). P stays in registers (S C-frag == P A-frag).
// One __syncthreads per key tile. V via ldmatrix.x4.trans (validated mapping).
// smem halves (stride 72): Q[128] | K[2][64] | V[2][64]  = 55296 B
// ============================================================================
#define HRA 72
#define KV_H (64*HRA)                  // 4608 halves per K/V buffer
#define OFF_KA (128*HRA)               // 9216
#define OFF_VA (OFF_KA + 2*KV_H)       // 18432
#define ATT_HALVES (OFF_VA + 2*KV_H)   // 27648
#define ATT_SMEM_BYTES (ATT_HALVES*2)  // 55296

__global__ void __launch_bounds__(256, 2)
attention_tc(const __half* __restrict__ QKV, const float* __restrict__ X,
             float* __restrict__ X1)
{
    extern __shared__ __half smh[];
    const uint32_t smb = smem_u32(smh);
    __half* Qs = smh;

    const int t    = threadIdx.x;
    const int lane = t & 31;
    const int w    = t >> 5;
    const int g    = lane >> 2;
    const int tg   = lane & 3;

    const int qb   = blockIdx.x * 128;
    const int h    = blockIdx.y;
    const int b    = blockIdx.z;
    const int brow = b * SS;

    // ---- loaders ----
    const __half* Qg = QKV + (size_t)(brow + qb) * NQKV + h * DH;
    const int ldr = t >> 3;              // 0..31 (+32 per pass)
    const int ldc = (t & 7) * 8;

    auto issueKV = [&](int kb, int buf) {
        const __half* Kg = QKV + (size_t)(brow + kb) * NQKV + DD     + h * DH;
        const __half* Vg = QKV + (size_t)(brow + kb) * NQKV + 2 * DD + h * DH;
        const uint32_t kd = smb + (uint32_t)((OFF_KA + buf * KV_H) * 2);
        const uint32_t vd = smb + (uint32_t)((OFF_VA + buf * KV_H) * 2);
#pragma unroll
        for (int p = 0; p < 2; p++) {
            int r = ldr + p * 32;
            CP_ASYNC16(kd + (uint32_t)((r * HRA + ldc) * 2), Kg + (size_t)r * NQKV + ldc);
            CP_ASYNC16(vd + (uint32_t)((r * HRA + ldc) * 2), Vg + (size_t)r * NQKV + ldc);
        }
        CP_COMMIT();
    };

    // prologue: Q (128 rows = 4 passes) + first K/V, one commit group
#pragma unroll
    for (int p = 0; p < 4; p++) {
        int e = p * 256 + t;
        int r = e >> 3, c8 = (e & 7) * 8;
        CP_ASYNC16(smb + (uint32_t)((r * HRA + c8) * 2), Qg + (size_t)r * NQKV + c8);
    }
    issueKV(0, 0);

    // per-thread state: rows r0 = w*16+g, r1 = r0+8
    const int r0 = w * 16 + g;
    const int r1 = r0 + 8;
    float m0 = -1e30f, m1 = -1e30f, l0 = 0.f, l1 = 0.f;
    float oacc[8][4];
#pragma unroll
    for (int i = 0; i < 8; i++)
#pragma unroll
        for (int q = 0; q < 4; q++) oacc[i][q] = 0.f;

    // ldmatrix per-lane V offset: sel bit0 -> key+8, bit1 -> dh+8
    const int lrow = lane & 7;
    const int sel  = lane >> 3;
    const int vlo  = ((sel & 1) * 8 + lrow) * HRA + (sel >> 1) * 8;

    for (int kt = 0; kt < SS / 64; kt++) {
        CP_WAIT0();
        __syncthreads();
        if (kt + 1 < SS / 64) issueKV((kt + 1) * 64, (kt + 1) & 1);

        const __half* Ks = smh + OFF_KA + (kt & 1) * KV_H;
        const uint32_t vsb = smb + (uint32_t)((OFF_VA + (kt & 1) * KV_H) * 2);

        // ---- S = Q K^T : 16 rows x 64 keys per warp ----
        float sacc[8][4];
#pragma unroll
        for (int j = 0; j < 8; j++)
#pragma unroll
            for (int q = 0; q < 4; q++) sacc[j][q] = 0.f;

#pragma unroll
        for (int kc = 0; kc < 4; kc++) {
            const int co = kc * 16 + tg * 2;
            uint32_t af[4];
            af[0] = *(const uint32_t*)&Qs[r0 * HRA + co];
            af[1] = *(const uint32_t*)&Qs[r1 * HRA + co];
            af[2] = *(const uint32_t*)&Qs[r0 * HRA + co + 8];
            af[3] = *(const uint32_t*)&Qs[r1 * HRA + co + 8];
#pragma unroll
            for (int j = 0; j < 8; j++) {
                uint32_t bf[2];
                bf[0] = *(const uint32_t*)&Ks[(j * 8 + g) * HRA + co];
                bf[1] = *(const uint32_t*)&Ks[(j * 8 + g) * HRA + co + 8];
                mma_f16(sacc[j], af, bf);
            }
        }

        // ---- warp-local softmax (registers + 2 shfls) ----
        float pm0 = -1e30f, pm1 = -1e30f;
#pragma unroll
        for (int j = 0; j < 8; j++) {
            pm0 = fmaxf(pm0, fmaxf(sacc[j][0], sacc[j][1]));
            pm1 = fmaxf(pm1, fmaxf(sacc[j][2], sacc[j][3]));
        }
        pm0 = fmaxf(pm0, __shfl_xor_sync(0xffffffffu, pm0, 1));
        pm0 = fmaxf(pm0, __shfl_xor_sync(0xffffffffu, pm0, 2));
        pm1 = fmaxf(pm1, __shfl_xor_sync(0xffffffffu, pm1, 1));
        pm1 = fmaxf(pm1, __shfl_xor_sync(0xffffffffu, pm1, 2));

        const float mn0 = fmaxf(m0, pm0);
        const float mn1 = fmaxf(m1, pm1);
        const float al0 = __expf(m0 - mn0);
        const float al1 = __expf(m1 - mn1);
        m0 = mn0; m1 = mn1;

        uint32_t pf0[8], pf1[8];
        float rs0 = 0.f, rs1 = 0.f;
#pragma unroll
        for (int j = 0; j < 8; j++) {
            float p00 = __expf(sacc[j][0] - mn0);
            float p01 = __expf(sacc[j][1] - mn0);
            float p10 = __expf(sacc[j][2] - mn1);
            float p11 = __expf(sacc[j][3] - mn1);
            rs0 += p00 + p01;
            rs1 += p10 + p11;
            __half2 h0 = __floats2half2_rn(p00, p01);
            __half2 h1 = __floats2half2_rn(p10, p11);
            pf0[j] = *(uint32_t*)&h0;
            pf1[j] = *(uint32_t*)&h1;
        }
        rs0 += __shfl_xor_sync(0xffffffffu, rs0, 1);
        rs0 += __shfl_xor_sync(0xffffffffu, rs0, 2);
        rs1 += __shfl_xor_sync(0xffffffffu, rs1, 1);
        rs1 += __shfl_xor_sync(0xffffffffu, rs1, 2);
        l0 = l0 * al0 + rs0;
        l1 = l1 * al1 + rs1;
#pragma unroll
        for (int i = 0; i < 8; i++) {
            oacc[i][0] *= al0; oacc[i][1] *= al0;
            oacc[i][2] *= al1; oacc[i][3] *= al1;
        }

        // ---- O += P @ V (P from registers; V via ldmatrix.trans) ----
#pragma unroll
        for (int kc = 0; kc < 4; kc++) {
            uint32_t af[4];
            af[0] = pf0[2 * kc];
            af[1] = pf1[2 * kc];
            af[2] = pf0[2 * kc + 1];
            af[3] = pf1[2 * kc + 1];
#pragma unroll
            for (int jp = 0; jp < 4; jp++) {
                uint32_t q0, q1, q2, q3;
                const uint32_t va = vsb +
                    (uint32_t)((kc * 16 * HRA + jp * 16 + vlo) * 2);
                LDSM_T4(q0, q1, q2, q3, va);
                uint32_t bf0[2] = { q0, q1 };
                uint32_t bf1[2] = { q2, q3 };
                mma_f16(oacc[jp * 2],     af, bf0);
                mma_f16(oacc[jp * 2 + 1], af, bf1);
            }
        }
    }

    // ---- epilogue: X1 = O/l + X ----
    const float il0 = 1.f / l0;
    const float il1 = 1.f / l1;
    const size_t tok0 = (size_t)(brow + qb + r0);
    const size_t tok1 = (size_t)(brow + qb + r1);
#pragma unroll
    for (int jd = 0; jd < 8; jd++) {
        const int col = h * DH + jd * 8 + tg * 2;
        float2 x0 = *(const float2*)(X + tok0 * DD + col);
        float2 x1 = *(const float2*)(X + tok1 * DD + col);
        float2 o0 = make_float2(oacc[jd][0] * il0 + x0.x, oacc[jd][1] * il0 + x0.y);
        float2 o1 = make_float2(oacc[jd][2] * il1 + x1.x, oacc[jd][3] * il1 + x1.y);
        *(float2*)(X1 + tok0 * DD + col) = o0;
        *(float2*)(X1 + tok1 * DD + col) = o1;
    }
}

// ============================================================================
// LayerNorm over D=1280; emits fp16 for the FFN1 GEMM.
// ============================================================================
__global__ void __launch_bounds__(256)
ln_kernel(const float* __restrict__ X, const float* __restrict__ gam,
          const float* __restrict__ bet, __half* __restrict__ Y)
{
    const int row = blockIdx.x;
    const float* xr = X + (size_t)row * DD;
    float v[5];
    float sum = 0.f, sq = 0.f;
#pragma unroll
    for (int i = 0; i < 5; i++) {
        v[i] = xr[threadIdx.x + i * 256];
        sum += v[i];
        sq  += v[i] * v[i];
    }
#pragma unroll
    for (int off = 16; off; off >>= 1) {
        sum += __shfl_xor_sync(0xffffffffu, sum, off);
        sq  += __shfl_xor_sync(0xffffffffu, sq , off);
    }
    __shared__ float sS[8], sQ[8];
    const int w = threadIdx.x >> 5, lane = threadIdx.x & 31;
    if (lane == 0) { sS[w] = sum; sQ[w] = sq; }
    __syncthreads();
    if (threadIdx.x == 0) {
        float a = 0.f, q = 0.f;
#pragma unroll
        for (int i = 0; i < 8; i++) { a += sS[i]; q += sQ[i]; }
        sS[0] = a; sQ[0] = q;
    }
    __syncthreads();
    const float mu   = sS[0] * (1.0f / DD);
    const float var  = sQ[0] * (1.0f / DD) - mu * mu;
    const float rstd = rsqrtf(var + 1e-5f);
    __half* yr = Y + (size_t)row * DD;
#pragma unroll
    for (int i = 0; i < 5; i++) {
        int c = threadIdx.x + i * 256;
        yr[c] = __float2half_rn((v[i] - mu) * rstd * gam[c] + bet[c]);
    }
}

// ============================================================================
// launch
// ============================================================================
extern "C" void kernel_launch(void* const* d_in, const int* in_sizes, int n_in,
                              void* d_out, int out_size)
{
    const float* x   = (const float*)d_in[0];
    const float* Wq  = (const float*)d_in[1];
    const float* Wk  = (const float*)d_in[2];
    const float* Wv  = (const float*)d_in[3];
    const float* lng = (const float*)d_in[4];
    const float* lnb = (const float*)d_in[5];
    const float* W1  = (const float*)d_in[6];
    const float* b1  = (const float*)d_in[7];
    const float* W2  = (const float*)d_in[8];
    const float* b2  = (const float*)d_in[9];
    float* out = (float*)d_out;

    __half *X16, *Wqkv, *W1t, *W2t, *QKV16, *H0, *H1;
    float *X1;
    cudaGetSymbolAddress((void**)&X16,   g_x16);
    cudaGetSymbolAddress((void**)&Wqkv,  g_Wqkv);
    cudaGetSymbolAddress((void**)&W1t,   g_W1t);
    cudaGetSymbolAddress((void**)&W2t,   g_W2t);
    cudaGetSymbolAddress((void**)&QKV16, g_QKV16);
    cudaGetSymbolAddress((void**)&X1,    g_x1);
    cudaGetSymbolAddress((void**)&H0,    g_h0);
    cudaGetSymbolAddress((void**)&H1,    g_h1);

    cudaFuncSetAttribute((const void*)gemm_f16<0,64>,  cudaFuncAttributeMaxDynamicSharedMemorySize, G16_SMEM(64));
    cudaFuncSetAttribute((const void*)gemm_f16<1,128>, cudaFuncAttributeMaxDynamicSharedMemorySize, G16_SMEM(128));
    cudaFuncSetAttribute((const void*)gemm_f16<2,128>, cudaFuncAttributeMaxDynamicSharedMemorySize, G16_SMEM(128));
    cudaFuncSetAttribute((const void*)attention_tc,    cudaFuncAttributeMaxDynamicSharedMemorySize, ATT_SMEM_BYTES);

    const dim3 blk(256);
    const dim3 tb(32, 8);

    // prep
    to_half<<<(MM*DD/4 + 255)/256, blk>>>(x, X16, MM*DD/4);
    thalf_qkv<<<dim3(DD/32, DD/32, 3), tb>>>(Wq, Wk, Wv, Wqkv);
    thalf<<<dim3(DF/32, DD/32), tb>>>(W1, DD, DF, W1t, 1.0f);
    thalf<<<dim3(DD/32, DF/32), tb>>>(W2, DF, DD, W2t, 1.0f);

    // QKV projection -> fp16
    gemm_f16<0,64><<<dim3(NQKV/128, MM/64), blk, G16_SMEM(64)>>>(
        X16, Wqkv, nullptr, QKV16, MM, NQKV, DD, nullptr, nullptr);

    // fused fp16 attention + residual (FA2 register softmax)
    attention_tc<<<dim3(SS/128, HH, BB), blk, ATT_SMEM_BYTES>>>(QKV16, x, X1);

    // layernorm -> fp16
    ln_kernel<<<MM, 256>>>(X1, lng, lnb, H0);

    // FFN
    gemm_f16<1,128><<<dim3(DF/128, MM/128), blk, G16_SMEM(128)>>>(
        H0, W1t, nullptr, H1, MM, DF, DD, b1, nullptr);
    gemm_f16<2,128><<<dim3(DD/128, MM/128), blk, G16_SMEM(128)>>>(
        H1, W2t, out, nullptr, MM, DD, DF, b2, X1);
}

// round 11
// speedup vs baseline: 8.0830x; 1.0835x over previous
#include <cuda_runtime.h>
#include <cuda_fp16.h>
#include <cstdint>

// ---------------- problem constants ----------------
#define BB 4
#define SS 1024
#define DD 1280
#define HH 20
#define DH 64
#define DF 5120
#define MM (BB*SS)          // 4096 rows
#define NQKV (3*DD)         // 3840

// ---------------- scratch (device globals) ----------------
__device__ __half g_x16  [(size_t)MM*DD];
__device__ __half g_Wqkv [(size_t)NQKV*DD];     // [N][K] fp16, Q rows pre-scaled
__device__ __half g_W1t  [(size_t)DF*DD];
__device__ __half g_W2t  [(size_t)DD*DF];
__device__ __half g_QKV16[(size_t)MM*NQKV];
__device__ float  g_x1   [MM*DD];
__device__ __half g_h0   [MM*DD];
__device__ __half g_h1   [(size_t)MM*DF];

__device__ __forceinline__ void mma_f16(float c[4], const uint32_t a[4], const uint32_t b[2]) {
    asm volatile(
        "mma.sync.aligned.m16n8k16.row.col.f32.f16.f16.f32 "
        "{%0,%1,%2,%3}, {%4,%5,%6,%7}, {%8,%9}, {%0,%1,%2,%3};\n"
        : "+f"(c[0]), "+f"(c[1]), "+f"(c[2]), "+f"(c[3])
        : "r"(a[0]), "r"(a[1]), "r"(a[2]), "r"(a[3]), "r"(b[0]), "r"(b[1]));
}

__device__ __forceinline__ uint32_t smem_u32(const void* p) {
    uint32_t a;
    asm("{ .reg .u64 t; cvta.to.shared.u64 t, %1; cvt.u32.u64 %0, t; }" : "=r"(a) : "l"(p));
    return a;
}

#define CP_ASYNC16(sm, gp) \
    asm volatile("cp.async.cg.shared.global [%0], [%1], 16;" :: "r"(sm), "l"(gp) : "memory")
#define CP_COMMIT() asm volatile("cp.async.commit_group;" ::: "memory")
#define CP_WAIT0()  asm volatile("cp.async.wait_group 0;" ::: "memory")

#define LDSM4(r0, r1, r2, r3, addr) \
    asm volatile("ldmatrix.sync.aligned.m8n8.x4.shared.b16 {%0,%1,%2,%3}, [%4];" \
                 : "=r"(r0), "=r"(r1), "=r"(r2), "=r"(r3) : "r"(addr))

#define LDSM_T4(r0, r1, r2, r3, addr) \
    asm volatile("ldmatrix.sync.aligned.m8n8.x4.trans.shared.b16 {%0,%1,%2,%3}, [%4];" \
                 : "=r"(r0), "=r"(r1), "=r"(r2), "=r"(r3) : "r"(addr))

// ============================================================================
// Prep kernels
// ============================================================================
__global__ void to_half(const float* __restrict__ in, __half* __restrict__ out, int n4)
{
    int i = blockIdx.x * 256 + threadIdx.x;
    if (i >= n4) return;
    float4 v = ((const float4*)in)[i];
    ((__half2*)out)[i * 2]     = __floats2half2_rn(v.x, v.y);
    ((__half2*)out)[i * 2 + 1] = __floats2half2_rn(v.z, v.w);
}

// transpose + convert: src [K][N] fp32 -> dst [N][K] fp16 (x scale)
__global__ void thalf(const float* __restrict__ src, int K, int N,
                      __half* __restrict__ dst, float scale)
{
    __shared__ float s[32][33];
    const int tx = threadIdx.x, ty = threadIdx.y;
    const int n0 = blockIdx.x * 32, k0 = blockIdx.y * 32;
#pragma unroll
    for (int i = 0; i < 4; i++)
        s[ty + i * 8][tx] = src[(size_t)(k0 + ty + i * 8) * N + n0 + tx];
    __syncthreads();
#pragma unroll
    for (int i = 0; i < 4; i++)
        dst[(size_t)(n0 + ty + i * 8) * K + k0 + tx] =
            __float2half_rn(s[tx][ty + i * 8] * scale);
}

// fused Wq/Wk/Wv transpose+convert (z selects source; Q rows scaled 1/8)
__global__ void thalf_qkv(const float* __restrict__ Wq, const float* __restrict__ Wk,
                          const float* __restrict__ Wv, __half* __restrict__ dst)
{
    __shared__ float s[32][33];
    const int tx = threadIdx.x, ty = threadIdx.y;
    const int n0 = blockIdx.x * 32, k0 = blockIdx.y * 32;
    const int z  = blockIdx.z;
    const float* src = (z == 0) ? Wq : (z == 1) ? Wk : Wv;
    const float scale = (z == 0) ? 0.125f : 1.0f;
    __half* d = dst + (size_t)z * DD * DD;
#pragma unroll
    for (int i = 0; i < 4; i++)
        s[ty + i * 8][tx] = src[(size_t)(k0 + ty + i * 8) * DD + n0 + tx];
    __syncthreads();
#pragma unroll
    for (int i = 0; i < 4; i++)
        d[(size_t)(n0 + ty + i * 8) * DD + k0 + tx] =
            __float2half_rn(s[tx][ty + i * 8] * scale);
}

// ============================================================================
// FP16 GEMM (m16n8k16, fp32 accum), cp.async 2-stage, ldmatrix fragment loads.
// MODE 0: C16 = half(AB); MODE 1: C16 = half(relu(AB+bias)); MODE 2: C = AB+bias+resid
// ============================================================================
#define HR 72
#define BH_ST (128*HR)
#define G16_SMEM(MT) (2*((MT)*HR + BH_ST)*2)

template <int MODE, int MTILE>
__global__ void __launch_bounds__(256, (MTILE == 128) ? 2 : 3)
gemm_f16(const __half* __restrict__ A, const __half* __restrict__ Bm,
         float* __restrict__ C, __half* __restrict__ C16, int M, int N, int K,
         const float* __restrict__ bias, const float* __restrict__ resid)
{
    constexpr int NI   = MTILE / 32;
    constexpr int PA   = MTILE / 32;
    constexpr int A_ST = MTILE * HR;
    constexpr int STG  = A_ST + BH_ST;

    extern __shared__ __half smh[];
    const uint32_t smb = smem_u32(smh);

    const int t    = threadIdx.x;
    const int lane = t & 31;
    const int w    = t >> 5;
    const int wm   = w & 1;
    const int wn   = w >> 1;
    const int g    = lane >> 2;
    const int tg   = lane & 3;
    const int m0   = blockIdx.y * MTILE;
    const int n0   = blockIdx.x * 128;

    const int ldr = t >> 3;
    const int ldc = (t & 7) * 8;
    const __half* Ag0 = A  + (size_t)(m0 + ldr) * K + ldc;
    const __half* Bg0 = Bm + (size_t)(n0 + ldr) * K + ldc;
    const uint32_t Asd = smb + (uint32_t)((ldr * HR + ldc) * 2);
    const uint32_t Bsd = smb + (uint32_t)((A_ST + ldr * HR + ldc) * 2);

    auto issue = [&](int kt, int buf) {
        const uint32_t bo = (uint32_t)(buf * STG * 2);
        const __half* Ag = Ag0 + kt * 64;
        const __half* Bg = Bg0 + kt * 64;
#pragma unroll
        for (int p = 0; p < PA; p++)
            CP_ASYNC16(Asd + bo + p * 32 * HR * 2, Ag + (size_t)p * 32 * K);
#pragma unroll
        for (int p = 0; p < 4; p++)
            CP_ASYNC16(Bsd + bo + p * 32 * HR * 2, Bg + (size_t)p * 32 * K);
        CP_COMMIT();
    };

    // ldmatrix per-lane fragment addresses (byte offsets from buffer base)
    const int lm16 = lane & 15;
    const int lhi  = lane >> 4;           // 0/1 -> k-half select
    const int lb8  = (lane >> 3) & 1;
    const int l8   = lane & 7;
    uint32_t aoff[NI], boff[2];
#pragma unroll
    for (int i = 0; i < NI; i++)
        aoff[i] = (uint32_t)(((wm * (MTILE / 2) + i * 16 + lm16) * HR + lhi * 8) * 2);
#pragma unroll
    for (int jp = 0; jp < 2; jp++)
        boff[jp] = (uint32_t)((A_ST + (wn * 32 + jp * 16 + lhi * 8 + l8) * HR + lb8 * 8) * 2);

    float acc[NI][4][4];
#pragma unroll
    for (int i = 0; i < NI; i++)
#pragma unroll
        for (int j = 0; j < 4; j++)
#pragma unroll
            for (int q = 0; q < 4; q++) acc[i][j][q] = 0.f;

    issue(0, 0);

    const int KT = K >> 6;
    for (int kt = 0; kt < KT; kt++) {
        CP_WAIT0();
        __syncthreads();
        if (kt + 1 < KT) issue(kt + 1, (kt + 1) & 1);

        const uint32_t bufb = smb + (uint32_t)((kt & 1) * STG * 2);
#pragma unroll
        for (int ks = 0; ks < 4; ks++) {
            const uint32_t cob = (uint32_t)(ks * 32);   // 16 halves
            uint32_t af[NI][4], bf[4][2];
#pragma unroll
            for (int i = 0; i < NI; i++)
                LDSM4(af[i][0], af[i][1], af[i][2], af[i][3], bufb + aoff[i] + cob);
#pragma unroll
            for (int jp = 0; jp < 2; jp++)
                LDSM4(bf[2*jp][0], bf[2*jp][1], bf[2*jp+1][0], bf[2*jp+1][1],
                      bufb + boff[jp] + cob);
#pragma unroll
            for (int i = 0; i < NI; i++)
#pragma unroll
                for (int j = 0; j < 4; j++)
                    mma_f16(acc[i][j], af[i], bf[j]);
        }
        __syncthreads();
    }

    // ---------------- epilogue ----------------
    const int mrow = m0 + wm * (MTILE / 2);
    const int ncol = n0 + wn * 32;
#pragma unroll
    for (int j = 0; j < 4; j++) {
        const int colj = ncol + j * 8 + tg * 2;
        float2 bv = make_float2(0.f, 0.f);
        if (MODE == 1 || MODE == 2) bv = *(const float2*)(bias + colj);
#pragma unroll
        for (int i = 0; i < NI; i++) {
            const int r0 = mrow + i * 16 + g;
            float2 v0 = make_float2(acc[i][j][0], acc[i][j][1]);
            float2 v1 = make_float2(acc[i][j][2], acc[i][j][3]);
            if (MODE == 0) {
                *(__half2*)(C16 + (size_t)r0 * N + colj)       = __floats2half2_rn(v0.x, v0.y);
                *(__half2*)(C16 + (size_t)(r0 + 8) * N + colj) = __floats2half2_rn(v1.x, v1.y);
            } else if (MODE == 1) {
                __half2 h0 = __floats2half2_rn(fmaxf(v0.x + bv.x, 0.f), fmaxf(v0.y + bv.y, 0.f));
                __half2 h1 = __floats2half2_rn(fmaxf(v1.x + bv.x, 0.f), fmaxf(v1.y + bv.y, 0.f));
                *(__half2*)(C16 + (size_t)r0 * N + colj)       = h0;
                *(__half2*)(C16 + (size_t)(r0 + 8) * N + colj) = h1;
            } else {
                float2 r0v = *(const float2*)(resid + (size_t)r0 * N + colj);
                float2 r1v = *(const float2*)(resid + (size_t)(r0 + 8) * N + colj);
                v0.x += bv.x + r0v.x; v0.y += bv.y + r0v.y;
                v1.x += bv.x + r1v.x; v1.y += bv.y + r1v.y;
                *(float2*)(C + (size_t)r0 * N + colj)       = v0;
                *(float2*)(C + (size_t)(r0 + 8) * N + colj) = v1;
            }
        }
    }
}

// ============================================================================
// Flash attention v4 + ldmatrix Q/K loads. qtile 128, 8 warps all-M,
// register softmax, P in registers, V via ldmatrix.trans.
// smem halves (stride 72): Q[128] | K[2][64] | V[2][64]  = 55296 B
// ============================================================================
#define HRA 72
#define KV_H (64*HRA)
#define OFF_KA (128*HRA)
#define OFF_VA (OFF_KA + 2*KV_H)
#define ATT_HALVES (OFF_VA + 2*KV_H)
#define ATT_SMEM_BYTES (ATT_HALVES*2)

__global__ void __launch_bounds__(256, 2)
attention_tc(const __half* __restrict__ QKV, const float* __restrict__ X,
             float* __restrict__ X1)
{
    extern __shared__ __half smh[];
    const uint32_t smb = smem_u32(smh);

    const int t    = threadIdx.x;
    const int lane = t & 31;
    const int w    = t >> 5;
    const int g    = lane >> 2;
    const int tg   = lane & 3;

    const int qb   = blockIdx.x * 128;
    const int h    = blockIdx.y;
    const int b    = blockIdx.z;
    const int brow = b * SS;

    const __half* Qg = QKV + (size_t)(brow + qb) * NQKV + h * DH;
    const int ldr = t >> 3;
    const int ldc = (t & 7) * 8;

    auto issueKV = [&](int kb, int buf) {
        const __half* Kg = QKV + (size_t)(brow + kb) * NQKV + DD     + h * DH;
        const __half* Vg = QKV + (size_t)(brow + kb) * NQKV + 2 * DD + h * DH;
        const uint32_t kd = smb + (uint32_t)((OFF_KA + buf * KV_H) * 2);
        const uint32_t vd = smb + (uint32_t)((OFF_VA + buf * KV_H) * 2);
#pragma unroll
        for (int p = 0; p < 2; p++) {
            int r = ldr + p * 32;
            CP_ASYNC16(kd + (uint32_t)((r * HRA + ldc) * 2), Kg + (size_t)r * NQKV + ldc);
            CP_ASYNC16(vd + (uint32_t)((r * HRA + ldc) * 2), Vg + (size_t)r * NQKV + ldc);
        }
        CP_COMMIT();
    };

#pragma unroll
    for (int p = 0; p < 4; p++) {
        int e = p * 256 + t;
        int r = e >> 3, c8 = (e & 7) * 8;
        CP_ASYNC16(smb + (uint32_t)((r * HRA + c8) * 2), Qg + (size_t)r * NQKV + c8);
    }
    issueKV(0, 0);

    const int r0 = w * 16 + g;
    const int r1 = r0 + 8;
    float m0 = -1e30f, m1 = -1e30f, l0 = 0.f, l1 = 0.f;
    float oacc[8][4];
#pragma unroll
    for (int i = 0; i < 8; i++)
#pragma unroll
        for (int q = 0; q < 4; q++) oacc[i][q] = 0.f;

    // ldmatrix lane addressing
    const int lm16 = lane & 15;
    const int lhi  = lane >> 4;
    const int lb8  = (lane >> 3) & 1;
    const int l8   = lane & 7;
    const uint32_t qoff = (uint32_t)(((w * 16 + lm16) * HRA + lhi * 8) * 2);
    uint32_t koff[4];
#pragma unroll
    for (int jp = 0; jp < 4; jp++)
        koff[jp] = (uint32_t)(((jp * 16 + lhi * 8 + l8) * HRA + lb8 * 8) * 2);
    // V (trans) per-lane offset: sel bit0 -> key+8, bit1 -> dh+8
    const int sel = lane >> 3;
    const int vlo = ((sel & 1) * 8 + l8) * HRA + (sel >> 1) * 8;

    for (int kt = 0; kt < SS / 64; kt++) {
        CP_WAIT0();
        __syncthreads();
        if (kt + 1 < SS / 64) issueKV((kt + 1) * 64, (kt + 1) & 1);

        const uint32_t ksb = smb + (uint32_t)((OFF_KA + (kt & 1) * KV_H) * 2);
        const uint32_t vsb = smb + (uint32_t)((OFF_VA + (kt & 1) * KV_H) * 2);

        // ---- S = Q K^T ----
        float sacc[8][4];
#pragma unroll
        for (int j = 0; j < 8; j++)
#pragma unroll
            for (int q = 0; q < 4; q++) sacc[j][q] = 0.f;

#pragma unroll
        for (int kc = 0; kc < 4; kc++) {
            const uint32_t cob = (uint32_t)(kc * 32);
            uint32_t af[4];
            LDSM4(af[0], af[1], af[2], af[3], smb + qoff + cob);
#pragma unroll
            for (int jp = 0; jp < 4; jp++) {
                uint32_t k0r, k1r, k2r, k3r;
                LDSM4(k0r, k1r, k2r, k3r, ksb + koff[jp] + cob);
                uint32_t bf0[2] = { k0r, k1r };
                uint32_t bf1[2] = { k2r, k3r };
                mma_f16(sacc[2*jp],     af, bf0);
                mma_f16(sacc[2*jp + 1], af, bf1);
            }
        }

        // ---- warp-local softmax ----
        float pm0 = -1e30f, pm1 = -1e30f;
#pragma unroll
        for (int j = 0; j < 8; j++) {
            pm0 = fmaxf(pm0, fmaxf(sacc[j][0], sacc[j][1]));
            pm1 = fmaxf(pm1, fmaxf(sacc[j][2], sacc[j][3]));
        }
        pm0 = fmaxf(pm0, __shfl_xor_sync(0xffffffffu, pm0, 1));
        pm0 = fmaxf(pm0, __shfl_xor_sync(0xffffffffu, pm0, 2));
        pm1 = fmaxf(pm1, __shfl_xor_sync(0xffffffffu, pm1, 1));
        pm1 = fmaxf(pm1, __shfl_xor_sync(0xffffffffu, pm1, 2));

        const float mn0 = fmaxf(m0, pm0);
        const float mn1 = fmaxf(m1, pm1);
        const float al0 = __expf(m0 - mn0);
        const float al1 = __expf(m1 - mn1);
        m0 = mn0; m1 = mn1;

        uint32_t pf0[8], pf1[8];
        float rs0 = 0.f, rs1 = 0.f;
#pragma unroll
        for (int j = 0; j < 8; j++) {
            float p00 = __expf(sacc[j][0] - mn0);
            float p01 = __expf(sacc[j][1] - mn0);
            float p10 = __expf(sacc[j][2] - mn1);
            float p11 = __expf(sacc[j][3] - mn1);
            rs0 += p00 + p01;
            rs1 += p10 + p11;
            __half2 h0 = __floats2half2_rn(p00, p01);
            __half2 h1 = __floats2half2_rn(p10, p11);
            pf0[j] = *(uint32_t*)&h0;
            pf1[j] = *(uint32_t*)&h1;
        }
        rs0 += __shfl_xor_sync(0xffffffffu, rs0, 1);
        rs0 += __shfl_xor_sync(0xffffffffu, rs0, 2);
        rs1 += __shfl_xor_sync(0xffffffffu, rs1, 1);
        rs1 += __shfl_xor_sync(0xffffffffu, rs1, 2);
        l0 = l0 * al0 + rs0;
        l1 = l1 * al1 + rs1;
#pragma unroll
        for (int i = 0; i < 8; i++) {
            oacc[i][0] *= al0; oacc[i][1] *= al0;
            oacc[i][2] *= al1; oacc[i][3] *= al1;
        }

        // ---- O += P @ V ----
#pragma unroll
        for (int kc = 0; kc < 4; kc++) {
            uint32_t af[4];
            af[0] = pf0[2 * kc];
            af[1] = pf1[2 * kc];
            af[2] = pf0[2 * kc + 1];
            af[3] = pf1[2 * kc + 1];
#pragma unroll
            for (int jp = 0; jp < 4; jp++) {
                uint32_t q0, q1, q2, q3;
                const uint32_t va = vsb +
                    (uint32_t)((kc * 16 * HRA + jp * 16 + vlo) * 2);
                LDSM_T4(q0, q1, q2, q3, va);
                uint32_t bf0[2] = { q0, q1 };
                uint32_t bf1[2] = { q2, q3 };
                mma_f16(oacc[jp * 2],     af, bf0);
                mma_f16(oacc[jp * 2 + 1], af, bf1);
            }
        }
    }

    // ---- epilogue: X1 = O/l + X ----
    const float il0 = 1.f / l0;
    const float il1 = 1.f / l1;
    const size_t tok0 = (size_t)(brow + qb + r0);
    const size_t tok1 = (size_t)(brow + qb + r1);
#pragma unroll
    for (int jd = 0; jd < 8; jd++) {
        const int col = h * DH + jd * 8 + tg * 2;
        float2 x0 = *(const float2*)(X + tok0 * DD + col);
        float2 x1 = *(const float2*)(X + tok1 * DD + col);
        float2 o0 = make_float2(oacc[jd][0] * il0 + x0.x, oacc[jd][1] * il0 + x0.y);
        float2 o1 = make_float2(oacc[jd][2] * il1 + x1.x, oacc[jd][3] * il1 + x1.y);
        *(float2*)(X1 + tok0 * DD + col) = o0;
        *(float2*)(X1 + tok1 * DD + col) = o1;
    }
}

// ============================================================================
// LayerNorm over D=1280; emits fp16 for the FFN1 GEMM.
// ============================================================================
__global__ void __launch_bounds__(256)
ln_kernel(const float* __restrict__ X, const float* __restrict__ gam,
          const float* __restrict__ bet, __half* __restrict__ Y)
{
    const int row = blockIdx.x;
    const float* xr = X + (size_t)row * DD;
    float v[5];
    float sum = 0.f, sq = 0.f;
#pragma unroll
    for (int i = 0; i < 5; i++) {
        v[i] = xr[threadIdx.x + i * 256];
        sum += v[i];
        sq  += v[i] * v[i];
    }
#pragma unroll
    for (int off = 16; off; off >>= 1) {
        sum += __shfl_xor_sync(0xffffffffu, sum, off);
        sq  += __shfl_xor_sync(0xffffffffu, sq , off);
    }
    __shared__ float sS[8], sQ[8];
    const int w = threadIdx.x >> 5, lane = threadIdx.x & 31;
    if (lane == 0) { sS[w] = sum; sQ[w] = sq; }
    __syncthreads();
    if (threadIdx.x == 0) {
        float a = 0.f, q = 0.f;
#pragma unroll
        for (int i = 0; i < 8; i++) { a += sS[i]; q += sQ[i]; }
        sS[0] = a; sQ[0] = q;
    }
    __syncthreads();
    const float mu   = sS[0] * (1.0f / DD);
    const float var  = sQ[0] * (1.0f / DD) - mu * mu;
    const float rstd = rsqrtf(var + 1e-5f);
    __half* yr = Y + (size_t)row * DD;
#pragma unroll
    for (int i = 0; i < 5; i++) {
        int c = threadIdx.x + i * 256;
        yr[c] = __float2half_rn((v[i] - mu) * rstd * gam[c] + bet[c]);
    }
}

// ============================================================================
// launch
// ============================================================================
extern "C" void kernel_launch(void* const* d_in, const int* in_sizes, int n_in,
                              void* d_out, int out_size)
{
    const float* x   = (const float*)d_in[0];
    const float* Wq  = (const float*)d_in[1];
    const float* Wk  = (const float*)d_in[2];
    const float* Wv  = (const float*)d_in[3];
    const float* lng = (const float*)d_in[4];
    const float* lnb = (const float*)d_in[5];
    const float* W1  = (const float*)d_in[6];
    const float* b1  = (const float*)d_in[7];
    const float* W2  = (const float*)d_in[8];
    const float* b2  = (const float*)d_in[9];
    float* out = (float*)d_out;

    __half *X16, *Wqkv, *W1t, *W2t, *QKV16, *H0, *H1;
    float *X1;
    cudaGetSymbolAddress((void**)&X16,   g_x16);
    cudaGetSymbolAddress((void**)&Wqkv,  g_Wqkv);
    cudaGetSymbolAddress((void**)&W1t,   g_W1t);
    cudaGetSymbolAddress((void**)&W2t,   g_W2t);
    cudaGetSymbolAddress((void**)&QKV16, g_QKV16);
    cudaGetSymbolAddress((void**)&X1,    g_x1);
    cudaGetSymbolAddress((void**)&H0,    g_h0);
    cudaGetSymbolAddress((void**)&H1,    g_h1);

    cudaFuncSetAttribute((const void*)gemm_f16<0,64>,  cudaFuncAttributeMaxDynamicSharedMemorySize, G16_SMEM(64));
    cudaFuncSetAttribute((const void*)gemm_f16<1,128>, cudaFuncAttributeMaxDynamicSharedMemorySize, G16_SMEM(128));
    cudaFuncSetAttribute((const void*)gemm_f16<2,128>, cudaFuncAttributeMaxDynamicSharedMemorySize, G16_SMEM(128));
    cudaFuncSetAttribute((const void*)attention_tc,    cudaFuncAttributeMaxDynamicSharedMemorySize, ATT_SMEM_BYTES);

    const dim3 blk(256);
    const dim3 tb(32, 8);

    // prep
    to_half<<<(MM*DD/4 + 255)/256, blk>>>(x, X16, MM*DD/4);
    thalf_qkv<<<dim3(DD/32, DD/32, 3), tb>>>(Wq, Wk, Wv, Wqkv);
    thalf<<<dim3(DF/32, DD/32), tb>>>(W1, DD, DF, W1t, 1.0f);
    thalf<<<dim3(DD/32, DF/32), tb>>>(W2, DF, DD, W2t, 1.0f);

    // QKV projection -> fp16
    gemm_f16<0,64><<<dim3(NQKV/128, MM/64), blk, G16_SMEM(64)>>>(
        X16, Wqkv, nullptr, QKV16, MM, NQKV, DD, nullptr, nullptr);

    // fused fp16 attention + residual
    attention_tc<<<dim3(SS/128, HH, BB), blk, ATT_SMEM_BYTES>>>(QKV16, x, X1);

    // layernorm -> fp16
    ln_kernel<<<MM, 256>>>(X1, lng, lnb, H0);

    // FFN
    gemm_f16<1,128><<<dim3(DF/128, MM/128), blk, G16_SMEM(128)>>>(
        H0, W1t, nullptr, H1, MM, DF, DD, b1, nullptr);
    gemm_f16<2,128><<<dim3(DD/128, MM/128), blk, G16_SMEM(128)>>>(
        H1, W2t, out, nullptr, MM, DD, DF, b2, X1);
}